// round 3
// baseline (speedup 1.0000x reference)
#include <cuda_runtime.h>
#include <math.h>

#define B_TOT   4096
#define NOBJ    64
#define DOBJ    32
#define FEAT    31
#define HID     256
#define OBS_W   2304
#define OTH_OFF 2048
#define NHEAD   4
#define HDIM    64
#define PITCH   260   // float pitch: mult of 4 (16B align), mod 32 = 4 (bank skew)

typedef unsigned long long ull;

__device__ __forceinline__ ull pack2(float lo, float hi) {
    ull r; asm("mov.b64 %0,{%1,%2};" : "=l"(r) : "f"(lo), "f"(hi)); return r;
}
__device__ __forceinline__ float2 unpack2(ull v) {
    float2 f; asm("mov.b64 {%0,%1},%2;" : "=f"(f.x), "=f"(f.y) : "l"(v)); return f;
}
__device__ __forceinline__ ull ffma2(ull a, ull b, ull c) {
    ull d; asm("fma.rn.f32x2 %0,%1,%2,%3;" : "=l"(d) : "l"(a), "l"(b), "l"(c)); return d;
}

// Transposed (j-major) weight scratch. Repacked at the start of every launch.
__device__ float g_pW1t[HID * DOBJ];   // [j][k], k padded 31->32 with zero
__device__ float g_pW2t[HID * HID];
__device__ float g_pW3t[HID * HID];
__device__ float g_oW1t[HID * HID];
__device__ float g_oW2t[HID * HID];
__device__ float g_Wqt [HID * HID];

__global__ void repack256(const float* __restrict__ W, float* __restrict__ Wt) {
    // Wt[j*256+k] = W[k*256+j]
    const int j = blockIdx.x, k = threadIdx.x;
    Wt[j * HID + k] = W[k * HID + j];
}
__global__ void repack31(const float* __restrict__ W, float* __restrict__ Wt) {
    // Wt[j*32+k] = (k<31) ? W[k*256+j] : 0
    const int j = blockIdx.x, k = threadIdx.x;
    Wt[j * DOBJ + k] = (k < FEAT) ? W[k * HID + j] : 0.0f;
}

struct SmemLayout {
    float feats[NOBJ * DOBJ];     // objs raw; [n*32 + d], d=31 is mask
    float A[NOBJ * PITCH];        // H1, then rawP
    float Bf[NOBJ * PITCH];       // H2
    float v0[HID];
    float v1[HID];
    float qt[HID];
    float qb[NHEAD];
    float mask[NOBJ];
    float logit[NHEAD * NOBJ];
    float wgt[NHEAD * NOBJ];
    float Th[NHEAD];
    float Svec[NHEAD * HDIM];
};

// 64x256 GEMM tile, transposed weights: thread owns cols {j0, j0+1}, rows r0..r0+15.
// Weights arrive pre-packed (k-adjacent) via LDG.128; zero marshalling ALU.
template<int KP, int PIN, bool RELU>
__device__ __forceinline__ void obj_gemm2t(const float* __restrict__ Wt,
                                           const float* __restrict__ bias,
                                           const float* sIn, float* sOut,
                                           int j0, int r0)
{
    constexpr int NC = KP / 4;
    const float* wr0 = Wt + (size_t)j0 * KP;
    const float* wr1 = wr0 + KP;
    ull acc0[16], acc1[16];
    {
        const ull b0 = pack2(bias[j0],     0.0f);
        const ull b1 = pack2(bias[j0 + 1], 0.0f);
#pragma unroll
        for (int r = 0; r < 16; r++) { acc0[r] = b0; acc1[r] = b1; }
    }
    const float* base = sIn + r0 * PIN;

    ulonglong2 w0 = *reinterpret_cast<const ulonglong2*>(wr0);
    ulonglong2 w1 = *reinterpret_cast<const ulonglong2*>(wr1);

    for (int c = 0; c < NC; c++) {
        const int cn = (c + 1 < NC) ? c + 1 : c;
        const ulonglong2 n0 = *reinterpret_cast<const ulonglong2*>(wr0 + cn * 4);
        const ulonglong2 n1 = *reinterpret_cast<const ulonglong2*>(wr1 + cn * 4);
        const float* p = base + 4 * c;
#pragma unroll
        for (int r = 0; r < 16; r++) {
            const ulonglong2 v = *reinterpret_cast<const ulonglong2*>(p + r * PIN);
            acc0[r] = ffma2(v.x, w0.x, acc0[r]);
            acc1[r] = ffma2(v.x, w1.x, acc1[r]);
            acc0[r] = ffma2(v.y, w0.y, acc0[r]);
            acc1[r] = ffma2(v.y, w1.y, acc1[r]);
        }
        w0 = n0; w1 = n1;
    }

#pragma unroll
    for (int r = 0; r < 16; r++) {
        const float2 a0 = unpack2(acc0[r]);
        const float2 a1 = unpack2(acc1[r]);
        float x0 = a0.x + a0.y;
        float x1 = a1.x + a1.y;
        if (RELU) { x0 = fmaxf(x0, 0.0f); x1 = fmaxf(x1, 0.0f); }
        *reinterpret_cast<float2*>(&sOut[(r0 + r) * PITCH + j0]) = make_float2(x0, x1);
    }
}

// 256->256 GEMV, transposed weights (row = Wt + j*256): pure packed loads.
__device__ __forceinline__ float gemv256t(const float* __restrict__ Wt_row, float bias,
                                          const float* sv)
{
    ull acc = pack2(bias, 0.0f);
#pragma unroll 8
    for (int k = 0; k < HID; k += 4) {
        const ulonglong2 w = *reinterpret_cast<const ulonglong2*>(Wt_row + k);
        const ulonglong2 v = *reinterpret_cast<const ulonglong2*>(sv + k);
        acc = ffma2(v.x, w.x, acc);
        acc = ffma2(v.y, w.y, acc);
    }
    const float2 a = unpack2(acc);
    return a.x + a.y;
}

__global__ void __launch_bounds__(512, 1) pinet_kernel(
    const float* __restrict__ obs,
    const float* __restrict__ ob1, const float* __restrict__ ob2,
    const float* __restrict__ pb1, const float* __restrict__ pb2,
    const float* __restrict__ pb3,
    const float* __restrict__ bq,
    const float* __restrict__ Wk,  const float* __restrict__ bk,
    const float* __restrict__ Wv,  const float* __restrict__ bv,
    float* __restrict__ out)
{
    extern __shared__ float smraw[];
    SmemLayout* s = reinterpret_cast<SmemLayout*>(smraw);

    const int b   = blockIdx.x;
    const int tid = threadIdx.x;
    const float* row = obs + (size_t)b * OBS_W;

    // ---- load objects (2048 floats across 512 threads) + others (256) ----
    {
        const float4* r4 = reinterpret_cast<const float4*>(row);
        reinterpret_cast<float4*>(s->feats)[tid] = r4[tid];
        if (tid < HID) s->v0[tid] = row[OTH_OFF + tid];
    }
    __syncthreads();
    if (tid < NOBJ) s->mask[tid] = s->feats[tid * DOBJ + (DOBJ - 1)];

    // ================= Stage A: per-sample path (threads 0..255) =================
    if (tid < HID) s->v1[tid] = fmaxf(gemv256t(g_oW1t + tid * HID, ob1[tid], s->v0), 0.0f);
    __syncthreads();
    if (tid < HID) {
        const float a = gemv256t(g_oW2t + tid * HID, ob2[tid], s->v1);
        out[(size_t)b * 512 + tid] = a;
        s->v0[tid] = a;
    }
    __syncthreads();
    if (tid < HID) s->v1[tid] = gemv256t(g_Wqt + tid * HID, bq[tid], s->v0);  // q, head-major
    __syncthreads();
    if (tid < HID) {
        // qt[h*64+d] = Wk[h,d,:] . q[h,:] ;  qb[h] = q[h,:] . bk[h,:]
        const int h = tid >> 6, d = tid & 63;
        const float4* wk4 = reinterpret_cast<const float4*>(Wk + h * (HDIM * HDIM) + d * HDIM);
        const float4* q4  = reinterpret_cast<const float4*>(s->v1 + h * HDIM);
        float t = 0.0f;
#pragma unroll
        for (int e = 0; e < HDIM / 4; e++) {
            const float4 w = wk4[e];
            const float4 qv = q4[e];
            t += w.x * qv.x + w.y * qv.y + w.z * qv.z + w.w * qv.w;
        }
        s->qt[tid] = t;
        if (tid < NHEAD) {
            float sb = 0.0f;
            for (int e = 0; e < HDIM; e++) sb += s->v1[tid * HDIM + e] * bk[tid * HDIM + e];
            s->qb[tid] = sb;
        }
    }
    __syncthreads();

    // ================= Stage B: per-object MLP (the big FLOPs) =================
    const int j0 = 2 * (tid & 127);    // column pair
    const int r0 = (tid >> 7) * 16;    // row group of 16
    obj_gemm2t<DOBJ, DOBJ,  true >(g_pW1t, pb1, s->feats, s->A,  j0, r0);  // mask col has 0 weight
    __syncthreads();
    obj_gemm2t<HID,  PITCH, true >(g_pW2t, pb2, s->A,     s->Bf, j0, r0);
    __syncthreads();
    obj_gemm2t<HID,  PITCH, false>(g_pW3t, pb3, s->Bf,    s->A,  j0, r0);
    __syncthreads();

    // ================= Stage C: attention (q-len 1; K/V folded) =================
    const int h = (tid >> 6) & 3;
    const int n = tid & 63;
    if (tid < 256) {
        const float* rp = s->A + n * PITCH + h * HDIM;
        const float* qt = s->qt + h * HDIM;
        float dot = 0.0f;
#pragma unroll
        for (int d = 0; d < HDIM; d += 4) {
            const float4 a4 = *reinterpret_cast<const float4*>(&rp[d]);
            const float4 b4 = *reinterpret_cast<const float4*>(&qt[d]);
            dot += a4.x * b4.x + a4.y * b4.y + a4.z * b4.z + a4.w * b4.w;
        }
        const float m = s->mask[n];
        float lg = fmaf(m, dot, s->qb[h]) * 0.0625f;   // / sqrt(256)
        if (m == 0.0f) lg = -1000000000.0f;
        s->logit[h * NOBJ + n] = lg;
    }
    __syncthreads();

    {   // softmax per head; wgt = attn*mask^2, Th = sum attn*mask
        const int wid = tid >> 5, lane = tid & 31;
        if (wid < NHEAD) {
            const int hh = wid;
            const float x0 = s->logit[hh * NOBJ + lane];
            const float x1 = s->logit[hh * NOBJ + 32 + lane];
            float mx = fmaxf(x0, x1);
#pragma unroll
            for (int o = 16; o > 0; o >>= 1) mx = fmaxf(mx, __shfl_xor_sync(0xffffffffu, mx, o));
            const float e0 = expf(x0 - mx);
            const float e1 = expf(x1 - mx);
            float sum = e0 + e1;
#pragma unroll
            for (int o = 16; o > 0; o >>= 1) sum += __shfl_xor_sync(0xffffffffu, sum, o);
            const float inv = 1.0f / sum;
            const float a0 = e0 * inv, a1 = e1 * inv;
            const float m0 = s->mask[lane], m1 = s->mask[32 + lane];
            s->wgt[hh * NOBJ + lane]      = a0 * m0 * m0;
            s->wgt[hh * NOBJ + 32 + lane] = a1 * m1 * m1;
            float tt = a0 * m0 + a1 * m1;
#pragma unroll
            for (int o = 16; o > 0; o >>= 1) tt += __shfl_xor_sync(0xffffffffu, tt, o);
            if (lane == 0) s->Th[hh] = tt;
        }
    }
    __syncthreads();

    if (tid < 256) {
        // Svec[h,d] = sum_n wgt[h,n] * rawP[n, h*64+d]
        const int d = tid & 63;
        const float* wp = s->wgt + h * NOBJ;
        float acc = 0.0f;
#pragma unroll 4
        for (int nn = 0; nn < NOBJ; nn++)
            acc = fmaf(wp[nn], s->A[nn * PITCH + h * HDIM + d], acc);
        s->Svec[tid] = acc;
    }
    __syncthreads();

    if (tid < 256) {
        // out_emb[h,e] = Svec[h,:] @ Wv[h] + Th[h]*bv[h,e]
        const int e = tid & 63;
        float o = s->Th[h] * bv[h * HDIM + e];
        const float* sv = s->Svec + h * HDIM;
        const float* wv = Wv + h * (HDIM * HDIM) + e;
#pragma unroll 4
        for (int d = 0; d < HDIM; d++)
            o = fmaf(sv[d], wv[d * HDIM], o);
        out[(size_t)b * 512 + 256 + h * HDIM + e] = o;
    }
}

extern "C" void kernel_launch(void* const* d_in, const int* in_sizes, int n_in,
                              void* d_out, int out_size)
{
    const float* obs = (const float*)d_in[0];
    const float* oW1 = (const float*)d_in[1];
    const float* ob1 = (const float*)d_in[2];
    const float* oW2 = (const float*)d_in[3];
    const float* ob2 = (const float*)d_in[4];
    const float* pW1 = (const float*)d_in[5];
    const float* pb1 = (const float*)d_in[6];
    const float* pW2 = (const float*)d_in[7];
    const float* pb2 = (const float*)d_in[8];
    const float* pW3 = (const float*)d_in[9];
    const float* pb3 = (const float*)d_in[10];
    const float* Wq  = (const float*)d_in[11];
    const float* bq  = (const float*)d_in[12];
    const float* Wk  = (const float*)d_in[13];
    const float* bk  = (const float*)d_in[14];
    const float* Wv  = (const float*)d_in[15];
    const float* bv  = (const float*)d_in[16];
    float* out = (float*)d_out;

    float *dW1t, *dW2t, *dW3t, *doW1t, *doW2t, *dWqt;
    cudaGetSymbolAddress((void**)&dW1t,  g_pW1t);
    cudaGetSymbolAddress((void**)&dW2t,  g_pW2t);
    cudaGetSymbolAddress((void**)&dW3t,  g_pW3t);
    cudaGetSymbolAddress((void**)&doW1t, g_oW1t);
    cudaGetSymbolAddress((void**)&doW2t, g_oW2t);
    cudaGetSymbolAddress((void**)&dWqt,  g_Wqt);

    repack31 <<<HID, DOBJ>>>(pW1, dW1t);
    repack256<<<HID, HID >>>(pW2, dW2t);
    repack256<<<HID, HID >>>(pW3, dW3t);
    repack256<<<HID, HID >>>(oW1, doW1t);
    repack256<<<HID, HID >>>(oW2, doW2t);
    repack256<<<HID, HID >>>(Wq,  dWqt);

    const int smem = (int)sizeof(SmemLayout);
    cudaFuncSetAttribute(pinet_kernel, cudaFuncAttributeMaxDynamicSharedMemorySize, smem);
    pinet_kernel<<<B_TOT, 512, smem>>>(obs, ob1, ob2, pb1, pb2, pb3,
                                       bq, Wk, bk, Wv, bv, out);
}

// round 4
// speedup vs baseline: 1.9001x; 1.9001x over previous
#include <cuda_runtime.h>
#include <math.h>

#define B_TOT   4096
#define NOBJ    64
#define DOBJ    32
#define FEAT    31
#define HID     256
#define OBS_W   2304
#define OTH_OFF 2048
#define NHEAD   4
#define HDIM    64
#define PITCH   260   // float pitch: mult of 4 (16B align), mod 32 = 4 (bank skew)

typedef unsigned long long ull;

__device__ __forceinline__ ull pack2(float lo, float hi) {
    ull r; asm("mov.b64 %0,{%1,%2};" : "=l"(r) : "f"(lo), "f"(hi)); return r;
}
__device__ __forceinline__ float2 unpack2(ull v) {
    float2 f; asm("mov.b64 {%0,%1},%2;" : "=f"(f.x), "=f"(f.y) : "l"(v)); return f;
}
__device__ __forceinline__ ull ffma2(ull a, ull b, ull c) {
    ull d; asm("fma.rn.f32x2 %0,%1,%2,%3;" : "=l"(d) : "l"(a), "l"(b), "l"(c)); return d;
}

// Pair-major packed weights: Wp2[k2*256 + j] = (W[2k2][j], W[2k2+1][j]).
// Coalesced across j AND pre-packed for fma.rn.f32x2.
__device__ ull g_pW1p[(DOBJ / 2) * HID];   // k padded 31->32 with zero
__device__ ull g_pW2p[(HID / 2) * HID];
__device__ ull g_pW3p[(HID / 2) * HID];
__device__ ull g_oW1p[(HID / 2) * HID];
__device__ ull g_oW2p[(HID / 2) * HID];
__device__ ull g_Wqp [(HID / 2) * HID];

__global__ void repack_pair256(const float* __restrict__ W, ull* __restrict__ Wp) {
    const int k2 = blockIdx.x, j = threadIdx.x;           // grid 128, block 256
    Wp[k2 * HID + j] = pack2(W[(2 * k2) * HID + j], W[(2 * k2 + 1) * HID + j]);
}
__global__ void repack_pair31(const float* __restrict__ W, ull* __restrict__ Wp) {
    const int k2 = blockIdx.x, j = threadIdx.x;           // grid 16, block 256
    const float hi = (2 * k2 + 1 < FEAT) ? W[(2 * k2 + 1) * HID + j] : 0.0f;
    Wp[k2 * HID + j] = pack2(W[(2 * k2) * HID + j], hi);
}

struct SmemLayout {
    float feats[NOBJ * DOBJ];     // objs raw; [n*32 + d], d=31 is mask
    float A[NOBJ * PITCH];        // H1, then rawP
    float Bf[NOBJ * PITCH];       // H2
    float v0[HID];
    float v1[HID];
    float qt[HID];
    float qb[NHEAD];
    float mask[NOBJ];
    float logit[NHEAD * NOBJ];
    float wgt[NHEAD * NOBJ];
    float Th[NHEAD];
    float Svec[NHEAD * HDIM];
};

// 64x256 GEMM tile: thread owns cols {j0, j0+1}, rows r0..r0+15.
// Weights: pair-major packed, coalesced ulonglong2 loads, double-buffered.
template<int KP, int PIN, bool RELU>
__device__ __forceinline__ void obj_gemm_p(const ull* __restrict__ Wp,
                                           const float* __restrict__ bias,
                                           const float* sIn, float* sOut,
                                           int j0, int r0)
{
    constexpr int NC = KP / 4;   // chunks of 4 k (= 2 k-pairs)
    ull acc0[16], acc1[16];
    {
        const ull b0 = pack2(bias[j0],     0.0f);
        const ull b1 = pack2(bias[j0 + 1], 0.0f);
#pragma unroll
        for (int r = 0; r < 16; r++) { acc0[r] = b0; acc1[r] = b1; }
    }
    const float* base = sIn + r0 * PIN;
    const ull* wbase = Wp + j0;

    // chunk c uses k-pairs 2c (wa: cols j0,j0+1) and 2c+1 (wb)
    ulonglong2 wa = *reinterpret_cast<const ulonglong2*>(wbase + 0 * HID);
    ulonglong2 wb = *reinterpret_cast<const ulonglong2*>(wbase + 1 * HID);

    for (int c = 0; c < NC; c++) {
        const int cn = (c + 1 < NC) ? c + 1 : c;
        const ulonglong2 na = *reinterpret_cast<const ulonglong2*>(wbase + (2 * cn) * HID);
        const ulonglong2 nb = *reinterpret_cast<const ulonglong2*>(wbase + (2 * cn + 1) * HID);
        const float* p = base + 4 * c;
#pragma unroll
        for (int r = 0; r < 16; r++) {
            const ulonglong2 v = *reinterpret_cast<const ulonglong2*>(p + r * PIN);
            acc0[r] = ffma2(v.x, wa.x, acc0[r]);
            acc1[r] = ffma2(v.x, wa.y, acc1[r]);
            acc0[r] = ffma2(v.y, wb.x, acc0[r]);
            acc1[r] = ffma2(v.y, wb.y, acc1[r]);
        }
        wa = na; wb = nb;
    }

#pragma unroll
    for (int r = 0; r < 16; r++) {
        const float2 a0 = unpack2(acc0[r]);
        const float2 a1 = unpack2(acc1[r]);
        float x0 = a0.x + a0.y;
        float x1 = a1.x + a1.y;
        if (RELU) { x0 = fmaxf(x0, 0.0f); x1 = fmaxf(x1, 0.0f); }
        *reinterpret_cast<float2*>(&sOut[(r0 + r) * PITCH + j0]) = make_float2(x0, x1);
    }
}

// 256->256 GEMV: thread j, pair-major weights, coalesced LDG.64.
__device__ __forceinline__ float gemv256p(const ull* __restrict__ Wp, float bias,
                                          const float* sv, int j)
{
    ull acc = pack2(bias, 0.0f);
    const ull* wp = Wp + j;
#pragma unroll 8
    for (int k2 = 0; k2 < HID / 2; k2 += 2) {
        const ulonglong2 v = *reinterpret_cast<const ulonglong2*>(sv + 2 * k2);
        acc = ffma2(v.x, wp[k2 * HID], acc);
        acc = ffma2(v.y, wp[(k2 + 1) * HID], acc);
    }
    const float2 a = unpack2(acc);
    return a.x + a.y;
}

__global__ void __launch_bounds__(512, 1) pinet_kernel(
    const float* __restrict__ obs,
    const float* __restrict__ ob1, const float* __restrict__ ob2,
    const float* __restrict__ pb1, const float* __restrict__ pb2,
    const float* __restrict__ pb3,
    const float* __restrict__ bq,
    const float* __restrict__ Wk,  const float* __restrict__ bk,
    const float* __restrict__ Wv,  const float* __restrict__ bv,
    float* __restrict__ out)
{
    extern __shared__ float smraw[];
    SmemLayout* s = reinterpret_cast<SmemLayout*>(smraw);

    const int b   = blockIdx.x;
    const int tid = threadIdx.x;
    const float* row = obs + (size_t)b * OBS_W;

    // ---- load objects (2048 floats across 512 threads) + others (256) ----
    {
        const float4* r4 = reinterpret_cast<const float4*>(row);
        reinterpret_cast<float4*>(s->feats)[tid] = r4[tid];
        if (tid < HID) s->v0[tid] = row[OTH_OFF + tid];
    }
    __syncthreads();
    if (tid < NOBJ) s->mask[tid] = s->feats[tid * DOBJ + (DOBJ - 1)];

    // ================= Stage A: per-sample path (threads 0..255) =================
    if (tid < HID) s->v1[tid] = fmaxf(gemv256p(g_oW1p, ob1[tid], s->v0, tid), 0.0f);
    __syncthreads();
    if (tid < HID) {
        const float a = gemv256p(g_oW2p, ob2[tid], s->v1, tid);
        out[(size_t)b * 512 + tid] = a;
        s->v0[tid] = a;
    }
    __syncthreads();
    if (tid < HID) s->v1[tid] = gemv256p(g_Wqp, bq[tid], s->v0, tid);  // q, head-major
    __syncthreads();
    if (tid < HID) {
        // qt[h*64+d] = Wk[h,d,:] . q[h,:] ;  qb[h] = q[h,:] . bk[h,:]
        const int h = tid >> 6, d = tid & 63;
        const float4* wk4 = reinterpret_cast<const float4*>(Wk + h * (HDIM * HDIM) + d * HDIM);
        const float4* q4  = reinterpret_cast<const float4*>(s->v1 + h * HDIM);
        float t = 0.0f;
#pragma unroll
        for (int e = 0; e < HDIM / 4; e++) {
            const float4 w = wk4[e];
            const float4 qv = q4[e];
            t += w.x * qv.x + w.y * qv.y + w.z * qv.z + w.w * qv.w;
        }
        s->qt[tid] = t;
        if (tid < NHEAD) {
            float sb = 0.0f;
            for (int e = 0; e < HDIM; e++) sb += s->v1[tid * HDIM + e] * bk[tid * HDIM + e];
            s->qb[tid] = sb;
        }
    }
    __syncthreads();

    // ================= Stage B: per-object MLP (the big FLOPs) =================
    const int j0 = 2 * (tid & 127);    // column pair
    const int r0 = (tid >> 7) * 16;    // row group of 16
    obj_gemm_p<DOBJ, DOBJ,  true >(g_pW1p, pb1, s->feats, s->A,  j0, r0);  // mask k has 0 weight
    __syncthreads();
    obj_gemm_p<HID,  PITCH, true >(g_pW2p, pb2, s->A,     s->Bf, j0, r0);
    __syncthreads();
    obj_gemm_p<HID,  PITCH, false>(g_pW3p, pb3, s->Bf,    s->A,  j0, r0);
    __syncthreads();

    // ================= Stage C: attention (q-len 1; K/V folded) =================
    const int h = (tid >> 6) & 3;
    const int n = tid & 63;
    if (tid < 256) {
        const float* rp = s->A + n * PITCH + h * HDIM;
        const float* qt = s->qt + h * HDIM;
        float dot = 0.0f;
#pragma unroll
        for (int d = 0; d < HDIM; d += 4) {
            const float4 a4 = *reinterpret_cast<const float4*>(&rp[d]);
            const float4 b4 = *reinterpret_cast<const float4*>(&qt[d]);
            dot += a4.x * b4.x + a4.y * b4.y + a4.z * b4.z + a4.w * b4.w;
        }
        const float m = s->mask[n];
        float lg = fmaf(m, dot, s->qb[h]) * 0.0625f;   // / sqrt(256)
        if (m == 0.0f) lg = -1000000000.0f;
        s->logit[h * NOBJ + n] = lg;
    }
    __syncthreads();

    {   // softmax per head; wgt = attn*mask^2, Th = sum attn*mask
        const int wid = tid >> 5, lane = tid & 31;
        if (wid < NHEAD) {
            const int hh = wid;
            const float x0 = s->logit[hh * NOBJ + lane];
            const float x1 = s->logit[hh * NOBJ + 32 + lane];
            float mx = fmaxf(x0, x1);
#pragma unroll
            for (int o = 16; o > 0; o >>= 1) mx = fmaxf(mx, __shfl_xor_sync(0xffffffffu, mx, o));
            const float e0 = expf(x0 - mx);
            const float e1 = expf(x1 - mx);
            float sum = e0 + e1;
#pragma unroll
            for (int o = 16; o > 0; o >>= 1) sum += __shfl_xor_sync(0xffffffffu, sum, o);
            const float inv = 1.0f / sum;
            const float a0 = e0 * inv, a1 = e1 * inv;
            const float m0 = s->mask[lane], m1 = s->mask[32 + lane];
            s->wgt[hh * NOBJ + lane]      = a0 * m0 * m0;
            s->wgt[hh * NOBJ + 32 + lane] = a1 * m1 * m1;
            float tt = a0 * m0 + a1 * m1;
#pragma unroll
            for (int o = 16; o > 0; o >>= 1) tt += __shfl_xor_sync(0xffffffffu, tt, o);
            if (lane == 0) s->Th[hh] = tt;
        }
    }
    __syncthreads();

    if (tid < 256) {
        // Svec[h,d] = sum_n wgt[h,n] * rawP[n, h*64+d]
        const int d = tid & 63;
        const float* wp = s->wgt + h * NOBJ;
        float acc = 0.0f;
#pragma unroll 4
        for (int nn = 0; nn < NOBJ; nn++)
            acc = fmaf(wp[nn], s->A[nn * PITCH + h * HDIM + d], acc);
        s->Svec[tid] = acc;
    }
    __syncthreads();

    if (tid < 256) {
        // out_emb[h,e] = Svec[h,:] @ Wv[h] + Th[h]*bv[h,e]
        const int e = tid & 63;
        float o = s->Th[h] * bv[h * HDIM + e];
        const float* sv = s->Svec + h * HDIM;
        const float* wv = Wv + h * (HDIM * HDIM) + e;
#pragma unroll 4
        for (int d = 0; d < HDIM; d++)
            o = fmaf(sv[d], wv[d * HDIM], o);
        out[(size_t)b * 512 + 256 + h * HDIM + e] = o;
    }
}

extern "C" void kernel_launch(void* const* d_in, const int* in_sizes, int n_in,
                              void* d_out, int out_size)
{
    const float* obs = (const float*)d_in[0];
    const float* oW1 = (const float*)d_in[1];
    const float* ob1 = (const float*)d_in[2];
    const float* oW2 = (const float*)d_in[3];
    const float* ob2 = (const float*)d_in[4];
    const float* pW1 = (const float*)d_in[5];
    const float* pb1 = (const float*)d_in[6];
    const float* pW2 = (const float*)d_in[7];
    const float* pb2 = (const float*)d_in[8];
    const float* pW3 = (const float*)d_in[9];
    const float* pb3 = (const float*)d_in[10];
    const float* Wq  = (const float*)d_in[11];
    const float* bq  = (const float*)d_in[12];
    const float* Wk  = (const float*)d_in[13];
    const float* bk  = (const float*)d_in[14];
    const float* Wv  = (const float*)d_in[15];
    const float* bv  = (const float*)d_in[16];
    float* out = (float*)d_out;

    ull *dW1p, *dW2p, *dW3p, *doW1p, *doW2p, *dWqp;
    cudaGetSymbolAddress((void**)&dW1p,  g_pW1p);
    cudaGetSymbolAddress((void**)&dW2p,  g_pW2p);
    cudaGetSymbolAddress((void**)&dW3p,  g_pW3p);
    cudaGetSymbolAddress((void**)&doW1p, g_oW1p);
    cudaGetSymbolAddress((void**)&doW2p, g_oW2p);
    cudaGetSymbolAddress((void**)&dWqp,  g_Wqp);

    repack_pair31 <<<DOBJ / 2, HID>>>(pW1, dW1p);
    repack_pair256<<<HID / 2,  HID>>>(pW2, dW2p);
    repack_pair256<<<HID / 2,  HID>>>(pW3, dW3p);
    repack_pair256<<<HID / 2,  HID>>>(oW1, doW1p);
    repack_pair256<<<HID / 2,  HID>>>(oW2, doW2p);
    repack_pair256<<<HID / 2,  HID>>>(Wq,  dWqp);

    const int smem = (int)sizeof(SmemLayout);
    cudaFuncSetAttribute(pinet_kernel, cudaFuncAttributeMaxDynamicSharedMemorySize, smem);
    pinet_kernel<<<B_TOT, 512, smem>>>(obs, ob1, ob2, pb1, pb2, pb3,
                                       bq, Wk, bk, Wv, bv, out);
}

// round 7
// speedup vs baseline: 2.8427x; 1.4961x over previous
#include <cuda_runtime.h>
#include <cuda_bf16.h>
#include <mma.h>
#include <math.h>
#include <stdint.h>

using namespace nvcuda;
typedef unsigned long long ull;

#define NOBJ    64
#define DOBJ    32
#define FEAT    31
#define HID     256
#define OBS_W   2304
#define OTH_OFF 2048
#define NHEAD   4
#define HDIM    64
#define MROWS   128          // 2 samples x 64 objects
#define AP      264          // act pitch (bf16 elems): mult of 8, odd/8 skew
#define BP      264          // B-tile pitch (bf16 elems)
#define RP      264          // rawP pitch (floats)
#define GRID_N  2048

using FragA = wmma::fragment<wmma::matrix_a, 16, 16, 16, __nv_bfloat16, wmma::row_major>;
using FragB = wmma::fragment<wmma::matrix_b, 16, 16, 16, __nv_bfloat16, wmma::row_major>;
using FragC = wmma::fragment<wmma::accumulator, 16, 16, 16, float>;

// ---------------- scalar f32x2 helpers (stage A) ----------------
static __device__ __forceinline__ ull pack2(float lo, float hi) {
    ull r; asm("mov.b64 %0,{%1,%2};" : "=l"(r) : "f"(lo), "f"(hi)); return r;
}
static __device__ __forceinline__ float2 unpack2(ull v) {
    float2 f; asm("mov.b64 {%0,%1},%2;" : "=f"(f.x), "=f"(f.y) : "l"(v)); return f;
}
static __device__ __forceinline__ ull ffma2(ull a, ull b, ull c) {
    ull d; asm("fma.rn.f32x2 %0,%1,%2,%3;" : "=l"(d) : "l"(a), "l"(b), "l"(c)); return d;
}

// ---------------- global scratch (prepared per launch) ----------------
__device__ __align__(16) __nv_bfloat16 g_B1h[32 * HID],  g_B1l[32 * HID];    // L1 (k pad 31->32)
__device__ __align__(16) __nv_bfloat16 g_B2h[HID * HID], g_B2l[HID * HID];   // L2
__device__ __align__(16) __nv_bfloat16 g_B3h[HID * HID], g_B3l[HID * HID];   // L3
__device__ ull g_oW1p[(HID/2)*HID], g_oW2p[(HID/2)*HID], g_Wqp[(HID/2)*HID];

__global__ void repack_pair256(const float* __restrict__ W, ull* __restrict__ Wp) {
    const int k2 = blockIdx.x, j = threadIdx.x;
    Wp[k2 * HID + j] = pack2(W[(2*k2) * HID + j], W[(2*k2+1) * HID + j]);
}
__global__ void build_B(const float* __restrict__ W, __nv_bfloat16* __restrict__ hi,
                        __nv_bfloat16* __restrict__ lo, int krows) {
    const int k = blockIdx.x, n = threadIdx.x;           // grid=krows_pad, block=256
    const float w = (k < krows) ? W[k * HID + n] : 0.0f;
    const __nv_bfloat16 h = __float2bfloat16_rn(w);
    const __nv_bfloat16 l = __float2bfloat16_rn(w - __bfloat162float(h));
    hi[blockIdx.x * HID + n] = h;
    lo[blockIdx.x * HID + n] = l;
}

// ---------------- SMEM ----------------
struct Smem {
    union {
        struct { __nv_bfloat16 hi[MROWS * AP]; __nv_bfloat16 lo[MROWS * AP]; } act;
        float rawP[MROWS * RP];                  // same byte size: 128*264*4
    } u;
    __nv_bfloat16 Bh[64 * BP];
    __nv_bfloat16 Bl[64 * BP];
    float stg[8][16 * 20];                        // per-warp C-frag staging
    float v0[2][HID], v1[2][HID], qt[2][HID];
    float qb[2][NHEAD], pq[2][NHEAD];
    float maskv[MROWS];
    float logit[2][NHEAD * NOBJ], wgt[2][NHEAD * NOBJ];
    float Th[2][NHEAD], Wsum[2][NHEAD];
    float Svec[2][HID];
};

// copy a [rows x 256] bf16 pair (hi,lo) from global into pitched SMEM tiles
static __device__ __forceinline__ void copyB(__nv_bfloat16* dstH, __nv_bfloat16* dstL,
                                             const __nv_bfloat16* srcH,
                                             const __nv_bfloat16* srcL,
                                             int rows, int tid) {
    const int4* sh = reinterpret_cast<const int4*>(srcH);
    const int4* sl = reinterpret_cast<const int4*>(srcL);
    for (int i = tid; i < rows * 32; i += 256) {
        const int r = i >> 5, c8 = i & 31;
        *reinterpret_cast<int4*>(&dstH[r * BP + c8 * 8]) = sh[i];
        *reinterpret_cast<int4*>(&dstL[r * BP + c8 * 8]) = sl[i];
    }
}

// one K-chunk of MMAs: 3 split terms (AhiBhi, AloBhi, AhiBlo) x nks k-steps
static __device__ __forceinline__ void mma_block(FragC (&c)[2][8],
    const __nv_bfloat16* actH, const __nv_bfloat16* actL,
    const __nv_bfloat16* Bh,   const __nv_bfloat16* Bl,
    int nks, int kbase, int mbase, int nbase)
{
#pragma unroll
    for (int term = 0; term < 3; term++) {
        const __nv_bfloat16* A = (term == 1) ? actL : actH;
        const __nv_bfloat16* B = (term == 2) ? Bl : Bh;
        for (int ks = 0; ks < nks; ks++) {
            FragA a0, a1;
            wmma::load_matrix_sync(a0, A + (size_t)mbase * AP + kbase + ks * 16, AP);
            wmma::load_matrix_sync(a1, A + (size_t)(mbase + 16) * AP + kbase + ks * 16, AP);
#pragma unroll
            for (int nt = 0; nt < 8; nt++) {
                FragB b;
                wmma::load_matrix_sync(b, B + (size_t)(ks * 16) * BP + nbase + nt * 16, BP);
                wmma::mma_sync(c[0][nt], a0, b, c[0][nt]);
                wmma::mma_sync(c[1][nt], a1, b, c[1][nt]);
            }
        }
    }
}

// epilogue: x = relu(C + bias); split to bf16 hi/lo; write act buffers
static __device__ __forceinline__ void epi_act(FragC (&c)[2][8], float* stg,
    const float* __restrict__ bias, __nv_bfloat16* actH, __nv_bfloat16* actL,
    int mbase, int nbase, int lane)
{
#pragma unroll
    for (int mi = 0; mi < 2; mi++)
#pragma unroll
        for (int ni = 0; ni < 8; ni++) {
            wmma::store_matrix_sync(stg, c[mi][ni], 20, wmma::mem_row_major);
            __syncwarp();
            for (int e = lane; e < 256; e += 32) {
                const int r = e >> 4, cc = e & 15;
                const int j = nbase + ni * 16 + cc;
                const int m = mbase + mi * 16 + r;
                float x = stg[r * 20 + cc] + __ldg(bias + j);
                x = fmaxf(x, 0.0f);
                const __nv_bfloat16 h = __float2bfloat16_rn(x);
                const __nv_bfloat16 l = __float2bfloat16_rn(x - __bfloat162float(h));
                actH[(size_t)m * AP + j] = h;
                actL[(size_t)m * AP + j] = l;
            }
            __syncwarp();
        }
}

// stage-A GEMV over both samples sharing weight loads (pair-major FFMA2)
static __device__ __forceinline__ void gemv2(const ull* __restrict__ Wp,
                                             const float* __restrict__ bias,
                                             const float* x0, const float* x1,
                                             float* y0, float* y1, int j, bool relu) {
    ull a0 = pack2(bias[j], 0.0f), a1 = a0;
    const ull* wp = Wp + j;
#pragma unroll 4
    for (int k2 = 0; k2 < HID / 2; k2 += 2) {
        const ull wA = wp[k2 * HID], wB = wp[(k2 + 1) * HID];
        const ulonglong2 u0 = *reinterpret_cast<const ulonglong2*>(x0 + 2 * k2);
        const ulonglong2 u1 = *reinterpret_cast<const ulonglong2*>(x1 + 2 * k2);
        a0 = ffma2(u0.x, wA, a0); a0 = ffma2(u0.y, wB, a0);
        a1 = ffma2(u1.x, wA, a1); a1 = ffma2(u1.y, wB, a1);
    }
    const float2 f0 = unpack2(a0), f1 = unpack2(a1);
    float r0 = f0.x + f0.y, r1 = f1.x + f1.y;
    if (relu) { r0 = fmaxf(r0, 0.0f); r1 = fmaxf(r1, 0.0f); }
    y0[j] = r0; y1[j] = r1;
}

__global__ void __launch_bounds__(256, 1) pinet_wmma_kernel(
    const float* __restrict__ obs,
    const float* __restrict__ ob1, const float* __restrict__ ob2,
    const float* __restrict__ pb1, const float* __restrict__ pb2,
    const float* __restrict__ pb3, const float* __restrict__ bq,
    const float* __restrict__ Wk,  const float* __restrict__ bk,
    const float* __restrict__ Wv,  const float* __restrict__ bv,
    float* __restrict__ out)
{
    extern __shared__ char smraw[];
    Smem* s = reinterpret_cast<Smem*>(smraw);
    const int tid = threadIdx.x, wid = tid >> 5, lane = tid & 31;
    __nv_bfloat16* actH = s->u.act.hi;
    __nv_bfloat16* actL = s->u.act.lo;

    // ---- load obs: feats -> act bf16 hi/lo (cols 0..31), mask, others ----
    {
        const float* r0 = obs + (size_t)(blockIdx.x * 2 + 0) * OBS_W;
        const float* r1 = obs + (size_t)(blockIdx.x * 2 + 1) * OBS_W;
        for (int i = tid; i < 512; i += 256) {
            const float4 a = reinterpret_cast<const float4*>(r0)[i];
            const float4 b = reinterpret_cast<const float4*>(r1)[i];
            const int m0 = i >> 3, d4 = (i & 7) * 4;
            const float va[8] = {a.x, a.y, a.z, a.w, b.x, b.y, b.z, b.w};
#pragma unroll
            for (int smp = 0; smp < 2; smp++) {
                const int m = smp * 64 + m0;
#pragma unroll
                for (int e = 0; e < 4; e++) {
                    const float x = va[smp * 4 + e];
                    const __nv_bfloat16 h = __float2bfloat16_rn(x);
                    const __nv_bfloat16 l = __float2bfloat16_rn(x - __bfloat162float(h));
                    actH[(size_t)m * AP + d4 + e] = h;
                    actL[(size_t)m * AP + d4 + e] = l;
                }
            }
            if ((i & 7) == 7) { s->maskv[m0] = a.w; s->maskv[64 + m0] = b.w; }
        }
        s->v0[0][tid] = r0[OTH_OFF + tid];
        s->v0[1][tid] = r1[OTH_OFF + tid];
    }
    __syncthreads();

    // ---- stage A: others MLP + q + qt/qb/pq (scalar FFMA2) ----
    gemv2(g_oW1p, ob1, s->v0[0], s->v0[1], s->v1[0], s->v1[1], tid, true);
    __syncthreads();
    gemv2(g_oW2p, ob2, s->v1[0], s->v1[1], s->v0[0], s->v0[1], tid, false);  // others_e
    out[(size_t)(blockIdx.x * 2 + 0) * 512 + tid] = s->v0[0][tid];
    out[(size_t)(blockIdx.x * 2 + 1) * 512 + tid] = s->v0[1][tid];
    __syncthreads();
    gemv2(g_Wqp, bq, s->v0[0], s->v0[1], s->v1[0], s->v1[1], tid, false);    // q
    __syncthreads();
    {   // qt[s][h*64+d] = Wk[h,d,:].q[s,h,:] ; qb[s][h] = q.bk
        const int h = tid >> 6, d = tid & 63;
#pragma unroll
        for (int sm = 0; sm < 2; sm++) {
            const float4* wk4 = reinterpret_cast<const float4*>(Wk + h * (HDIM*HDIM) + d * HDIM);
            const float4* q4  = reinterpret_cast<const float4*>(&s->v1[sm][h * HDIM]);
            float t = 0.0f;
#pragma unroll
            for (int e = 0; e < HDIM / 4; e++) {
                const float4 w = wk4[e], qv = q4[e];
                t += w.x*qv.x + w.y*qv.y + w.z*qv.z + w.w*qv.w;
            }
            s->qt[sm][tid] = t;
            if (tid < NHEAD) {
                float sb = 0.0f;
                for (int e = 0; e < HDIM; e++) sb += s->v1[sm][tid * HDIM + e] * bk[tid * HDIM + e];
                s->qb[sm][tid] = sb;
            }
        }
    }
    __syncthreads();
    if (tid < 8) {   // pq[s][h] = pb3[h-slice] . qt[s][h-slice]
        const int sm = tid >> 2, hh = tid & 3;
        float t = 0.0f;
        for (int d = 0; d < HDIM; d++) t += pb3[hh * HDIM + d] * s->qt[sm][hh * HDIM + d];
        s->pq[sm][hh] = t;
    }

    // ---- object MLP on warp MMA ----
    const int mbase = (wid >> 1) * 32;
    const int nbase = (wid & 1) * 128;
    FragC c[2][8];

    // L1: K=32 (feat cols; col31 has zero weights)
    copyB(s->Bh, s->Bl, g_B1h, g_B1l, 32, tid);
#pragma unroll
    for (int mi = 0; mi < 2; mi++)
#pragma unroll
        for (int ni = 0; ni < 8; ni++) wmma::fill_fragment(c[mi][ni], 0.0f);
    __syncthreads();
    mma_block(c, actH, actL, s->Bh, s->Bl, 2, 0, mbase, nbase);
    __syncthreads();                       // all L1 MMAs done before act overwrite
    epi_act(c, s->stg[wid], pb1, actH, actL, mbase, nbase, lane);
    __syncthreads();

    // L2: K=256 in 4 quarters
#pragma unroll
    for (int mi = 0; mi < 2; mi++)
#pragma unroll
        for (int ni = 0; ni < 8; ni++) wmma::fill_fragment(c[mi][ni], 0.0f);
    for (int q = 0; q < 4; q++) {
        copyB(s->Bh, s->Bl, g_B2h + q * 64 * HID, g_B2l + q * 64 * HID, 64, tid);
        __syncthreads();
        mma_block(c, actH, actL, s->Bh, s->Bl, 4, q * 64, mbase, nbase);
        __syncthreads();
    }
    epi_act(c, s->stg[wid], pb2, actH, actL, mbase, nbase, lane);
    __syncthreads();

    // L3: K=256 in 4 quarters -> rawP (bias folded into attention)
#pragma unroll
    for (int mi = 0; mi < 2; mi++)
#pragma unroll
        for (int ni = 0; ni < 8; ni++) wmma::fill_fragment(c[mi][ni], 0.0f);
    for (int q = 0; q < 4; q++) {
        copyB(s->Bh, s->Bl, g_B3h + q * 64 * HID, g_B3l + q * 64 * HID, 64, tid);
        __syncthreads();
        mma_block(c, actH, actL, s->Bh, s->Bl, 4, q * 64, mbase, nbase);
        __syncthreads();
    }
    // act buffers dead; store C directly as fp32 rawP into the union
#pragma unroll
    for (int mi = 0; mi < 2; mi++)
#pragma unroll
        for (int ni = 0; ni < 8; ni++)
            wmma::store_matrix_sync(&s->u.rawP[(size_t)(mbase + mi * 16) * RP + nbase + ni * 16],
                                    c[mi][ni], RP, wmma::mem_row_major);
    __syncthreads();

    // ---- attention (q-len 1; K/V folded; pb3 folded via pq/Wsum) ----
#pragma unroll
    for (int sm = 0; sm < 2; sm++) {
        const int h = tid >> 6, n = tid & 63;
        const float* rp = s->u.rawP + (size_t)(sm * 64 + n) * RP + h * HDIM;
        const float* qt = s->qt[sm] + h * HDIM;
        float dot = 0.0f;
#pragma unroll
        for (int d = 0; d < HDIM; d += 4) {
            const float4 a4 = *reinterpret_cast<const float4*>(&rp[d]);
            const float4 b4 = *reinterpret_cast<const float4*>(&qt[d]);
            dot += a4.x*b4.x + a4.y*b4.y + a4.z*b4.z + a4.w*b4.w;
        }
        const float m = s->maskv[sm * 64 + n];
        float lg = (m * (dot + s->pq[sm][h]) + s->qb[sm][h]) * 0.0625f;
        if (m == 0.0f) lg = -1000000000.0f;
        s->logit[sm][h * NOBJ + n] = lg;
    }
    __syncthreads();
    {   // softmax: 8 warps = 2 samples x 4 heads
        const int sm = wid >> 2, hh = wid & 3;
        const float x0 = s->logit[sm][hh * NOBJ + lane];
        const float x1 = s->logit[sm][hh * NOBJ + 32 + lane];
        float mx = fmaxf(x0, x1);
#pragma unroll
        for (int o = 16; o > 0; o >>= 1) mx = fmaxf(mx, __shfl_xor_sync(0xffffffffu, mx, o));
        const float e0 = expf(x0 - mx), e1 = expf(x1 - mx);
        float sum = e0 + e1;
#pragma unroll
        for (int o = 16; o > 0; o >>= 1) sum += __shfl_xor_sync(0xffffffffu, sum, o);
        const float inv = 1.0f / sum;
        const float a0 = e0 * inv, a1 = e1 * inv;
        const float m0 = s->maskv[sm * 64 + lane], m1 = s->maskv[sm * 64 + 32 + lane];
        const float w0 = a0 * m0 * m0, w1 = a1 * m1 * m1;
        s->wgt[sm][hh * NOBJ + lane]      = w0;
        s->wgt[sm][hh * NOBJ + 32 + lane] = w1;
        float tt = a0 * m0 + a1 * m1;
        float ws = w0 + w1;
#pragma unroll
        for (int o = 16; o > 0; o >>= 1) {
            tt += __shfl_xor_sync(0xffffffffu, tt, o);
            ws += __shfl_xor_sync(0xffffffffu, ws, o);
        }
        if (lane == 0) { s->Th[sm][hh] = tt; s->Wsum[sm][hh] = ws; }
    }
    __syncthreads();
#pragma unroll
    for (int sm = 0; sm < 2; sm++) {   // Svec = sum_n wgt*rawP + Wsum*pb3
        const int h = tid >> 6, d = tid & 63;
        const float* wp = s->wgt[sm] + h * NOBJ;
        float acc = 0.0f;
#pragma unroll 4
        for (int nn = 0; nn < NOBJ; nn++)
            acc = fmaf(wp[nn], s->u.rawP[(size_t)(sm * 64 + nn) * RP + h * HDIM + d], acc);
        s->Svec[sm][tid] = acc + s->Wsum[sm][h] * pb3[h * HDIM + d];
    }
    __syncthreads();
#pragma unroll
    for (int sm = 0; sm < 2; sm++) {   // out_emb = Svec @ Wv + Th*bv
        const int h = tid >> 6, e = tid & 63;
        float o = s->Th[sm][h] * bv[h * HDIM + e];
        const float* sv = s->Svec[sm] + h * HDIM;
        const float* wv = Wv + h * (HDIM * HDIM) + e;
#pragma unroll 4
        for (int d = 0; d < HDIM; d++)
            o = fmaf(sv[d], wv[d * HDIM], o);
        out[(size_t)(blockIdx.x * 2 + sm) * 512 + 256 + h * HDIM + e] = o;
    }
}

extern "C" void kernel_launch(void* const* d_in, const int* in_sizes, int n_in,
                              void* d_out, int out_size)
{
    const float* obs = (const float*)d_in[0];
    const float* oW1 = (const float*)d_in[1];
    const float* ob1 = (const float*)d_in[2];
    const float* oW2 = (const float*)d_in[3];
    const float* ob2 = (const float*)d_in[4];
    const float* pW1 = (const float*)d_in[5];
    const float* pb1 = (const float*)d_in[6];
    const float* pW2 = (const float*)d_in[7];
    const float* pb2 = (const float*)d_in[8];
    const float* pW3 = (const float*)d_in[9];
    const float* pb3 = (const float*)d_in[10];
    const float* Wq  = (const float*)d_in[11];
    const float* bq  = (const float*)d_in[12];
    const float* Wk  = (const float*)d_in[13];
    const float* bk  = (const float*)d_in[14];
    const float* Wv  = (const float*)d_in[15];
    const float* bv  = (const float*)d_in[16];
    float* out = (float*)d_out;

    __nv_bfloat16 *b1h, *b1l, *b2h, *b2l, *b3h, *b3l;
    ull *o1p, *o2p, *qp;
    cudaGetSymbolAddress((void**)&b1h, g_B1h); cudaGetSymbolAddress((void**)&b1l, g_B1l);
    cudaGetSymbolAddress((void**)&b2h, g_B2h); cudaGetSymbolAddress((void**)&b2l, g_B2l);
    cudaGetSymbolAddress((void**)&b3h, g_B3h); cudaGetSymbolAddress((void**)&b3l, g_B3l);
    cudaGetSymbolAddress((void**)&o1p, g_oW1p); cudaGetSymbolAddress((void**)&o2p, g_oW2p);
    cudaGetSymbolAddress((void**)&qp,  g_Wqp);

    build_B<<<32,  HID>>>(pW1, b1h, b1l, FEAT);   // 31 real rows, row 31 zero
    build_B<<<HID, HID>>>(pW2, b2h, b2l, HID);
    build_B<<<HID, HID>>>(pW3, b3h, b3l, HID);
    repack_pair256<<<HID/2, HID>>>(oW1, o1p);
    repack_pair256<<<HID/2, HID>>>(oW2, o2p);
    repack_pair256<<<HID/2, HID>>>(Wq,  qp);

    const int smem = (int)sizeof(Smem);
    cudaFuncSetAttribute(pinet_wmma_kernel, cudaFuncAttributeMaxDynamicSharedMemorySize, smem);
    pinet_wmma_kernel<<<GRID_N, 256, smem>>>(obs, ob1, ob2, pb1, pb2, pb3,
                                             bq, Wk, bk, Wv, bv, out);
}

// round 10
// speedup vs baseline: 3.1386x; 1.1041x over previous
#include <cuda_runtime.h>
#include <cuda_bf16.h>
#include <mma.h>
#include <math.h>
#include <stdint.h>

using namespace nvcuda;
typedef unsigned long long ull;

#define NOBJ    64
#define DOBJ    32
#define FEAT    31
#define HID     256
#define OBS_W   2304
#define OTH_OFF 2048
#define NHEAD   4
#define HDIM    64
#define MROWS   128          // 2 samples x 64 objects
#define AP      264          // act pitch (bf16)
#define BP      264          // B-tile pitch (bf16)
#define RP      264          // rawP pitch (floats)
#define GRID_N  2048

using FragA = wmma::fragment<wmma::matrix_a, 16, 16, 16, __nv_bfloat16, wmma::row_major>;
using FragB = wmma::fragment<wmma::matrix_b, 16, 16, 16, __nv_bfloat16, wmma::row_major>;
using FragC = wmma::fragment<wmma::accumulator, 16, 16, 16, float>;

// ---------------- helpers ----------------
static __device__ __forceinline__ uint32_t smem_u32(const void* p) {
    uint32_t a; asm("{ .reg .u64 t; cvta.to.shared.u64 t, %1; cvt.u32.u64 %0, t; }"
                    : "=r"(a) : "l"(p)); return a;
}
static __device__ __forceinline__ void cp16(uint32_t dst, const void* src) {
    asm volatile("cp.async.ca.shared.global [%0], [%1], 16;" :: "r"(dst), "l"(src));
}
#define CP_COMMIT() asm volatile("cp.async.commit_group;" ::: "memory")
#define CP_WAIT1()  asm volatile("cp.async.wait_group 1;" ::: "memory")
#define CP_WAIT0()  asm volatile("cp.async.wait_group 0;" ::: "memory")

static __device__ __forceinline__ ull pack2(float lo, float hi) {
    ull r; asm("mov.b64 %0,{%1,%2};" : "=l"(r) : "f"(lo), "f"(hi)); return r;
}
static __device__ __forceinline__ float2 unpack2(ull v) {
    float2 f; asm("mov.b64 {%0,%1},%2;" : "=f"(f.x), "=f"(f.y) : "l"(v)); return f;
}
static __device__ __forceinline__ ull ffma2(ull a, ull b, ull c) {
    ull d; asm("fma.rn.f32x2 %0,%1,%2,%3;" : "=l"(d) : "l"(a), "l"(b), "l"(c)); return d;
}

// ---------------- global scratch ----------------
__device__ __align__(16) __nv_bfloat16 g_B1h[32 * HID],  g_B1l[32 * HID];    // L1 (k pad 31->32)
__device__ __align__(16) __nv_bfloat16 g_B2h[HID * HID], g_B2l[HID * HID];   // L2
__device__ __align__(16) __nv_bfloat16 g_B3h[HID * HID], g_B3l[HID * HID];   // L3
__device__ ull g_oW1p[(HID/2)*HID], g_oW2p[(HID/2)*HID], g_Wqp[(HID/2)*HID];

// ONE fused prep kernel (grid 256 x block 256)
__global__ void prep_all(const float* __restrict__ pW1, const float* __restrict__ pW2,
                         const float* __restrict__ pW3, const float* __restrict__ oW1,
                         const float* __restrict__ oW2, const float* __restrict__ Wq)
{
    const int b = blockIdx.x, t = threadIdx.x;
    {   // L2/L3 row b
        const float w2 = pW2[b * HID + t];
        const __nv_bfloat16 h2 = __float2bfloat16_rn(w2);
        g_B2h[b * HID + t] = h2;
        g_B2l[b * HID + t] = __float2bfloat16_rn(w2 - __bfloat162float(h2));
        const float w3 = pW3[b * HID + t];
        const __nv_bfloat16 h3 = __float2bfloat16_rn(w3);
        g_B3h[b * HID + t] = h3;
        g_B3l[b * HID + t] = __float2bfloat16_rn(w3 - __bfloat162float(h3));
    }
    if (b < 32) {   // L1 row b (row 31 zero)
        const float w = (b < FEAT) ? pW1[b * HID + t] : 0.0f;
        const __nv_bfloat16 h = __float2bfloat16_rn(w);
        g_B1h[b * HID + t] = h;
        g_B1l[b * HID + t] = __float2bfloat16_rn(w - __bfloat162float(h));
    }
    if (b < 128) {  // pair-major packing for stage-A weights, k2 = b
        g_oW1p[b * HID + t] = pack2(oW1[(2*b) * HID + t], oW1[(2*b+1) * HID + t]);
        g_oW2p[b * HID + t] = pack2(oW2[(2*b) * HID + t], oW2[(2*b+1) * HID + t]);
        g_Wqp [b * HID + t] = pack2(Wq [(2*b) * HID + t], Wq [(2*b+1) * HID + t]);
    }
}

// ---------------- SMEM ----------------
struct Buf { __nv_bfloat16 h[32 * BP]; __nv_bfloat16 l[32 * BP]; };

struct Smem {
    union {
        struct { __nv_bfloat16 hi[MROWS * AP]; __nv_bfloat16 lo[MROWS * AP]; } act;
        float rawP[MROWS * RP];
    } u;
    Buf bufs[2];
    float stg[8][16 * 20];
    float v0[2][HID], v1[2][HID], qt[2][HID];
    float qb[2][NHEAD], pq[2][NHEAD];
    float maskv[MROWS];
    float logit[2][NHEAD * NOBJ], wgt[2][NHEAD * NOBJ];
    float Th[2][NHEAD], Wsum[2][NHEAD];
    float Svec[2][HID];
};

// async-copy one 32x256 hi/lo chunk into a Buf (4+4 int4 per thread)
static __device__ __forceinline__ void cp_chunk(Buf* buf, const __nv_bfloat16* srcH,
                                                const __nv_bfloat16* srcL, int tid) {
    const char* sh = reinterpret_cast<const char*>(srcH);
    const char* sl = reinterpret_cast<const char*>(srcL);
    const uint32_t dh = smem_u32(buf->h), dl = smem_u32(buf->l);
#pragma unroll
    for (int i = 0; i < 4; i++) {
        const int idx = tid + i * 256;        // 0..1023
        const int r = idx >> 5, c = idx & 31; // 32 int4 per 512B row
        cp16(dh + (uint32_t)(r * BP * 2 + c * 16), sh + (size_t)idx * 16);
        cp16(dl + (uint32_t)(r * BP * 2 + c * 16), sl + (size_t)idx * 16);
    }
}

// MMA over one 32-K chunk: shared a/b fragment loads across the 3 split terms
static __device__ __forceinline__ void mma_chunk(FragC (&c)[2][8],
    const __nv_bfloat16* actH, const __nv_bfloat16* actL,
    const Buf* buf, int kbase, int mbase, int nbase)
{
#pragma unroll
    for (int ks = 0; ks < 2; ks++) {
        FragA ah0, ah1, al0, al1;
        wmma::load_matrix_sync(ah0, actH + (size_t)mbase * AP + kbase + ks * 16, AP);
        wmma::load_matrix_sync(ah1, actH + (size_t)(mbase + 16) * AP + kbase + ks * 16, AP);
        wmma::load_matrix_sync(al0, actL + (size_t)mbase * AP + kbase + ks * 16, AP);
        wmma::load_matrix_sync(al1, actL + (size_t)(mbase + 16) * AP + kbase + ks * 16, AP);
#pragma unroll
        for (int nt = 0; nt < 8; nt++) {
            FragB bh, bl;
            wmma::load_matrix_sync(bh, buf->h + (size_t)(ks * 16) * BP + nbase + nt * 16, BP);
            wmma::load_matrix_sync(bl, buf->l + (size_t)(ks * 16) * BP + nbase + nt * 16, BP);
            wmma::mma_sync(c[0][nt], ah0, bh, c[0][nt]);
            wmma::mma_sync(c[1][nt], ah1, bh, c[1][nt]);
            wmma::mma_sync(c[0][nt], al0, bh, c[0][nt]);
            wmma::mma_sync(c[1][nt], al1, bh, c[1][nt]);
            wmma::mma_sync(c[0][nt], ah0, bl, c[0][nt]);
            wmma::mma_sync(c[1][nt], ah1, bl, c[1][nt]);
        }
    }
}

// 8-chunk double-buffered layer pipeline; chunks 0,1 must already be in flight.
// Chunk ch lives in bufs[(ch+PH)&1].
template<int PH>
static __device__ __forceinline__ void layer_pipe(FragC (&c)[2][8],
    const __nv_bfloat16* actH, const __nv_bfloat16* actL, Buf* bufs,
    const __nv_bfloat16* srcH, const __nv_bfloat16* srcL,
    int mbase, int nbase, int tid)
{
    for (int ch = 0; ch < 8; ch++) {
        if (ch < 7) CP_WAIT1(); else CP_WAIT0();
        __syncthreads();
        mma_chunk(c, actH, actL, &bufs[(ch + PH) & 1], ch * 32, mbase, nbase);
        __syncthreads();
        if (ch + 2 < 8) {
            cp_chunk(&bufs[(ch + PH) & 1], srcH + (ch + 2) * 32 * HID,
                     srcL + (ch + 2) * 32 * HID, tid);
            CP_COMMIT();
        }
    }
}

// epilogue: x = relu(C + bias); split to bf16 hi/lo act buffers
static __device__ __forceinline__ void epi_act(FragC (&c)[2][8], float* stg,
    const float* __restrict__ bias, __nv_bfloat16* actH, __nv_bfloat16* actL,
    int mbase, int nbase, int lane)
{
#pragma unroll
    for (int mi = 0; mi < 2; mi++)
#pragma unroll
        for (int ni = 0; ni < 8; ni++) {
            wmma::store_matrix_sync(stg, c[mi][ni], 20, wmma::mem_row_major);
            __syncwarp();
            for (int e = lane; e < 256; e += 32) {
                const int r = e >> 4, cc = e & 15;
                const int j = nbase + ni * 16 + cc;
                const int m = mbase + mi * 16 + r;
                float x = fmaxf(stg[r * 20 + cc] + __ldg(bias + j), 0.0f);
                const __nv_bfloat16 h = __float2bfloat16_rn(x);
                const __nv_bfloat16 l = __float2bfloat16_rn(x - __bfloat162float(h));
                actH[(size_t)m * AP + j] = h;
                actL[(size_t)m * AP + j] = l;
            }
            __syncwarp();
        }
}

static __device__ __forceinline__ void gemv2(const ull* __restrict__ Wp,
                                             const float* __restrict__ bias,
                                             const float* x0, const float* x1,
                                             float* y0, float* y1, int j, bool relu) {
    ull a0 = pack2(bias[j], 0.0f), a1 = a0;
    const ull* wp = Wp + j;
#pragma unroll 4
    for (int k2 = 0; k2 < HID / 2; k2 += 2) {
        const ull wA = wp[k2 * HID], wB = wp[(k2 + 1) * HID];
        const ulonglong2 u0 = *reinterpret_cast<const ulonglong2*>(x0 + 2 * k2);
        const ulonglong2 u1 = *reinterpret_cast<const ulonglong2*>(x1 + 2 * k2);
        a0 = ffma2(u0.x, wA, a0); a0 = ffma2(u0.y, wB, a0);
        a1 = ffma2(u1.x, wA, a1); a1 = ffma2(u1.y, wB, a1);
    }
    const float2 f0 = unpack2(a0), f1 = unpack2(a1);
    float r0 = f0.x + f0.y, r1 = f1.x + f1.y;
    if (relu) { r0 = fmaxf(r0, 0.0f); r1 = fmaxf(r1, 0.0f); }
    y0[j] = r0; y1[j] = r1;
}

__global__ void __launch_bounds__(256, 1) pinet_wmma_kernel(
    const float* __restrict__ obs,
    const float* __restrict__ ob1, const float* __restrict__ ob2,
    const float* __restrict__ pb1, const float* __restrict__ pb2,
    const float* __restrict__ pb3, const float* __restrict__ bq,
    const float* __restrict__ Wk,  const float* __restrict__ bk,
    const float* __restrict__ Wv,  const float* __restrict__ bv,
    float* __restrict__ out)
{
    extern __shared__ char smraw[];
    Smem* s = reinterpret_cast<Smem*>(smraw);
    const int tid = threadIdx.x, wid = tid >> 5, lane = tid & 31;
    __nv_bfloat16* actH = s->u.act.hi;
    __nv_bfloat16* actL = s->u.act.lo;

    // ---- prefetch L1 weights (buf0) and L2 chunk0 (buf1) immediately ----
    cp_chunk(&s->bufs[0], g_B1h, g_B1l, tid); CP_COMMIT();
    cp_chunk(&s->bufs[1], g_B2h, g_B2l, tid); CP_COMMIT();

    // ---- load obs: feats -> act bf16 hi/lo (cols 0..31), mask, others ----
    {
        const float* r0 = obs + (size_t)(blockIdx.x * 2 + 0) * OBS_W;
        const float* r1 = obs + (size_t)(blockIdx.x * 2 + 1) * OBS_W;
        for (int i = tid; i < 512; i += 256) {
            const float4 a = reinterpret_cast<const float4*>(r0)[i];
            const float4 b = reinterpret_cast<const float4*>(r1)[i];
            const int m0 = i >> 3, d4 = (i & 7) * 4;
            const float va[8] = {a.x, a.y, a.z, a.w, b.x, b.y, b.z, b.w};
#pragma unroll
            for (int smp = 0; smp < 2; smp++) {
                const int m = smp * 64 + m0;
#pragma unroll
                for (int e = 0; e < 4; e++) {
                    const float x = va[smp * 4 + e];
                    const __nv_bfloat16 h = __float2bfloat16_rn(x);
                    const __nv_bfloat16 l = __float2bfloat16_rn(x - __bfloat162float(h));
                    actH[(size_t)m * AP + d4 + e] = h;
                    actL[(size_t)m * AP + d4 + e] = l;
                }
            }
            if ((i & 7) == 7) { s->maskv[m0] = a.w; s->maskv[64 + m0] = b.w; }
        }
        s->v0[0][tid] = r0[OTH_OFF + tid];
        s->v0[1][tid] = r1[OTH_OFF + tid];
    }
    __syncthreads();

    // ---- stage A (overlaps the in-flight cp.async) ----
    gemv2(g_oW1p, ob1, s->v0[0], s->v0[1], s->v1[0], s->v1[1], tid, true);
    __syncthreads();
    gemv2(g_oW2p, ob2, s->v1[0], s->v1[1], s->v0[0], s->v0[1], tid, false);
    out[(size_t)(blockIdx.x * 2 + 0) * 512 + tid] = s->v0[0][tid];
    out[(size_t)(blockIdx.x * 2 + 1) * 512 + tid] = s->v0[1][tid];
    __syncthreads();
    gemv2(g_Wqp, bq, s->v0[0], s->v0[1], s->v1[0], s->v1[1], tid, false);
    __syncthreads();
    {
        const int h = tid >> 6, d = tid & 63;
#pragma unroll
        for (int sm = 0; sm < 2; sm++) {
            const float4* wk4 = reinterpret_cast<const float4*>(Wk + h * (HDIM*HDIM) + d * HDIM);
            const float4* q4  = reinterpret_cast<const float4*>(&s->v1[sm][h * HDIM]);
            float t = 0.0f;
#pragma unroll
            for (int e = 0; e < HDIM / 4; e++) {
                const float4 w = wk4[e], qv = q4[e];
                t += w.x*qv.x + w.y*qv.y + w.z*qv.z + w.w*qv.w;
            }
            s->qt[sm][tid] = t;
            if (tid < NHEAD) {
                float sb = 0.0f;
                for (int e = 0; e < HDIM; e++) sb += s->v1[sm][tid * HDIM + e] * bk[tid * HDIM + e];
                s->qb[sm][tid] = sb;
            }
        }
    }
    __syncthreads();
    if (tid < 8) {
        const int sm = tid >> 2, hh = tid & 3;
        float t = 0.0f;
        for (int d = 0; d < HDIM; d++) t += pb3[hh * HDIM + d] * s->qt[sm][hh * HDIM + d];
        s->pq[sm][hh] = t;
    }

    // ---- object MLP on warp MMA, cp.async pipelined ----
    const int mbase = (wid >> 1) * 32;
    const int nbase = (wid & 1) * 128;
    FragC c[2][8];

    // L1 (weights already in buf0; K=32, one chunk)
#pragma unroll
    for (int mi = 0; mi < 2; mi++)
#pragma unroll
        for (int ni = 0; ni < 8; ni++) wmma::fill_fragment(c[mi][ni], 0.0f);
    CP_WAIT1();                 // L1 done (L2c0 may still be in flight)
    __syncthreads();
    mma_chunk(c, actH, actL, &s->bufs[0], 0, mbase, nbase);
    __syncthreads();
    cp_chunk(&s->bufs[0], g_B2h + 32 * HID, g_B2l + 32 * HID, tid);  // L2 chunk1 -> buf0
    CP_COMMIT();
    epi_act(c, s->stg[wid], pb1, actH, actL, mbase, nbase, lane);
    __syncthreads();

    // L2: chunks 0..7, chunk ch in bufs[(ch+1)&1]
#pragma unroll
    for (int mi = 0; mi < 2; mi++)
#pragma unroll
        for (int ni = 0; ni < 8; ni++) wmma::fill_fragment(c[mi][ni], 0.0f);
    layer_pipe<1>(c, actH, actL, s->bufs, g_B2h, g_B2l, mbase, nbase, tid);
    // prefetch L3 chunks 0,1 (both buffers free), then epilogue
    cp_chunk(&s->bufs[0], g_B3h, g_B3l, tid); CP_COMMIT();
    cp_chunk(&s->bufs[1], g_B3h + 32 * HID, g_B3l + 32 * HID, tid); CP_COMMIT();
    epi_act(c, s->stg[wid], pb2, actH, actL, mbase, nbase, lane);
    __syncthreads();

    // L3: chunk ch in bufs[ch&1]
#pragma unroll
    for (int mi = 0; mi < 2; mi++)
#pragma unroll
        for (int ni = 0; ni < 8; ni++) wmma::fill_fragment(c[mi][ni], 0.0f);
    layer_pipe<0>(c, actH, actL, s->bufs, g_B3h, g_B3l, mbase, nbase, tid);
    // act dead; store fp32 rawP into the union
#pragma unroll
    for (int mi = 0; mi < 2; mi++)
#pragma unroll
        for (int ni = 0; ni < 8; ni++)
            wmma::store_matrix_sync(&s->u.rawP[(size_t)(mbase + mi * 16) * RP + nbase + ni * 16],
                                    c[mi][ni], RP, wmma::mem_row_major);
    __syncthreads();

    // ---- attention (q-len 1; K/V folded; pb3 folded via pq/Wsum) ----
#pragma unroll
    for (int sm = 0; sm < 2; sm++) {
        const int h = tid >> 6, n = tid & 63;
        const float* rp = s->u.rawP + (size_t)(sm * 64 + n) * RP + h * HDIM;
        const float* qt = s->qt[sm] + h * HDIM;
        float dot = 0.0f;
#pragma unroll
        for (int d = 0; d < HDIM; d += 4) {
            const float4 a4 = *reinterpret_cast<const float4*>(&rp[d]);
            const float4 b4 = *reinterpret_cast<const float4*>(&qt[d]);
            dot += a4.x*b4.x + a4.y*b4.y + a4.z*b4.z + a4.w*b4.w;
        }
        const float m = s->maskv[sm * 64 + n];
        float lg = (m * (dot + s->pq[sm][h]) + s->qb[sm][h]) * 0.0625f;
        if (m == 0.0f) lg = -1000000000.0f;
        s->logit[sm][h * NOBJ + n] = lg;
    }
    __syncthreads();
    {
        const int sm = wid >> 2, hh = wid & 3;
        const float x0 = s->logit[sm][hh * NOBJ + lane];
        const float x1 = s->logit[sm][hh * NOBJ + 32 + lane];
        float mx = fmaxf(x0, x1);
#pragma unroll
        for (int o = 16; o > 0; o >>= 1) mx = fmaxf(mx, __shfl_xor_sync(0xffffffffu, mx, o));
        const float e0 = expf(x0 - mx), e1 = expf(x1 - mx);
        float sum = e0 + e1;
#pragma unroll
        for (int o = 16; o > 0; o >>= 1) sum += __shfl_xor_sync(0xffffffffu, sum, o);
        const float inv = 1.0f / sum;
        const float a0 = e0 * inv, a1 = e1 * inv;
        const float m0 = s->maskv[sm * 64 + lane], m1 = s->maskv[sm * 64 + 32 + lane];
        const float w0 = a0 * m0 * m0, w1 = a1 * m1 * m1;
        s->wgt[sm][hh * NOBJ + lane]      = w0;
        s->wgt[sm][hh * NOBJ + 32 + lane] = w1;
        float tt = a0 * m0 + a1 * m1;
        float ws = w0 + w1;
#pragma unroll
        for (int o = 16; o > 0; o >>= 1) {
            tt += __shfl_xor_sync(0xffffffffu, tt, o);
            ws += __shfl_xor_sync(0xffffffffu, ws, o);
        }
        if (lane == 0) { s->Th[sm][hh] = tt; s->Wsum[sm][hh] = ws; }
    }
    __syncthreads();
#pragma unroll
    for (int sm = 0; sm < 2; sm++) {
        const int h = tid >> 6, d = tid & 63;
        const float* wp = s->wgt[sm] + h * NOBJ;
        float acc = 0.0f;
#pragma unroll 4
        for (int nn = 0; nn < NOBJ; nn++)
            acc = fmaf(wp[nn], s->u.rawP[(size_t)(sm * 64 + nn) * RP + h * HDIM + d], acc);
        s->Svec[sm][tid] = acc + s->Wsum[sm][h] * pb3[h * HDIM + d];
    }
    __syncthreads();
#pragma unroll
    for (int sm = 0; sm < 2; sm++) {
        const int h = tid >> 6, e = tid & 63;
        float o = s->Th[sm][h] * bv[h * HDIM + e];
        const float* sv = s->Svec[sm] + h * HDIM;
        const float* wv = Wv + h * (HDIM * HDIM) + e;
#pragma unroll 4
        for (int d = 0; d < HDIM; d++)
            o = fmaf(sv[d], wv[d * HDIM], o);
        out[(size_t)(blockIdx.x * 2 + sm) * 512 + 256 + h * HDIM + e] = o;
    }
}

extern "C" void kernel_launch(void* const* d_in, const int* in_sizes, int n_in,
                              void* d_out, int out_size)
{
    const float* obs = (const float*)d_in[0];
    const float* oW1 = (const float*)d_in[1];
    const float* ob1 = (const float*)d_in[2];
    const float* oW2 = (const float*)d_in[3];
    const float* ob2 = (const float*)d_in[4];
    const float* pW1 = (const float*)d_in[5];
    const float* pb1 = (const float*)d_in[6];
    const float* pW2 = (const float*)d_in[7];
    const float* pb2 = (const float*)d_in[8];
    const float* pW3 = (const float*)d_in[9];
    const float* pb3 = (const float*)d_in[10];
    const float* Wq  = (const float*)d_in[11];
    const float* bq  = (const float*)d_in[12];
    const float* Wk  = (const float*)d_in[13];
    const float* bk  = (const float*)d_in[14];
    const float* Wv  = (const float*)d_in[15];
    const float* bv  = (const float*)d_in[16];
    float* out = (float*)d_out;

    prep_all<<<256, 256>>>(pW1, pW2, pW3, oW1, oW2, Wq);

    const int smem = (int)sizeof(Smem);
    cudaFuncSetAttribute(pinet_wmma_kernel, cudaFuncAttributeMaxDynamicSharedMemorySize, smem);
    pinet_wmma_kernel<<<GRID_N, 256, smem>>>(obs, ob1, ob2, pb1, pb2, pb3,
                                             bq, Wk, bk, Wv, bv, out);
}

// round 11
// speedup vs baseline: 3.4964x; 1.1140x over previous
#include <cuda_runtime.h>
#include <cuda_bf16.h>
#include <mma.h>
#include <math.h>
#include <stdint.h>

using namespace nvcuda;
typedef unsigned long long ull;

#define NOBJ    64
#define DOBJ    32
#define FEAT    31
#define HID     256
#define OBS_W   2304
#define OTH_OFF 2048
#define NHEAD   4
#define HDIM    64
#define MROWS   128          // 2 samples x 64 objects
#define AP      264          // act pitch (bf16)
#define BP      264          // B-tile pitch (bf16)
#define RP      264          // rawP pitch (floats)
#define GRID_N  2048
#define NTHR    512

using FragA = wmma::fragment<wmma::matrix_a, 16, 16, 16, __nv_bfloat16, wmma::row_major>;
using FragB = wmma::fragment<wmma::matrix_b, 16, 16, 16, __nv_bfloat16, wmma::row_major>;
using FragC = wmma::fragment<wmma::accumulator, 16, 16, 16, float>;

// ---------------- helpers ----------------
static __device__ __forceinline__ uint32_t smem_u32(const void* p) {
    uint32_t a; asm("{ .reg .u64 t; cvta.to.shared.u64 t, %1; cvt.u32.u64 %0, t; }"
                    : "=r"(a) : "l"(p)); return a;
}
static __device__ __forceinline__ void cp16(uint32_t dst, const void* src) {
    asm volatile("cp.async.ca.shared.global [%0], [%1], 16;" :: "r"(dst), "l"(src));
}
#define CP_COMMIT() asm volatile("cp.async.commit_group;" ::: "memory")
#define CP_WAIT1()  asm volatile("cp.async.wait_group 1;" ::: "memory")
#define CP_WAIT0()  asm volatile("cp.async.wait_group 0;" ::: "memory")

static __device__ __forceinline__ ull pack2(float lo, float hi) {
    ull r; asm("mov.b64 %0,{%1,%2};" : "=l"(r) : "f"(lo), "f"(hi)); return r;
}
static __device__ __forceinline__ float2 unpack2(ull v) {
    float2 f; asm("mov.b64 {%0,%1},%2;" : "=f"(f.x), "=f"(f.y) : "l"(v)); return f;
}
static __device__ __forceinline__ ull ffma2(ull a, ull b, ull c) {
    ull d; asm("fma.rn.f32x2 %0,%1,%2,%3;" : "=l"(d) : "l"(a), "l"(b), "l"(c)); return d;
}

// ---------------- global scratch ----------------
__device__ __align__(16) __nv_bfloat16 g_B1h[32 * HID],  g_B1l[32 * HID];    // L1 (k pad 31->32)
__device__ __align__(16) __nv_bfloat16 g_B2h[HID * HID], g_B2l[HID * HID];   // L2
__device__ __align__(16) __nv_bfloat16 g_B3h[HID * HID], g_B3l[HID * HID];   // L3
__device__ ull g_oW1p[(HID/2)*HID], g_oW2p[(HID/2)*HID], g_Wqp[(HID/2)*HID];

// ONE fused prep kernel (grid 256 x block 256)
__global__ void prep_all(const float* __restrict__ pW1, const float* __restrict__ pW2,
                         const float* __restrict__ pW3, const float* __restrict__ oW1,
                         const float* __restrict__ oW2, const float* __restrict__ Wq)
{
    const int b = blockIdx.x, t = threadIdx.x;
    {   // L2/L3 row b
        const float w2 = pW2[b * HID + t];
        const __nv_bfloat16 h2 = __float2bfloat16_rn(w2);
        g_B2h[b * HID + t] = h2;
        g_B2l[b * HID + t] = __float2bfloat16_rn(w2 - __bfloat162float(h2));
        const float w3 = pW3[b * HID + t];
        const __nv_bfloat16 h3 = __float2bfloat16_rn(w3);
        g_B3h[b * HID + t] = h3;
        g_B3l[b * HID + t] = __float2bfloat16_rn(w3 - __bfloat162float(h3));
    }
    if (b < 32) {   // L1 row b (row 31 zero)
        const float w = (b < FEAT) ? pW1[b * HID + t] : 0.0f;
        const __nv_bfloat16 h = __float2bfloat16_rn(w);
        g_B1h[b * HID + t] = h;
        g_B1l[b * HID + t] = __float2bfloat16_rn(w - __bfloat162float(h));
    }
    if (b < 128) {  // pair-major packing for stage-A weights, k2 = b
        g_oW1p[b * HID + t] = pack2(oW1[(2*b) * HID + t], oW1[(2*b+1) * HID + t]);
        g_oW2p[b * HID + t] = pack2(oW2[(2*b) * HID + t], oW2[(2*b+1) * HID + t]);
        g_Wqp [b * HID + t] = pack2(Wq [(2*b) * HID + t], Wq [(2*b+1) * HID + t]);
    }
}

// ---------------- SMEM ----------------
struct Buf { __nv_bfloat16 h[32 * BP]; __nv_bfloat16 l[32 * BP]; };

struct Smem {
    union {
        struct { __nv_bfloat16 hi[MROWS * AP]; __nv_bfloat16 lo[MROWS * AP]; } act;
        float rawP[MROWS * RP];
    } u;
    Buf bufs[2];
    float stg[16][256];                      // per-warp 16x16 C staging (ldm=16)
    float v0[2][HID], v1[2][HID], qt[2][HID];
    float qb[2][NHEAD], pq[2][NHEAD];
    float maskv[MROWS];
    float logit[2][NHEAD * NOBJ], wgt[2][NHEAD * NOBJ];
    float Th[2][NHEAD], Wsum[2][NHEAD];
    float Svec[2][HID];
};

// async-copy one 32x256 hi/lo chunk into a Buf (2+2 int4 per thread @512thr)
static __device__ __forceinline__ void cp_chunk(Buf* buf, const __nv_bfloat16* srcH,
                                                const __nv_bfloat16* srcL, int tid) {
    const char* sh = reinterpret_cast<const char*>(srcH);
    const char* sl = reinterpret_cast<const char*>(srcL);
    const uint32_t dh = smem_u32(buf->h), dl = smem_u32(buf->l);
#pragma unroll
    for (int i = 0; i < 2; i++) {
        const int idx = tid + i * NTHR;       // 0..1023
        const int r = idx >> 5, c = idx & 31; // 32 int4 per 512B row
        cp16(dh + (uint32_t)(r * BP * 2 + c * 16), sh + (size_t)idx * 16);
        cp16(dl + (uint32_t)(r * BP * 2 + c * 16), sl + (size_t)idx * 16);
    }
}

// MMA over one 32-K chunk: warp tile 32x64 (c[2][4]); 3-term bf16 split
static __device__ __forceinline__ void mma_chunk(FragC (&c)[2][4],
    const __nv_bfloat16* actH, const __nv_bfloat16* actL,
    const Buf* buf, int kbase, int mbase, int nbase)
{
#pragma unroll
    for (int ks = 0; ks < 2; ks++) {
        FragA ah0, ah1, al0, al1;
        wmma::load_matrix_sync(ah0, actH + (size_t)mbase * AP + kbase + ks * 16, AP);
        wmma::load_matrix_sync(ah1, actH + (size_t)(mbase + 16) * AP + kbase + ks * 16, AP);
        wmma::load_matrix_sync(al0, actL + (size_t)mbase * AP + kbase + ks * 16, AP);
        wmma::load_matrix_sync(al1, actL + (size_t)(mbase + 16) * AP + kbase + ks * 16, AP);
#pragma unroll
        for (int nt = 0; nt < 4; nt++) {
            FragB bh, bl;
            wmma::load_matrix_sync(bh, buf->h + (size_t)(ks * 16) * BP + nbase + nt * 16, BP);
            wmma::load_matrix_sync(bl, buf->l + (size_t)(ks * 16) * BP + nbase + nt * 16, BP);
            wmma::mma_sync(c[0][nt], ah0, bh, c[0][nt]);
            wmma::mma_sync(c[1][nt], ah1, bh, c[1][nt]);
            wmma::mma_sync(c[0][nt], al0, bh, c[0][nt]);
            wmma::mma_sync(c[1][nt], al1, bh, c[1][nt]);
            wmma::mma_sync(c[0][nt], ah0, bl, c[0][nt]);
            wmma::mma_sync(c[1][nt], ah1, bl, c[1][nt]);
        }
    }
}

// 8-chunk double-buffered layer pipeline; chunks 0,1 already in flight.
// Chunk ch lives in bufs[(ch+PH)&1].
template<int PH>
static __device__ __forceinline__ void layer_pipe(FragC (&c)[2][4],
    const __nv_bfloat16* actH, const __nv_bfloat16* actL, Buf* bufs,
    const __nv_bfloat16* srcH, const __nv_bfloat16* srcL,
    int mbase, int nbase, int tid)
{
    for (int ch = 0; ch < 8; ch++) {
        if (ch < 7) CP_WAIT1(); else CP_WAIT0();
        __syncthreads();
        mma_chunk(c, actH, actL, &bufs[(ch + PH) & 1], ch * 32, mbase, nbase);
        __syncthreads();
        if (ch + 2 < 8) {
            cp_chunk(&bufs[(ch + PH) & 1], srcH + (ch + 2) * 32 * HID,
                     srcL + (ch + 2) * 32 * HID, tid);
            CP_COMMIT();
        }
    }
}

// epilogue: x = relu(C + bias); split to bf16 hi/lo act buffers (packed STS.32)
static __device__ __forceinline__ void epi_act(FragC (&c)[2][4], float* stg,
    const float* __restrict__ bias, __nv_bfloat16* actH, __nv_bfloat16* actL,
    int mbase, int nbase, int lane)
{
#pragma unroll
    for (int mi = 0; mi < 2; mi++)
#pragma unroll
        for (int ni = 0; ni < 4; ni++) {
            wmma::store_matrix_sync(stg, c[mi][ni], 16, wmma::mem_row_major);
            __syncwarp();
#pragma unroll
            for (int e = lane; e < 128; e += 32) {
                const int r = e >> 3, c2 = (e & 7) * 2;
                const int j = nbase + ni * 16 + c2;
                const int m = mbase + mi * 16 + r;
                const float x0 = fmaxf(stg[r * 16 + c2]     + __ldg(bias + j),     0.0f);
                const float x1 = fmaxf(stg[r * 16 + c2 + 1] + __ldg(bias + j + 1), 0.0f);
                const __nv_bfloat16 h0 = __float2bfloat16_rn(x0), h1 = __float2bfloat16_rn(x1);
                const __nv_bfloat16 l0 = __float2bfloat16_rn(x0 - __bfloat162float(h0));
                const __nv_bfloat16 l1 = __float2bfloat16_rn(x1 - __bfloat162float(h1));
                *reinterpret_cast<uint32_t*>(&actH[(size_t)m * AP + j]) =
                    (uint32_t)__bfloat16_as_ushort(h0) | ((uint32_t)__bfloat16_as_ushort(h1) << 16);
                *reinterpret_cast<uint32_t*>(&actL[(size_t)m * AP + j]) =
                    (uint32_t)__bfloat16_as_ushort(l0) | ((uint32_t)__bfloat16_as_ushort(l1) << 16);
            }
            __syncwarp();
        }
}

// 256->256 GEMV for one sample (thread j of that sample's 256-thread group)
static __device__ __forceinline__ void gemv1(const ull* __restrict__ Wp,
                                             const float* __restrict__ bias,
                                             const float* x, float* y, int j, bool relu) {
    ull a = pack2(bias[j], 0.0f);
    const ull* wp = Wp + j;
#pragma unroll 4
    for (int k2 = 0; k2 < HID / 2; k2 += 2) {
        const ulonglong2 u = *reinterpret_cast<const ulonglong2*>(x + 2 * k2);
        a = ffma2(u.x, wp[k2 * HID], a);
        a = ffma2(u.y, wp[(k2 + 1) * HID], a);
    }
    const float2 f = unpack2(a);
    float r = f.x + f.y;
    if (relu) r = fmaxf(r, 0.0f);
    y[j] = r;
}

__global__ void __launch_bounds__(NTHR, 1) pinet_wmma_kernel(
    const float* __restrict__ obs,
    const float* __restrict__ ob1, const float* __restrict__ ob2,
    const float* __restrict__ pb1, const float* __restrict__ pb2,
    const float* __restrict__ pb3, const float* __restrict__ bq,
    const float* __restrict__ Wk,  const float* __restrict__ bk,
    const float* __restrict__ Wv,  const float* __restrict__ bv,
    float* __restrict__ out)
{
    extern __shared__ char smraw[];
    Smem* s = reinterpret_cast<Smem*>(smraw);
    const int tid = threadIdx.x, wid = tid >> 5, lane = tid & 31;
    const int smp = tid >> 8, idx = tid & 255;   // stage-A/attention mapping
    __nv_bfloat16* actH = s->u.act.hi;
    __nv_bfloat16* actL = s->u.act.lo;

    // ---- prefetch L1 weights (buf0) and L2 chunk0 (buf1) immediately ----
    cp_chunk(&s->bufs[0], g_B1h, g_B1l, tid); CP_COMMIT();
    cp_chunk(&s->bufs[1], g_B2h, g_B2l, tid); CP_COMMIT();

    const float* r0 = obs + (size_t)(blockIdx.x * 2 + 0) * OBS_W;
    const float* r1 = obs + (size_t)(blockIdx.x * 2 + 1) * OBS_W;

    // ---- load obs: feats -> act bf16 hi/lo (cols 0..31), mask, others ----
    {
        const int i = tid;                    // one float4 per sample per thread
        const float4 a = reinterpret_cast<const float4*>(r0)[i];
        const float4 b = reinterpret_cast<const float4*>(r1)[i];
        const int m0 = i >> 3, d4 = (i & 7) * 4;
        const float va[8] = {a.x, a.y, a.z, a.w, b.x, b.y, b.z, b.w};
#pragma unroll
        for (int sm = 0; sm < 2; sm++) {
            const int m = sm * 64 + m0;
#pragma unroll
            for (int e = 0; e < 4; e++) {
                const float x = va[sm * 4 + e];
                const __nv_bfloat16 h = __float2bfloat16_rn(x);
                const __nv_bfloat16 l = __float2bfloat16_rn(x - __bfloat162float(h));
                actH[(size_t)m * AP + d4 + e] = h;
                actL[(size_t)m * AP + d4 + e] = l;
            }
        }
        if ((i & 7) == 7) { s->maskv[m0] = a.w; s->maskv[64 + m0] = b.w; }
        s->v0[smp][idx] = (smp == 0) ? r0[OTH_OFF + idx] : r1[OTH_OFF + idx];
    }
    __syncthreads();

    // ---- stage A (512 threads = 2 samples x 256 cols; overlaps cp.async) ----
    gemv1(g_oW1p, ob1, s->v0[smp], s->v1[smp], idx, true);
    __syncthreads();
    gemv1(g_oW2p, ob2, s->v1[smp], s->v0[smp], idx, false);       // others_e
    out[(size_t)(blockIdx.x * 2 + smp) * 512 + idx] = s->v0[smp][idx];
    __syncthreads();
    gemv1(g_Wqp, bq, s->v0[smp], s->v1[smp], idx, false);         // q
    __syncthreads();
    {   // qt[s][h*64+d] = Wk[h,d,:].q[s,h,:] ; qb[s][h] = q.bk
        const int h = idx >> 6, d = idx & 63;
        const float4* wk4 = reinterpret_cast<const float4*>(Wk + h * (HDIM*HDIM) + d * HDIM);
        const float4* q4  = reinterpret_cast<const float4*>(&s->v1[smp][h * HDIM]);
        float t = 0.0f;
#pragma unroll
        for (int e = 0; e < HDIM / 4; e++) {
            const float4 w = wk4[e], qv = q4[e];
            t += w.x*qv.x + w.y*qv.y + w.z*qv.z + w.w*qv.w;
        }
        s->qt[smp][idx] = t;
        if (idx < NHEAD) {
            float sb = 0.0f;
            for (int e = 0; e < HDIM; e++) sb += s->v1[smp][idx * HDIM + e] * bk[idx * HDIM + e];
            s->qb[smp][idx] = sb;
        }
    }
    __syncthreads();
    if (tid < 8) {   // pq[s][h] = pb3[h-slice] . qt[s][h-slice]
        const int sm = tid >> 2, hh = tid & 3;
        float t = 0.0f;
        for (int d = 0; d < HDIM; d++) t += pb3[hh * HDIM + d] * s->qt[sm][hh * HDIM + d];
        s->pq[sm][hh] = t;
    }

    // ---- object MLP on warp MMA, cp.async pipelined; warp tile 32x64 ----
    const int mbase = (wid >> 2) * 32;
    const int nbase = (wid & 3) * 64;
    FragC c[2][4];

    // L1 (weights already in buf0; K=32, one chunk)
#pragma unroll
    for (int mi = 0; mi < 2; mi++)
#pragma unroll
        for (int ni = 0; ni < 4; ni++) wmma::fill_fragment(c[mi][ni], 0.0f);
    CP_WAIT1();                 // L1 done (L2c0 may still be in flight)
    __syncthreads();
    mma_chunk(c, actH, actL, &s->bufs[0], 0, mbase, nbase);
    __syncthreads();
    cp_chunk(&s->bufs[0], g_B2h + 32 * HID, g_B2l + 32 * HID, tid);  // L2 chunk1 -> buf0
    CP_COMMIT();
    epi_act(c, s->stg[wid], pb1, actH, actL, mbase, nbase, lane);
    __syncthreads();

    // L2: chunks 0..7, chunk ch in bufs[(ch+1)&1]
#pragma unroll
    for (int mi = 0; mi < 2; mi++)
#pragma unroll
        for (int ni = 0; ni < 4; ni++) wmma::fill_fragment(c[mi][ni], 0.0f);
    layer_pipe<1>(c, actH, actL, s->bufs, g_B2h, g_B2l, mbase, nbase, tid);
    // prefetch L3 chunks 0,1 (both buffers free), then epilogue
    cp_chunk(&s->bufs[0], g_B3h, g_B3l, tid); CP_COMMIT();
    cp_chunk(&s->bufs[1], g_B3h + 32 * HID, g_B3l + 32 * HID, tid); CP_COMMIT();
    epi_act(c, s->stg[wid], pb2, actH, actL, mbase, nbase, lane);
    __syncthreads();

    // L3: chunk ch in bufs[ch&1]
#pragma unroll
    for (int mi = 0; mi < 2; mi++)
#pragma unroll
        for (int ni = 0; ni < 4; ni++) wmma::fill_fragment(c[mi][ni], 0.0f);
    layer_pipe<0>(c, actH, actL, s->bufs, g_B3h, g_B3l, mbase, nbase, tid);
    // act dead; store fp32 rawP into the union
#pragma unroll
    for (int mi = 0; mi < 2; mi++)
#pragma unroll
        for (int ni = 0; ni < 4; ni++)
            wmma::store_matrix_sync(&s->u.rawP[(size_t)(mbase + mi * 16) * RP + nbase + ni * 16],
                                    c[mi][ni], RP, wmma::mem_row_major);
    __syncthreads();

    // ---- attention (q-len 1; K/V folded; pb3 folded via pq/Wsum) ----
    {
        const int h = idx >> 6, n = idx & 63;
        const float* rp = s->u.rawP + (size_t)(smp * 64 + n) * RP + h * HDIM;
        const float* qt = s->qt[smp] + h * HDIM;
        float dot = 0.0f;
#pragma unroll
        for (int d = 0; d < HDIM; d += 4) {
            const float4 a4 = *reinterpret_cast<const float4*>(&rp[d]);
            const float4 b4 = *reinterpret_cast<const float4*>(&qt[d]);
            dot += a4.x*b4.x + a4.y*b4.y + a4.z*b4.z + a4.w*b4.w;
        }
        const float m = s->maskv[smp * 64 + n];
        float lg = (m * (dot + s->pq[smp][h]) + s->qb[smp][h]) * 0.0625f;
        if (m == 0.0f) lg = -1000000000.0f;
        s->logit[smp][h * NOBJ + n] = lg;
    }
    __syncthreads();
    if (wid < 8) {   // softmax: 8 warp-tasks = 2 samples x 4 heads
        const int sm = wid >> 2, hh = wid & 3;
        const float x0 = s->logit[sm][hh * NOBJ + lane];
        const float x1 = s->logit[sm][hh * NOBJ + 32 + lane];
        float mx = fmaxf(x0, x1);
#pragma unroll
        for (int o = 16; o > 0; o >>= 1) mx = fmaxf(mx, __shfl_xor_sync(0xffffffffu, mx, o));
        const float e0 = expf(x0 - mx), e1 = expf(x1 - mx);
        float sum = e0 + e1;
#pragma unroll
        for (int o = 16; o > 0; o >>= 1) sum += __shfl_xor_sync(0xffffffffu, sum, o);
        const float inv = 1.0f / sum;
        const float a0 = e0 * inv, a1 = e1 * inv;
        const float m0 = s->maskv[sm * 64 + lane], m1 = s->maskv[sm * 64 + 32 + lane];
        const float w0 = a0 * m0 * m0, w1 = a1 * m1 * m1;
        s->wgt[sm][hh * NOBJ + lane]      = w0;
        s->wgt[sm][hh * NOBJ + 32 + lane] = w1;
        float tt = a0 * m0 + a1 * m1;
        float ws = w0 + w1;
#pragma unroll
        for (int o = 16; o > 0; o >>= 1) {
            tt += __shfl_xor_sync(0xffffffffu, tt, o);
            ws += __shfl_xor_sync(0xffffffffu, ws, o);
        }
        if (lane == 0) { s->Th[sm][hh] = tt; s->Wsum[sm][hh] = ws; }
    }
    __syncthreads();
    {   // Svec = sum_n wgt*rawP + Wsum*pb3
        const int h = idx >> 6, d = idx & 63;
        const float* wp = s->wgt[smp] + h * NOBJ;
        float acc = 0.0f;
#pragma unroll 4
        for (int nn = 0; nn < NOBJ; nn++)
            acc = fmaf(wp[nn], s->u.rawP[(size_t)(smp * 64 + nn) * RP + h * HDIM + d], acc);
        s->Svec[smp][idx] = acc + s->Wsum[smp][h] * pb3[h * HDIM + d];
    }
    __syncthreads();
    {   // out_emb = Svec @ Wv + Th*bv
        const int h = idx >> 6, e = idx & 63;
        float o = s->Th[smp][h] * bv[h * HDIM + e];
        const float* sv = s->Svec[smp] + h * HDIM;
        const float* wv = Wv + h * (HDIM * HDIM) + e;
#pragma unroll 4
        for (int d = 0; d < HDIM; d++)
            o = fmaf(sv[d], wv[d * HDIM], o);
        out[(size_t)(blockIdx.x * 2 + smp) * 512 + 256 + h * HDIM + e] = o;
    }
}

extern "C" void kernel_launch(void* const* d_in, const int* in_sizes, int n_in,
                              void* d_out, int out_size)
{
    const float* obs = (const float*)d_in[0];
    const float* oW1 = (const float*)d_in[1];
    const float* ob1 = (const float*)d_in[2];
    const float* oW2 = (const float*)d_in[3];
    const float* ob2 = (const float*)d_in[4];
    const float* pW1 = (const float*)d_in[5];
    const float* pb1 = (const float*)d_in[6];
    const float* pW2 = (const float*)d_in[7];
    const float* pb2 = (const float*)d_in[8];
    const float* pW3 = (const float*)d_in[9];
    const float* pb3 = (const float*)d_in[10];
    const float* Wq  = (const float*)d_in[11];
    const float* bq  = (const float*)d_in[12];
    const float* Wk  = (const float*)d_in[13];
    const float* bk  = (const float*)d_in[14];
    const float* Wv  = (const float*)d_in[15];
    const float* bv  = (const float*)d_in[16];
    float* out = (float*)d_out;

    prep_all<<<256, 256>>>(pW1, pW2, pW3, oW1, oW2, Wq);

    const int smem = (int)sizeof(Smem);
    cudaFuncSetAttribute(pinet_wmma_kernel, cudaFuncAttributeMaxDynamicSharedMemorySize, smem);
    pinet_wmma_kernel<<<GRID_N, NTHR, smem>>>(obs, ob1, ob2, pb1, pb2, pb3,
                                              bq, Wk, bk, Wv, bv, out);
}

// round 12
// speedup vs baseline: 3.6447x; 1.0424x over previous
#include <cuda_runtime.h>
#include <cuda_bf16.h>
#include <mma.h>
#include <math.h>
#include <stdint.h>

using namespace nvcuda;
typedef unsigned long long ull;

#define NOBJ    64
#define FEAT    31
#define HID     256
#define OBS_W   2304
#define OTH_OFF 2048
#define NHEAD   4
#define HDIM    64
#define MROWS   64           // 1 sample x 64 objects per CTA
#define AP      264          // act pitch (bf16)
#define BP      264          // B-tile pitch (bf16)
#define RP      264          // rawP pitch (floats)
#define GRID_N  4096
#define NTHR    256
#define CHROWS  16           // K-rows per weight chunk
#define CHELE   (CHROWS * HID)

using FragA = wmma::fragment<wmma::matrix_a, 16, 16, 16, __nv_bfloat16, wmma::row_major>;
using FragB = wmma::fragment<wmma::matrix_b, 16, 16, 16, __nv_bfloat16, wmma::row_major>;
using FragC = wmma::fragment<wmma::accumulator, 16, 16, 16, float>;

// ---------------- helpers ----------------
static __device__ __forceinline__ uint32_t smem_u32(const void* p) {
    uint32_t a; asm("{ .reg .u64 t; cvta.to.shared.u64 t, %1; cvt.u32.u64 %0, t; }"
                    : "=r"(a) : "l"(p)); return a;
}
static __device__ __forceinline__ void cp16(uint32_t dst, const void* src) {
    asm volatile("cp.async.ca.shared.global [%0], [%1], 16;" :: "r"(dst), "l"(src));
}
#define CP_COMMIT() asm volatile("cp.async.commit_group;" ::: "memory")
#define CP_WAIT1()  asm volatile("cp.async.wait_group 1;" ::: "memory")
#define CP_WAIT0()  asm volatile("cp.async.wait_group 0;" ::: "memory")

static __device__ __forceinline__ ull pack2(float lo, float hi) {
    ull r; asm("mov.b64 %0,{%1,%2};" : "=l"(r) : "f"(lo), "f"(hi)); return r;
}
static __device__ __forceinline__ float2 unpack2(ull v) {
    float2 f; asm("mov.b64 {%0,%1},%2;" : "=f"(f.x), "=f"(f.y) : "l"(v)); return f;
}
static __device__ __forceinline__ ull ffma2(ull a, ull b, ull c) {
    ull d; asm("fma.rn.f32x2 %0,%1,%2,%3;" : "=l"(d) : "l"(a), "l"(b), "l"(c)); return d;
}

// ---------------- global scratch ----------------
__device__ __align__(16) __nv_bfloat16 g_B1h[32 * HID],  g_B1l[32 * HID];    // L1 (k pad 31->32)
__device__ __align__(16) __nv_bfloat16 g_B2h[HID * HID], g_B2l[HID * HID];   // L2
__device__ __align__(16) __nv_bfloat16 g_B3h[HID * HID], g_B3l[HID * HID];   // L3
__device__ ull g_oW1p[(HID/2)*HID], g_oW2p[(HID/2)*HID], g_Wqp[(HID/2)*HID];

// ONE fused prep kernel (grid 256 x block 256)
__global__ void prep_all(const float* __restrict__ pW1, const float* __restrict__ pW2,
                         const float* __restrict__ pW3, const float* __restrict__ oW1,
                         const float* __restrict__ oW2, const float* __restrict__ Wq)
{
    const int b = blockIdx.x, t = threadIdx.x;
    {
        const float w2 = pW2[b * HID + t];
        const __nv_bfloat16 h2 = __float2bfloat16_rn(w2);
        g_B2h[b * HID + t] = h2;
        g_B2l[b * HID + t] = __float2bfloat16_rn(w2 - __bfloat162float(h2));
        const float w3 = pW3[b * HID + t];
        const __nv_bfloat16 h3 = __float2bfloat16_rn(w3);
        g_B3h[b * HID + t] = h3;
        g_B3l[b * HID + t] = __float2bfloat16_rn(w3 - __bfloat162float(h3));
    }
    if (b < 32) {
        const float w = (b < FEAT) ? pW1[b * HID + t] : 0.0f;
        const __nv_bfloat16 h = __float2bfloat16_rn(w);
        g_B1h[b * HID + t] = h;
        g_B1l[b * HID + t] = __float2bfloat16_rn(w - __bfloat162float(h));
    }
    if (b < 128) {
        g_oW1p[b * HID + t] = pack2(oW1[(2*b) * HID + t], oW1[(2*b+1) * HID + t]);
        g_oW2p[b * HID + t] = pack2(oW2[(2*b) * HID + t], oW2[(2*b+1) * HID + t]);
        g_Wqp [b * HID + t] = pack2(Wq [(2*b) * HID + t], Wq [(2*b+1) * HID + t]);
    }
}

// ---------------- SMEM (~108 KB -> 2 CTAs/SM) ----------------
struct Buf { __nv_bfloat16 h[CHROWS * BP]; __nv_bfloat16 l[CHROWS * BP]; };

struct Smem {
    union {
        struct { __nv_bfloat16 hi[MROWS * AP]; __nv_bfloat16 lo[MROWS * AP]; } act;
        float rawP[MROWS * RP];
    } u;
    Buf bufs[2];
    union {                          // phase-disjoint scratch
        float stg[8][256];           // epilogue staging (per warp 16x16)
        struct { float v0[HID]; float v1[HID]; } sa;          // stage A
        struct { float logit[NHEAD * NOBJ]; float wgt[NHEAD * NOBJ];
                 float Svec[HID]; float Th[NHEAD]; float Wsum[NHEAD]; } at;
    } w;
    float qt[HID];
    float qv[HID];                   // q vector (persists into qt/qb calc)
    float qb[NHEAD], pq[NHEAD];
    float maskv[MROWS];
};

// async-copy one 16x256 hi/lo chunk (4 cp.async per thread @256thr)
static __device__ __forceinline__ void cp_chunk(Buf* buf, const __nv_bfloat16* srcH,
                                                const __nv_bfloat16* srcL, int tid) {
    const char* sh = reinterpret_cast<const char*>(srcH);
    const char* sl = reinterpret_cast<const char*>(srcL);
    const uint32_t dh = smem_u32(buf->h), dl = smem_u32(buf->l);
#pragma unroll
    for (int i = 0; i < 2; i++) {
        const int idx = tid + i * NTHR;       // 0..511 (16 rows x 32 int4)
        const int r = idx >> 5, c = idx & 31;
        cp16(dh + (uint32_t)(r * BP * 2 + c * 16), sh + (size_t)idx * 16);
        cp16(dl + (uint32_t)(r * BP * 2 + c * 16), sl + (size_t)idx * 16);
    }
}

// MMA over one 16-K chunk: warp tile 32x64 (c[2][4]); 3-term bf16 split
static __device__ __forceinline__ void mma_chunk(FragC (&c)[2][4],
    const __nv_bfloat16* actH, const __nv_bfloat16* actL,
    const Buf* buf, int kbase, int mbase, int nbase)
{
    FragA ah0, ah1, al0, al1;
    wmma::load_matrix_sync(ah0, actH + (size_t)mbase * AP + kbase, AP);
    wmma::load_matrix_sync(ah1, actH + (size_t)(mbase + 16) * AP + kbase, AP);
    wmma::load_matrix_sync(al0, actL + (size_t)mbase * AP + kbase, AP);
    wmma::load_matrix_sync(al1, actL + (size_t)(mbase + 16) * AP + kbase, AP);
#pragma unroll
    for (int nt = 0; nt < 4; nt++) {
        FragB bh, bl;
        wmma::load_matrix_sync(bh, buf->h + nbase + nt * 16, BP);
        wmma::load_matrix_sync(bl, buf->l + nbase + nt * 16, BP);
        wmma::mma_sync(c[0][nt], ah0, bh, c[0][nt]);
        wmma::mma_sync(c[1][nt], ah1, bh, c[1][nt]);
        wmma::mma_sync(c[0][nt], al0, bh, c[0][nt]);
        wmma::mma_sync(c[1][nt], al1, bh, c[1][nt]);
        wmma::mma_sync(c[0][nt], ah0, bl, c[0][nt]);
        wmma::mma_sync(c[1][nt], ah1, bl, c[1][nt]);
    }
}

// 16-chunk double-buffered layer; chunks 0,1 already in flight, chunk ch in bufs[ch&1]
static __device__ __forceinline__ void layer_pipe(FragC (&c)[2][4],
    const __nv_bfloat16* actH, const __nv_bfloat16* actL, Buf* bufs,
    const __nv_bfloat16* srcH, const __nv_bfloat16* srcL,
    int mbase, int nbase, int tid)
{
    for (int ch = 0; ch < 16; ch++) {
        if (ch < 15) CP_WAIT1(); else CP_WAIT0();
        __syncthreads();
        mma_chunk(c, actH, actL, &bufs[ch & 1], ch * CHROWS, mbase, nbase);
        __syncthreads();
        if (ch + 2 < 16) {
            cp_chunk(&bufs[ch & 1], srcH + (ch + 2) * CHELE, srcL + (ch + 2) * CHELE, tid);
            CP_COMMIT();
        }
    }
}

// epilogue: x = relu(C + bias); split to bf16 hi/lo act buffers (packed STS.32)
static __device__ __forceinline__ void epi_act(FragC (&c)[2][4], float* stg,
    const float* __restrict__ bias, __nv_bfloat16* actH, __nv_bfloat16* actL,
    int mbase, int nbase, int lane)
{
#pragma unroll
    for (int mi = 0; mi < 2; mi++)
#pragma unroll
        for (int ni = 0; ni < 4; ni++) {
            wmma::store_matrix_sync(stg, c[mi][ni], 16, wmma::mem_row_major);
            __syncwarp();
#pragma unroll
            for (int e = lane; e < 128; e += 32) {
                const int r = e >> 3, c2 = (e & 7) * 2;
                const int j = nbase + ni * 16 + c2;
                const int m = mbase + mi * 16 + r;
                const float x0 = fmaxf(stg[r * 16 + c2]     + __ldg(bias + j),     0.0f);
                const float x1 = fmaxf(stg[r * 16 + c2 + 1] + __ldg(bias + j + 1), 0.0f);
                const __nv_bfloat16 h0 = __float2bfloat16_rn(x0), h1 = __float2bfloat16_rn(x1);
                const __nv_bfloat16 l0 = __float2bfloat16_rn(x0 - __bfloat162float(h0));
                const __nv_bfloat16 l1 = __float2bfloat16_rn(x1 - __bfloat162float(h1));
                *reinterpret_cast<uint32_t*>(&actH[(size_t)m * AP + j]) =
                    (uint32_t)__bfloat16_as_ushort(h0) | ((uint32_t)__bfloat16_as_ushort(h1) << 16);
                *reinterpret_cast<uint32_t*>(&actL[(size_t)m * AP + j]) =
                    (uint32_t)__bfloat16_as_ushort(l0) | ((uint32_t)__bfloat16_as_ushort(l1) << 16);
            }
            __syncwarp();
        }
}

// 256->256 GEMV, thread j = output column
static __device__ __forceinline__ void gemv1(const ull* __restrict__ Wp,
                                             const float* __restrict__ bias,
                                             const float* x, float* y, int j, bool relu) {
    ull a = pack2(bias[j], 0.0f);
    const ull* wp = Wp + j;
#pragma unroll 4
    for (int k2 = 0; k2 < HID / 2; k2 += 2) {
        const ulonglong2 u = *reinterpret_cast<const ulonglong2*>(x + 2 * k2);
        a = ffma2(u.x, wp[k2 * HID], a);
        a = ffma2(u.y, wp[(k2 + 1) * HID], a);
    }
    const float2 f = unpack2(a);
    float r = f.x + f.y;
    if (relu) r = fmaxf(r, 0.0f);
    y[j] = r;
}

__global__ void __launch_bounds__(NTHR, 2) pinet_wmma_kernel(
    const float* __restrict__ obs,
    const float* __restrict__ ob1, const float* __restrict__ ob2,
    const float* __restrict__ pb1, const float* __restrict__ pb2,
    const float* __restrict__ pb3, const float* __restrict__ bq,
    const float* __restrict__ Wk,  const float* __restrict__ bk,
    const float* __restrict__ Wv,  const float* __restrict__ bv,
    float* __restrict__ out)
{
    extern __shared__ char smraw[];
    Smem* s = reinterpret_cast<Smem*>(smraw);
    const int tid = threadIdx.x, wid = tid >> 5, lane = tid & 31;
    __nv_bfloat16* actH = s->u.act.hi;
    __nv_bfloat16* actL = s->u.act.lo;

    // ---- prefetch L1 weight chunks into both bufs ----
    cp_chunk(&s->bufs[0], g_B1h,         g_B1l,         tid); CP_COMMIT();
    cp_chunk(&s->bufs[1], g_B1h + CHELE, g_B1l + CHELE, tid); CP_COMMIT();

    const float* row = obs + (size_t)blockIdx.x * OBS_W;

    // ---- load obs: feats -> act bf16 hi/lo (cols 0..31), mask, others ----
    {
#pragma unroll
        for (int i2 = 0; i2 < 2; i2++) {
            const int i = tid + i2 * NTHR;           // 0..511 float4s of feats
            const float4 a = reinterpret_cast<const float4*>(row)[i];
            const int m0 = i >> 3, d4 = (i & 7) * 4;
            const float va[4] = {a.x, a.y, a.z, a.w};
#pragma unroll
            for (int e = 0; e < 4; e++) {
                const float x = va[e];
                const __nv_bfloat16 h = __float2bfloat16_rn(x);
                const __nv_bfloat16 l = __float2bfloat16_rn(x - __bfloat162float(h));
                actH[(size_t)m0 * AP + d4 + e] = h;
                actL[(size_t)m0 * AP + d4 + e] = l;
            }
            if ((i & 7) == 7) s->maskv[m0] = a.w;
        }
        s->w.sa.v0[tid] = row[OTH_OFF + tid];
    }
    __syncthreads();

    // ---- stage A (overlaps in-flight cp.async) ----
    gemv1(g_oW1p, ob1, s->w.sa.v0, s->w.sa.v1, tid, true);
    __syncthreads();
    {
        // others_e into registers then back to v0 (avoid aliasing hazards via sync)
        float oe;
        {
            ull a = pack2(ob2[tid], 0.0f);
            const ull* wp = g_oW2p + tid;
#pragma unroll 4
            for (int k2 = 0; k2 < HID / 2; k2 += 2) {
                const ulonglong2 u = *reinterpret_cast<const ulonglong2*>(s->w.sa.v1 + 2 * k2);
                a = ffma2(u.x, wp[k2 * HID], a);
                a = ffma2(u.y, wp[(k2 + 1) * HID], a);
            }
            const float2 f = unpack2(a);
            oe = f.x + f.y;
        }
        out[(size_t)blockIdx.x * 512 + tid] = oe;
        __syncthreads();
        s->w.sa.v0[tid] = oe;
    }
    __syncthreads();
    gemv1(g_Wqp, bq, s->w.sa.v0, s->qv, tid, false);    // q (persistent buffer)
    __syncthreads();
    {   // qt[h*64+d] = Wk[h,d,:].q[h,:] ; qb[h] = q.bk
        const int h = tid >> 6, d = tid & 63;
        const float4* wk4 = reinterpret_cast<const float4*>(Wk + h * (HDIM*HDIM) + d * HDIM);
        const float4* q4  = reinterpret_cast<const float4*>(&s->qv[h * HDIM]);
        float t = 0.0f;
#pragma unroll
        for (int e = 0; e < HDIM / 4; e++) {
            const float4 w = wk4[e], qv = q4[e];
            t += w.x*qv.x + w.y*qv.y + w.z*qv.z + w.w*qv.w;
        }
        s->qt[tid] = t;
        if (tid < NHEAD) {
            float sb = 0.0f;
            for (int e = 0; e < HDIM; e++) sb += s->qv[tid * HDIM + e] * bk[tid * HDIM + e];
            s->qb[tid] = sb;
        }
    }
    __syncthreads();
    if (tid < NHEAD) {   // pq[h] = pb3[h-slice] . qt[h-slice]
        float t = 0.0f;
        for (int d = 0; d < HDIM; d++) t += pb3[tid * HDIM + d] * s->qt[tid * HDIM + d];
        s->pq[tid] = t;
    }

    // ---- object MLP on warp MMA; warp tile 32x64; 2 CTAs/SM overlap ----
    const int mbase = (wid >> 2) * 32;
    const int nbase = (wid & 3) * 64;
    FragC c[2][4];

    // L1: 2 chunks (K=32)
#pragma unroll
    for (int mi = 0; mi < 2; mi++)
#pragma unroll
        for (int ni = 0; ni < 4; ni++) wmma::fill_fragment(c[mi][ni], 0.0f);
    CP_WAIT1();
    __syncthreads();
    mma_chunk(c, actH, actL, &s->bufs[0], 0, mbase, nbase);
    __syncthreads();
    cp_chunk(&s->bufs[0], g_B2h, g_B2l, tid); CP_COMMIT();          // L2 c0
    CP_WAIT1();
    __syncthreads();
    mma_chunk(c, actH, actL, &s->bufs[1], CHROWS, mbase, nbase);
    __syncthreads();
    cp_chunk(&s->bufs[1], g_B2h + CHELE, g_B2l + CHELE, tid); CP_COMMIT();  // L2 c1
    epi_act(c, s->w.stg[wid], pb1, actH, actL, mbase, nbase, lane);
    __syncthreads();

    // L2: 16 chunks
#pragma unroll
    for (int mi = 0; mi < 2; mi++)
#pragma unroll
        for (int ni = 0; ni < 4; ni++) wmma::fill_fragment(c[mi][ni], 0.0f);
    layer_pipe(c, actH, actL, s->bufs, g_B2h, g_B2l, mbase, nbase, tid);
    cp_chunk(&s->bufs[0], g_B3h, g_B3l, tid); CP_COMMIT();          // L3 c0
    cp_chunk(&s->bufs[1], g_B3h + CHELE, g_B3l + CHELE, tid); CP_COMMIT();  // L3 c1
    epi_act(c, s->w.stg[wid], pb2, actH, actL, mbase, nbase, lane);
    __syncthreads();

    // L3: 16 chunks -> rawP (pb3 folded into attention)
#pragma unroll
    for (int mi = 0; mi < 2; mi++)
#pragma unroll
        for (int ni = 0; ni < 4; ni++) wmma::fill_fragment(c[mi][ni], 0.0f);
    layer_pipe(c, actH, actL, s->bufs, g_B3h, g_B3l, mbase, nbase, tid);
#pragma unroll
    for (int mi = 0; mi < 2; mi++)
#pragma unroll
        for (int ni = 0; ni < 4; ni++)
            wmma::store_matrix_sync(&s->u.rawP[(size_t)(mbase + mi * 16) * RP + nbase + ni * 16],
                                    c[mi][ni], RP, wmma::mem_row_major);
    __syncthreads();

    // ---- attention (q-len 1; K/V folded; pb3 folded via pq/Wsum) ----
    {
        const int h = tid >> 6, n = tid & 63;
        const float* rp = s->u.rawP + (size_t)n * RP + h * HDIM;
        const float* qt = s->qt + h * HDIM;
        float dot = 0.0f;
#pragma unroll
        for (int d = 0; d < HDIM; d += 4) {
            const float4 a4 = *reinterpret_cast<const float4*>(&rp[d]);
            const float4 b4 = *reinterpret_cast<const float4*>(&qt[d]);
            dot += a4.x*b4.x + a4.y*b4.y + a4.z*b4.z + a4.w*b4.w;
        }
        const float m = s->maskv[n];
        float lg = (m * (dot + s->pq[h]) + s->qb[h]) * 0.0625f;
        if (m == 0.0f) lg = -1000000000.0f;
        s->w.at.logit[h * NOBJ + n] = lg;
    }
    __syncthreads();
    if (wid < NHEAD) {   // softmax: warp = head
        const int hh = wid;
        const float x0 = s->w.at.logit[hh * NOBJ + lane];
        const float x1 = s->w.at.logit[hh * NOBJ + 32 + lane];
        float mx = fmaxf(x0, x1);
#pragma unroll
        for (int o = 16; o > 0; o >>= 1) mx = fmaxf(mx, __shfl_xor_sync(0xffffffffu, mx, o));
        const float e0 = expf(x0 - mx), e1 = expf(x1 - mx);
        float sum = e0 + e1;
#pragma unroll
        for (int o = 16; o > 0; o >>= 1) sum += __shfl_xor_sync(0xffffffffu, sum, o);
        const float inv = 1.0f / sum;
        const float a0 = e0 * inv, a1 = e1 * inv;
        const float m0 = s->maskv[lane], m1 = s->maskv[32 + lane];
        const float w0 = a0 * m0 * m0, w1 = a1 * m1 * m1;
        s->w.at.wgt[hh * NOBJ + lane]      = w0;
        s->w.at.wgt[hh * NOBJ + 32 + lane] = w1;
        float tt = a0 * m0 + a1 * m1;
        float ws = w0 + w1;
#pragma unroll
        for (int o = 16; o > 0; o >>= 1) {
            tt += __shfl_xor_sync(0xffffffffu, tt, o);
            ws += __shfl_xor_sync(0xffffffffu, ws, o);
        }
        if (lane == 0) { s->w.at.Th[hh] = tt; s->w.at.Wsum[hh] = ws; }
    }
    __syncthreads();
    {   // Svec = sum_n wgt*rawP + Wsum*pb3
        const int h = tid >> 6, d = tid & 63;
        const float* wp = s->w.at.wgt + h * NOBJ;
        float acc = 0.0f;
#pragma unroll 4
        for (int nn = 0; nn < NOBJ; nn++)
            acc = fmaf(wp[nn], s->u.rawP[(size_t)nn * RP + h * HDIM + d], acc);
        s->w.at.Svec[tid] = acc + s->w.at.Wsum[h] * pb3[h * HDIM + d];
    }
    __syncthreads();
    {   // out_emb = Svec @ Wv + Th*bv
        const int h = tid >> 6, e = tid & 63;
        float o = s->w.at.Th[h] * bv[h * HDIM + e];
        const float* sv = s->w.at.Svec + h * HDIM;
        const float* wv = Wv + h * (HDIM * HDIM) + e;
#pragma unroll 4
        for (int d = 0; d < HDIM; d++)
            o = fmaf(sv[d], wv[d * HDIM], o);
        out[(size_t)blockIdx.x * 512 + 256 + h * HDIM + e] = o;
    }
}

extern "C" void kernel_launch(void* const* d_in, const int* in_sizes, int n_in,
                              void* d_out, int out_size)
{
    const float* obs = (const float*)d_in[0];
    const float* oW1 = (const float*)d_in[1];
    const float* ob1 = (const float*)d_in[2];
    const float* oW2 = (const float*)d_in[3];
    const float* ob2 = (const float*)d_in[4];
    const float* pW1 = (const float*)d_in[5];
    const float* pb1 = (const float*)d_in[6];
    const float* pW2 = (const float*)d_in[7];
    const float* pb2 = (const float*)d_in[8];
    const float* pW3 = (const float*)d_in[9];
    const float* pb3 = (const float*)d_in[10];
    const float* Wq  = (const float*)d_in[11];
    const float* bq  = (const float*)d_in[12];
    const float* Wk  = (const float*)d_in[13];
    const float* bk  = (const float*)d_in[14];
    const float* Wv  = (const float*)d_in[15];
    const float* bv  = (const float*)d_in[16];
    float* out = (float*)d_out;

    prep_all<<<256, 256>>>(pW1, pW2, pW3, oW1, oW2, Wq);

    const int smem = (int)sizeof(Smem);
    cudaFuncSetAttribute(pinet_wmma_kernel, cudaFuncAttributeMaxDynamicSharedMemorySize, smem);
    pinet_wmma_kernel<<<GRID_N, NTHR, smem>>>(obs, ob1, ob2, pb1, pb2, pb3,
                                              bq, Wk, bk, Wv, bv, out);
}

// round 13
// speedup vs baseline: 5.4928x; 1.5071x over previous
#include <cuda_runtime.h>
#include <cuda_fp16.h>
#include <mma.h>
#include <math.h>
#include <stdint.h>

using namespace nvcuda;
typedef unsigned long long ull;

#define NOBJ    64
#define FEAT    31
#define HID     256
#define OBS_W   2304
#define OTH_OFF 2048
#define NHEAD   4
#define HDIM    64
#define MROWS   64           // 1 sample x 64 objects per CTA
#define AP      264          // act pitch (half)
#define BP      264          // B-tile pitch (half)
#define RP      264          // rawP pitch (floats)
#define GRID_N  4096
#define NTHR    256
#define CHROWS  32           // K-rows per weight chunk
#define CHELE   (CHROWS * HID)

using FragA = wmma::fragment<wmma::matrix_a, 16, 16, 16, __half, wmma::row_major>;
using FragB = wmma::fragment<wmma::matrix_b, 16, 16, 16, __half, wmma::row_major>;
using FragC = wmma::fragment<wmma::accumulator, 16, 16, 16, float>;

// ---------------- helpers ----------------
static __device__ __forceinline__ uint32_t smem_u32(const void* p) {
    uint32_t a; asm("{ .reg .u64 t; cvta.to.shared.u64 t, %1; cvt.u32.u64 %0, t; }"
                    : "=r"(a) : "l"(p)); return a;
}
static __device__ __forceinline__ void cp16(uint32_t dst, const void* src) {
    asm volatile("cp.async.ca.shared.global [%0], [%1], 16;" :: "r"(dst), "l"(src));
}
#define CP_COMMIT() asm volatile("cp.async.commit_group;" ::: "memory")
#define CP_WAIT1()  asm volatile("cp.async.wait_group 1;" ::: "memory")
#define CP_WAIT0()  asm volatile("cp.async.wait_group 0;" ::: "memory")

static __device__ __forceinline__ ull pack2(float lo, float hi) {
    ull r; asm("mov.b64 %0,{%1,%2};" : "=l"(r) : "f"(lo), "f"(hi)); return r;
}
static __device__ __forceinline__ float2 unpack2(ull v) {
    float2 f; asm("mov.b64 {%0,%1},%2;" : "=f"(f.x), "=f"(f.y) : "l"(v)); return f;
}
static __device__ __forceinline__ ull ffma2(ull a, ull b, ull c) {
    ull d; asm("fma.rn.f32x2 %0,%1,%2,%3;" : "=l"(d) : "l"(a), "l"(b), "l"(c)); return d;
}
static __device__ __forceinline__ uint32_t packh2(float x0, float x1) {
    const __half h0 = __float2half_rn(x0), h1 = __float2half_rn(x1);
    return (uint32_t)__half_as_ushort(h0) | ((uint32_t)__half_as_ushort(h1) << 16);
}

// ---------------- global scratch (fp16 single weights) ----------------
__device__ __align__(16) __half g_B1[32 * HID];     // L1 (k pad 31->32)
__device__ __align__(16) __half g_B2[HID * HID];    // L2
__device__ __align__(16) __half g_B3[HID * HID];    // L3
__device__ ull g_oW1p[(HID/2)*HID], g_oW2p[(HID/2)*HID], g_Wqp[(HID/2)*HID];

// ONE fused prep kernel (grid 256 x block 256)
__global__ void prep_all(const float* __restrict__ pW1, const float* __restrict__ pW2,
                         const float* __restrict__ pW3, const float* __restrict__ oW1,
                         const float* __restrict__ oW2, const float* __restrict__ Wq)
{
    const int b = blockIdx.x, t = threadIdx.x;
    g_B2[b * HID + t] = __float2half_rn(pW2[b * HID + t]);
    g_B3[b * HID + t] = __float2half_rn(pW3[b * HID + t]);
    if (b < 32)
        g_B1[b * HID + t] = __float2half_rn((b < FEAT) ? pW1[b * HID + t] : 0.0f);
    if (b < 128) {
        g_oW1p[b * HID + t] = pack2(oW1[(2*b) * HID + t], oW1[(2*b+1) * HID + t]);
        g_oW2p[b * HID + t] = pack2(oW2[(2*b) * HID + t], oW2[(2*b+1) * HID + t]);
        g_Wqp [b * HID + t] = pack2(Wq [(2*b) * HID + t], Wq [(2*b+1) * HID + t]);
    }
}

// ---------------- SMEM (~109 KB -> 2 CTAs/SM) ----------------
struct Buf { __half w[CHROWS * BP]; };

struct Smem {
    union {
        struct { __half hi[MROWS * AP]; __half lo[MROWS * AP]; } act;
        float rawP[MROWS * RP];
    } u;
    Buf bufs[2];
    union {                          // phase-disjoint scratch
        float stg[8][256];           // epilogue staging (per warp 16x16)
        struct { float v0[HID]; float v1[HID]; } sa;          // stage A
        struct { float logit[NHEAD * NOBJ]; float wgt[NHEAD * NOBJ];
                 float Svec[HID]; float Th[NHEAD]; float Wsum[NHEAD]; } at;
    } w;
    float qt[HID];
    float qv[HID];
    float qb[NHEAD], pq[NHEAD];
    float maskv[MROWS];
};

// async-copy one 32x256 fp16 chunk (4 cp.async per thread @256thr)
static __device__ __forceinline__ void cp_chunk(Buf* buf, const __half* src, int tid) {
    const char* sp = reinterpret_cast<const char*>(src);
    const uint32_t dp = smem_u32(buf->w);
#pragma unroll
    for (int i = 0; i < 4; i++) {
        const int idx = tid + i * NTHR;       // 0..1023 (32 rows x 32 int4)
        const int r = idx >> 5, c = idx & 31;
        cp16(dp + (uint32_t)(r * BP * 2 + c * 16), sp + (size_t)idx * 16);
    }
}

// MMA over one 32-K chunk: warp tile 32x64 (c[2][4]); 2-term fp16 (A split, B RN)
static __device__ __forceinline__ void mma_chunk(FragC (&c)[2][4],
    const __half* actH, const __half* actL,
    const Buf* buf, int kbase, int mbase, int nbase)
{
#pragma unroll
    for (int ks = 0; ks < 2; ks++) {
        FragA ah0, ah1, al0, al1;
        wmma::load_matrix_sync(ah0, actH + (size_t)mbase * AP + kbase + ks * 16, AP);
        wmma::load_matrix_sync(ah1, actH + (size_t)(mbase + 16) * AP + kbase + ks * 16, AP);
        wmma::load_matrix_sync(al0, actL + (size_t)mbase * AP + kbase + ks * 16, AP);
        wmma::load_matrix_sync(al1, actL + (size_t)(mbase + 16) * AP + kbase + ks * 16, AP);
#pragma unroll
        for (int nt = 0; nt < 4; nt++) {
            FragB b;
            wmma::load_matrix_sync(b, buf->w + (size_t)(ks * 16) * BP + nbase + nt * 16, BP);
            wmma::mma_sync(c[0][nt], ah0, b, c[0][nt]);
            wmma::mma_sync(c[1][nt], ah1, b, c[1][nt]);
            wmma::mma_sync(c[0][nt], al0, b, c[0][nt]);
            wmma::mma_sync(c[1][nt], al1, b, c[1][nt]);
        }
    }
}

// 8-chunk double-buffered layer; chunks 0,1 already in flight, chunk ch in bufs[(ch+PH)&1]
template<int PH>
static __device__ __forceinline__ void layer_pipe(FragC (&c)[2][4],
    const __half* actH, const __half* actL, Buf* bufs,
    const __half* src, int mbase, int nbase, int tid)
{
    for (int ch = 0; ch < 8; ch++) {
        if (ch < 7) CP_WAIT1(); else CP_WAIT0();
        __syncthreads();
        mma_chunk(c, actH, actL, &bufs[(ch + PH) & 1], ch * CHROWS, mbase, nbase);
        __syncthreads();
        if (ch + 2 < 8) {
            cp_chunk(&bufs[(ch + PH) & 1], src + (size_t)(ch + 2) * CHELE, tid);
            CP_COMMIT();
        }
    }
}

// epilogue: x = relu(C + bias); split to fp16 hi/lo act buffers (packed STS.32)
static __device__ __forceinline__ void epi_act(FragC (&c)[2][4], float* stg,
    const float* __restrict__ bias, __half* actH, __half* actL,
    int mbase, int nbase, int lane)
{
#pragma unroll
    for (int mi = 0; mi < 2; mi++)
#pragma unroll
        for (int ni = 0; ni < 4; ni++) {
            wmma::store_matrix_sync(stg, c[mi][ni], 16, wmma::mem_row_major);
            __syncwarp();
#pragma unroll
            for (int e = lane; e < 128; e += 32) {
                const int r = e >> 3, c2 = (e & 7) * 2;
                const int j = nbase + ni * 16 + c2;
                const int m = mbase + mi * 16 + r;
                const float x0 = fmaxf(stg[r * 16 + c2]     + __ldg(bias + j),     0.0f);
                const float x1 = fmaxf(stg[r * 16 + c2 + 1] + __ldg(bias + j + 1), 0.0f);
                const __half h0 = __float2half_rn(x0), h1 = __float2half_rn(x1);
                const float l0f = x0 - __half2float(h0);
                const float l1f = x1 - __half2float(h1);
                *reinterpret_cast<uint32_t*>(&actH[(size_t)m * AP + j]) =
                    (uint32_t)__half_as_ushort(h0) | ((uint32_t)__half_as_ushort(h1) << 16);
                *reinterpret_cast<uint32_t*>(&actL[(size_t)m * AP + j]) = packh2(l0f, l1f);
            }
            __syncwarp();
        }
}

// 256->256 GEMV, thread j = output column
static __device__ __forceinline__ void gemv1(const ull* __restrict__ Wp,
                                             const float* __restrict__ bias,
                                             const float* x, float* y, int j, bool relu) {
    ull a = pack2(bias[j], 0.0f);
    const ull* wp = Wp + j;
#pragma unroll 4
    for (int k2 = 0; k2 < HID / 2; k2 += 2) {
        const ulonglong2 u = *reinterpret_cast<const ulonglong2*>(x + 2 * k2);
        a = ffma2(u.x, wp[k2 * HID], a);
        a = ffma2(u.y, wp[(k2 + 1) * HID], a);
    }
    const float2 f = unpack2(a);
    float r = f.x + f.y;
    if (relu) r = fmaxf(r, 0.0f);
    y[j] = r;
}

__global__ void __launch_bounds__(NTHR, 2) pinet_wmma_kernel(
    const float* __restrict__ obs,
    const float* __restrict__ ob1, const float* __restrict__ ob2,
    const float* __restrict__ pb1, const float* __restrict__ pb2,
    const float* __restrict__ pb3, const float* __restrict__ bq,
    const float* __restrict__ Wk,  const float* __restrict__ bk,
    const float* __restrict__ Wv,  const float* __restrict__ bv,
    float* __restrict__ out)
{
    extern __shared__ char smraw[];
    Smem* s = reinterpret_cast<Smem*>(smraw);
    const int tid = threadIdx.x, wid = tid >> 5, lane = tid & 31;
    __half* actH = s->u.act.hi;
    __half* actL = s->u.act.lo;

    // ---- prefetch L1 weights (buf0) and L2 chunk0 (buf1) ----
    cp_chunk(&s->bufs[0], g_B1, tid); CP_COMMIT();
    cp_chunk(&s->bufs[1], g_B2, tid); CP_COMMIT();

    const float* row = obs + (size_t)blockIdx.x * OBS_W;

    // ---- load obs: feats -> act fp16 hi/lo (cols 0..31), mask, others ----
    {
#pragma unroll
        for (int i2 = 0; i2 < 2; i2++) {
            const int i = tid + i2 * NTHR;           // 0..511 float4s of feats
            const float4 a = reinterpret_cast<const float4*>(row)[i];
            const int m0 = i >> 3, d4 = (i & 7) * 4;
            const float va[4] = {a.x, a.y, a.z, a.w};
#pragma unroll
            for (int e = 0; e < 4; e += 2) {
                const float x0 = va[e], x1 = va[e + 1];
                const __half h0 = __float2half_rn(x0), h1 = __float2half_rn(x1);
                *reinterpret_cast<uint32_t*>(&actH[(size_t)m0 * AP + d4 + e]) =
                    (uint32_t)__half_as_ushort(h0) | ((uint32_t)__half_as_ushort(h1) << 16);
                *reinterpret_cast<uint32_t*>(&actL[(size_t)m0 * AP + d4 + e]) =
                    packh2(x0 - __half2float(h0), x1 - __half2float(h1));
            }
            if ((i & 7) == 7) s->maskv[m0] = a.w;
        }
        s->w.sa.v0[tid] = row[OTH_OFF + tid];
    }
    __syncthreads();

    // ---- stage A (overlaps in-flight cp.async) ----
    gemv1(g_oW1p, ob1, s->w.sa.v0, s->w.sa.v1, tid, true);
    __syncthreads();
    {
        float oe;
        {
            ull a = pack2(ob2[tid], 0.0f);
            const ull* wp = g_oW2p + tid;
#pragma unroll 4
            for (int k2 = 0; k2 < HID / 2; k2 += 2) {
                const ulonglong2 u = *reinterpret_cast<const ulonglong2*>(s->w.sa.v1 + 2 * k2);
                a = ffma2(u.x, wp[k2 * HID], a);
                a = ffma2(u.y, wp[(k2 + 1) * HID], a);
            }
            const float2 f = unpack2(a);
            oe = f.x + f.y;
        }
        out[(size_t)blockIdx.x * 512 + tid] = oe;
        __syncthreads();
        s->w.sa.v0[tid] = oe;
    }
    __syncthreads();
    gemv1(g_Wqp, bq, s->w.sa.v0, s->qv, tid, false);    // q
    __syncthreads();
    {   // qt[h*64+d] = Wk[h,d,:].q[h,:] ; qb[h] = q.bk
        const int h = tid >> 6, d = tid & 63;
        const float4* wk4 = reinterpret_cast<const float4*>(Wk + h * (HDIM*HDIM) + d * HDIM);
        const float4* q4  = reinterpret_cast<const float4*>(&s->qv[h * HDIM]);
        float t = 0.0f;
#pragma unroll
        for (int e = 0; e < HDIM / 4; e++) {
            const float4 w = wk4[e], qv = q4[e];
            t += w.x*qv.x + w.y*qv.y + w.z*qv.z + w.w*qv.w;
        }
        s->qt[tid] = t;
        if (tid < NHEAD) {
            float sb = 0.0f;
            for (int e = 0; e < HDIM; e++) sb += s->qv[tid * HDIM + e] * bk[tid * HDIM + e];
            s->qb[tid] = sb;
        }
    }
    __syncthreads();
    if (tid < NHEAD) {   // pq[h] = pb3[h-slice] . qt[h-slice]
        float t = 0.0f;
        for (int d = 0; d < HDIM; d++) t += pb3[tid * HDIM + d] * s->qt[tid * HDIM + d];
        s->pq[tid] = t;
    }

    // ---- object MLP on warp MMA; warp tile 32x64; 2 CTAs/SM ----
    const int mbase = (wid >> 2) * 32;
    const int nbase = (wid & 3) * 64;
    FragC c[2][4];

    // L1: one 32-K chunk (weights in buf0)
#pragma unroll
    for (int mi = 0; mi < 2; mi++)
#pragma unroll
        for (int ni = 0; ni < 4; ni++) wmma::fill_fragment(c[mi][ni], 0.0f);
    CP_WAIT1();                 // L1 done (L2c0 may still be in flight)
    __syncthreads();
    mma_chunk(c, actH, actL, &s->bufs[0], 0, mbase, nbase);
    __syncthreads();
    cp_chunk(&s->bufs[0], g_B2 + CHELE, tid); CP_COMMIT();   // L2 chunk1 -> buf0
    epi_act(c, s->w.stg[wid], pb1, actH, actL, mbase, nbase, lane);
    __syncthreads();

    // L2: 8 chunks, chunk ch in bufs[(ch+1)&1]
#pragma unroll
    for (int mi = 0; mi < 2; mi++)
#pragma unroll
        for (int ni = 0; ni < 4; ni++) wmma::fill_fragment(c[mi][ni], 0.0f);
    layer_pipe<1>(c, actH, actL, s->bufs, g_B2, mbase, nbase, tid);
    cp_chunk(&s->bufs[0], g_B3, tid); CP_COMMIT();           // L3 c0
    cp_chunk(&s->bufs[1], g_B3 + CHELE, tid); CP_COMMIT();   // L3 c1
    epi_act(c, s->w.stg[wid], pb2, actH, actL, mbase, nbase, lane);
    __syncthreads();

    // L3: 8 chunks, chunk ch in bufs[ch&1] -> rawP (pb3 folded into attention)
#pragma unroll
    for (int mi = 0; mi < 2; mi++)
#pragma unroll
        for (int ni = 0; ni < 4; ni++) wmma::fill_fragment(c[mi][ni], 0.0f);
    layer_pipe<0>(c, actH, actL, s->bufs, g_B3, mbase, nbase, tid);
#pragma unroll
    for (int mi = 0; mi < 2; mi++)
#pragma unroll
        for (int ni = 0; ni < 4; ni++)
            wmma::store_matrix_sync(&s->u.rawP[(size_t)(mbase + mi * 16) * RP + nbase + ni * 16],
                                    c[mi][ni], RP, wmma::mem_row_major);
    __syncthreads();

    // ---- attention (q-len 1; K/V folded; pb3 folded via pq/Wsum) ----
    {
        const int h = tid >> 6, n = tid & 63;
        const float* rp = s->u.rawP + (size_t)n * RP + h * HDIM;
        const float* qt = s->qt + h * HDIM;
        float dot = 0.0f;
#pragma unroll
        for (int d = 0; d < HDIM; d += 4) {
            const float4 a4 = *reinterpret_cast<const float4*>(&rp[d]);
            const float4 b4 = *reinterpret_cast<const float4*>(&qt[d]);
            dot += a4.x*b4.x + a4.y*b4.y + a4.z*b4.z + a4.w*b4.w;
        }
        const float m = s->maskv[n];
        float lg = (m * (dot + s->pq[h]) + s->qb[h]) * 0.0625f;
        if (m == 0.0f) lg = -1000000000.0f;
        s->w.at.logit[h * NOBJ + n] = lg;
    }
    __syncthreads();
    if (wid < NHEAD) {   // softmax: warp = head
        const int hh = wid;
        const float x0 = s->w.at.logit[hh * NOBJ + lane];
        const float x1 = s->w.at.logit[hh * NOBJ + 32 + lane];
        float mx = fmaxf(x0, x1);
#pragma unroll
        for (int o = 16; o > 0; o >>= 1) mx = fmaxf(mx, __shfl_xor_sync(0xffffffffu, mx, o));
        const float e0 = expf(x0 - mx), e1 = expf(x1 - mx);
        float sum = e0 + e1;
#pragma unroll
        for (int o = 16; o > 0; o >>= 1) sum += __shfl_xor_sync(0xffffffffu, sum, o);
        const float inv = 1.0f / sum;
        const float a0 = e0 * inv, a1 = e1 * inv;
        const float m0 = s->maskv[lane], m1 = s->maskv[32 + lane];
        const float w0 = a0 * m0 * m0, w1 = a1 * m1 * m1;
        s->w.at.wgt[hh * NOBJ + lane]      = w0;
        s->w.at.wgt[hh * NOBJ + 32 + lane] = w1;
        float tt = a0 * m0 + a1 * m1;
        float ws = w0 + w1;
#pragma unroll
        for (int o = 16; o > 0; o >>= 1) {
            tt += __shfl_xor_sync(0xffffffffu, tt, o);
            ws += __shfl_xor_sync(0xffffffffu, ws, o);
        }
        if (lane == 0) { s->w.at.Th[hh] = tt; s->w.at.Wsum[hh] = ws; }
    }
    __syncthreads();
    {   // Svec = sum_n wgt*rawP + Wsum*pb3
        const int h = tid >> 6, d = tid & 63;
        const float* wp = s->w.at.wgt + h * NOBJ;
        float acc = 0.0f;
#pragma unroll 4
        for (int nn = 0; nn < NOBJ; nn++)
            acc = fmaf(wp[nn], s->u.rawP[(size_t)nn * RP + h * HDIM + d], acc);
        s->w.at.Svec[tid] = acc + s->w.at.Wsum[h] * pb3[h * HDIM + d];
    }
    __syncthreads();
    {   // out_emb = Svec @ Wv + Th*bv
        const int h = tid >> 6, e = tid & 63;
        float o = s->w.at.Th[h] * bv[h * HDIM + e];
        const float* sv = s->w.at.Svec + h * HDIM;
        const float* wv = Wv + h * (HDIM * HDIM) + e;
#pragma unroll 4
        for (int d = 0; d < HDIM; d++)
            o = fmaf(sv[d], wv[d * HDIM], o);
        out[(size_t)blockIdx.x * 512 + 256 + h * HDIM + e] = o;
    }
}

extern "C" void kernel_launch(void* const* d_in, const int* in_sizes, int n_in,
                              void* d_out, int out_size)
{
    const float* obs = (const float*)d_in[0];
    const float* oW1 = (const float*)d_in[1];
    const float* ob1 = (const float*)d_in[2];
    const float* oW2 = (const float*)d_in[3];
    const float* ob2 = (const float*)d_in[4];
    const float* pW1 = (const float*)d_in[5];
    const float* pb1 = (const float*)d_in[6];
    const float* pW2 = (const float*)d_in[7];
    const float* pb2 = (const float*)d_in[8];
    const float* pW3 = (const float*)d_in[9];
    const float* pb3 = (const float*)d_in[10];
    const float* Wq  = (const float*)d_in[11];
    const float* bq  = (const float*)d_in[12];
    const float* Wk  = (const float*)d_in[13];
    const float* bk  = (const float*)d_in[14];
    const float* Wv  = (const float*)d_in[15];
    const float* bv  = (const float*)d_in[16];
    float* out = (float*)d_out;

    prep_all<<<256, 256>>>(pW1, pW2, pW3, oW1, oW2, Wq);

    const int smem = (int)sizeof(Smem);
    cudaFuncSetAttribute(pinet_wmma_kernel, cudaFuncAttributeMaxDynamicSharedMemorySize, smem);
    pinet_wmma_kernel<<<GRID_N, NTHR, smem>>>(obs, ob1, ob2, pb1, pb2, pb3,
                                              bq, Wk, bk, Wv, bv, out);
}

// round 14
// speedup vs baseline: 6.4675x; 1.1774x over previous
#include <cuda_runtime.h>
#include <cuda_fp16.h>
#include <mma.h>
#include <math.h>
#include <stdint.h>

using namespace nvcuda;
typedef unsigned long long ull;

#define NOBJ    64
#define FEAT    31
#define HID     256
#define OBS_W   2304
#define OTH_OFF 2048
#define NHEAD   4
#define HDIM    64
#define MROWS   64           // 1 sample x 64 objects per CTA
#define AP      264          // act pitch (half)
#define BP      264          // B-tile pitch (half)
#define RP      264          // rawP pitch (floats)
#define GRID_N  4096
#define NTHR    256
#define CHROWS  32           // K-rows per weight chunk
#define CHELE   (CHROWS * HID)

using FragA = wmma::fragment<wmma::matrix_a, 16, 16, 16, __half, wmma::row_major>;
using FragB = wmma::fragment<wmma::matrix_b, 16, 16, 16, __half, wmma::row_major>;
using FragC = wmma::fragment<wmma::accumulator, 16, 16, 16, float>;

// ---------------- helpers ----------------
static __device__ __forceinline__ uint32_t smem_u32(const void* p) {
    uint32_t a; asm("{ .reg .u64 t; cvta.to.shared.u64 t, %1; cvt.u32.u64 %0, t; }"
                    : "=r"(a) : "l"(p)); return a;
}
static __device__ __forceinline__ void cp16(uint32_t dst, const void* src) {
    asm volatile("cp.async.ca.shared.global [%0], [%1], 16;" :: "r"(dst), "l"(src));
}
#define CP_COMMIT() asm volatile("cp.async.commit_group;" ::: "memory")
#define CP_WAIT1()  asm volatile("cp.async.wait_group 1;" ::: "memory")
#define CP_WAIT0()  asm volatile("cp.async.wait_group 0;" ::: "memory")

static __device__ __forceinline__ ull pack2(float lo, float hi) {
    ull r; asm("mov.b64 %0,{%1,%2};" : "=l"(r) : "f"(lo), "f"(hi)); return r;
}
static __device__ __forceinline__ float2 unpack2(ull v) {
    float2 f; asm("mov.b64 {%0,%1},%2;" : "=f"(f.x), "=f"(f.y) : "l"(v)); return f;
}
static __device__ __forceinline__ ull ffma2(ull a, ull b, ull c) {
    ull d; asm("fma.rn.f32x2 %0,%1,%2,%3;" : "=l"(d) : "l"(a), "l"(b), "l"(c)); return d;
}
static __device__ __forceinline__ uint32_t packh2(float x0, float x1) {
    const __half h0 = __float2half_rn(x0), h1 = __float2half_rn(x1);
    return (uint32_t)__half_as_ushort(h0) | ((uint32_t)__half_as_ushort(h1) << 16);
}

// ---------------- global scratch (fp16 RN weights) ----------------
__device__ __align__(16) __half g_B1[32 * HID];     // L1 (k pad 31->32)
__device__ __align__(16) __half g_B2[HID * HID];    // L2
__device__ __align__(16) __half g_B3[HID * HID];    // L3
__device__ ull g_oW1p[(HID/2)*HID], g_oW2p[(HID/2)*HID], g_Wqp[(HID/2)*HID];

// ONE fused prep kernel (grid 256 x block 256)
__global__ void prep_all(const float* __restrict__ pW1, const float* __restrict__ pW2,
                         const float* __restrict__ pW3, const float* __restrict__ oW1,
                         const float* __restrict__ oW2, const float* __restrict__ Wq)
{
    const int b = blockIdx.x, t = threadIdx.x;
    g_B2[b * HID + t] = __float2half_rn(pW2[b * HID + t]);
    g_B3[b * HID + t] = __float2half_rn(pW3[b * HID + t]);
    if (b < 32)
        g_B1[b * HID + t] = __float2half_rn((b < FEAT) ? pW1[b * HID + t] : 0.0f);
    if (b < 128) {
        g_oW1p[b * HID + t] = pack2(oW1[(2*b) * HID + t], oW1[(2*b+1) * HID + t]);
        g_oW2p[b * HID + t] = pack2(oW2[(2*b) * HID + t], oW2[(2*b+1) * HID + t]);
        g_Wqp [b * HID + t] = pack2(Wq [(2*b) * HID + t], Wq [(2*b+1) * HID + t]);
    }
}

// ---------------- SMEM (~111 KB -> 2 CTAs/SM) ----------------
struct Buf { __half w[CHROWS * BP]; };

struct Smem {
    union {
        __half act[MROWS * AP];          // fp16 activations (single precision term)
        float rawP[MROWS * RP];
    } u;
    Buf bufs[2];
    union {                              // phase-disjoint scratch
        float stg[8][256];               // epilogue staging (per warp 16x16)
        struct { float v0[HID]; float v1[HID]; } sa;          // stage A
        struct { float logit[NHEAD * NOBJ]; float wgt[NHEAD * NOBJ];
                 float Svec[HID]; float Th[NHEAD]; float Wsum[NHEAD]; } at;
    } w;
    float qt[HID];
    float qv[HID];
    float qb[NHEAD], pq[NHEAD];
    float maskv[MROWS];
};

// async-copy one 32x256 fp16 chunk (4 cp.async per thread @256thr)
static __device__ __forceinline__ void cp_chunk(Buf* buf, const __half* src, int tid) {
    const char* sp = reinterpret_cast<const char*>(src);
    const uint32_t dp = smem_u32(buf->w);
#pragma unroll
    for (int i = 0; i < 4; i++) {
        const int idx = tid + i * NTHR;       // 0..1023 (32 rows x 32 int4)
        const int r = idx >> 5, c = idx & 31;
        cp16(dp + (uint32_t)(r * BP * 2 + c * 16), sp + (size_t)idx * 16);
    }
}

// MMA over one 32-K chunk: warp tile 32x64 (c[2][4]); single-term fp16
static __device__ __forceinline__ void mma_chunk(FragC (&c)[2][4],
    const __half* act, const Buf* buf, int kbase, int mbase, int nbase)
{
#pragma unroll
    for (int ks = 0; ks < 2; ks++) {
        FragA a0, a1;
        wmma::load_matrix_sync(a0, act + (size_t)mbase * AP + kbase + ks * 16, AP);
        wmma::load_matrix_sync(a1, act + (size_t)(mbase + 16) * AP + kbase + ks * 16, AP);
#pragma unroll
        for (int nt = 0; nt < 4; nt++) {
            FragB b;
            wmma::load_matrix_sync(b, buf->w + (size_t)(ks * 16) * BP + nbase + nt * 16, BP);
            wmma::mma_sync(c[0][nt], a0, b, c[0][nt]);
            wmma::mma_sync(c[1][nt], a1, b, c[1][nt]);
        }
    }
}

// 8-chunk double-buffered layer; chunks 0,1 already in flight, chunk ch in bufs[(ch+PH)&1]
template<int PH>
static __device__ __forceinline__ void layer_pipe(FragC (&c)[2][4],
    const __half* act, Buf* bufs, const __half* src,
    int mbase, int nbase, int tid)
{
    for (int ch = 0; ch < 8; ch++) {
        if (ch < 7) CP_WAIT1(); else CP_WAIT0();
        __syncthreads();
        mma_chunk(c, act, &bufs[(ch + PH) & 1], ch * CHROWS, mbase, nbase);
        __syncthreads();
        if (ch + 2 < 8) {
            cp_chunk(&bufs[(ch + PH) & 1], src + (size_t)(ch + 2) * CHELE, tid);
            CP_COMMIT();
        }
    }
}

// epilogue: x = relu(C + bias) -> fp16 act (packed STS.32)
static __device__ __forceinline__ void epi_act(FragC (&c)[2][4], float* stg,
    const float* __restrict__ bias, __half* act, int mbase, int nbase, int lane)
{
#pragma unroll
    for (int mi = 0; mi < 2; mi++)
#pragma unroll
        for (int ni = 0; ni < 4; ni++) {
            wmma::store_matrix_sync(stg, c[mi][ni], 16, wmma::mem_row_major);
            __syncwarp();
#pragma unroll
            for (int e = lane; e < 128; e += 32) {
                const int r = e >> 3, c2 = (e & 7) * 2;
                const int j = nbase + ni * 16 + c2;
                const int m = mbase + mi * 16 + r;
                const float x0 = fmaxf(stg[r * 16 + c2]     + __ldg(bias + j),     0.0f);
                const float x1 = fmaxf(stg[r * 16 + c2 + 1] + __ldg(bias + j + 1), 0.0f);
                *reinterpret_cast<uint32_t*>(&act[(size_t)m * AP + j]) = packh2(x0, x1);
            }
            __syncwarp();
        }
}

// 256->256 GEMV, thread j = output column
static __device__ __forceinline__ void gemv1(const ull* __restrict__ Wp,
                                             const float* __restrict__ bias,
                                             const float* x, float* y, int j, bool relu) {
    ull a = pack2(bias[j], 0.0f);
    const ull* wp = Wp + j;
#pragma unroll 4
    for (int k2 = 0; k2 < HID / 2; k2 += 2) {
        const ulonglong2 u = *reinterpret_cast<const ulonglong2*>(x + 2 * k2);
        a = ffma2(u.x, wp[k2 * HID], a);
        a = ffma2(u.y, wp[(k2 + 1) * HID], a);
    }
    const float2 f = unpack2(a);
    float r = f.x + f.y;
    if (relu) r = fmaxf(r, 0.0f);
    y[j] = r;
}

__global__ void __launch_bounds__(NTHR, 2) pinet_wmma_kernel(
    const float* __restrict__ obs,
    const float* __restrict__ ob1, const float* __restrict__ ob2,
    const float* __restrict__ pb1, const float* __restrict__ pb2,
    const float* __restrict__ pb3, const float* __restrict__ bq,
    const float* __restrict__ Wk,  const float* __restrict__ bk,
    const float* __restrict__ Wv,  const float* __restrict__ bv,
    float* __restrict__ out)
{
    extern __shared__ char smraw[];
    Smem* s = reinterpret_cast<Smem*>(smraw);
    const int tid = threadIdx.x, wid = tid >> 5, lane = tid & 31;
    __half* act = s->u.act;

    // ---- prefetch L1 weights (buf0) and L2 chunk0 (buf1) ----
    cp_chunk(&s->bufs[0], g_B1, tid); CP_COMMIT();
    cp_chunk(&s->bufs[1], g_B2, tid); CP_COMMIT();

    const float* row = obs + (size_t)blockIdx.x * OBS_W;

    // ---- load obs: feats -> act fp16 (cols 0..31), mask, others ----
    {
#pragma unroll
        for (int i2 = 0; i2 < 2; i2++) {
            const int i = tid + i2 * NTHR;           // 0..511 float4s of feats
            const float4 a = reinterpret_cast<const float4*>(row)[i];
            const int m0 = i >> 3, d4 = (i & 7) * 4;
            *reinterpret_cast<uint32_t*>(&act[(size_t)m0 * AP + d4])     = packh2(a.x, a.y);
            *reinterpret_cast<uint32_t*>(&act[(size_t)m0 * AP + d4 + 2]) = packh2(a.z, a.w);
            if ((i & 7) == 7) s->maskv[m0] = a.w;
        }
        s->w.sa.v0[tid] = row[OTH_OFF + tid];
    }
    __syncthreads();

    // ---- stage A (overlaps in-flight cp.async) ----
    gemv1(g_oW1p, ob1, s->w.sa.v0, s->w.sa.v1, tid, true);
    __syncthreads();
    {
        float oe;
        {
            ull a = pack2(ob2[tid], 0.0f);
            const ull* wp = g_oW2p + tid;
#pragma unroll 4
            for (int k2 = 0; k2 < HID / 2; k2 += 2) {
                const ulonglong2 u = *reinterpret_cast<const ulonglong2*>(s->w.sa.v1 + 2 * k2);
                a = ffma2(u.x, wp[k2 * HID], a);
                a = ffma2(u.y, wp[(k2 + 1) * HID], a);
            }
            const float2 f = unpack2(a);
            oe = f.x + f.y;
        }
        out[(size_t)blockIdx.x * 512 + tid] = oe;
        __syncthreads();
        s->w.sa.v0[tid] = oe;
    }
    __syncthreads();
    gemv1(g_Wqp, bq, s->w.sa.v0, s->qv, tid, false);    // q
    __syncthreads();
    {   // qt[h*64+d] = Wk[h,d,:].q[h,:] ; qb[h] = q.bk
        const int h = tid >> 6, d = tid & 63;
        const float4* wk4 = reinterpret_cast<const float4*>(Wk + h * (HDIM*HDIM) + d * HDIM);
        const float4* q4  = reinterpret_cast<const float4*>(&s->qv[h * HDIM]);
        float t = 0.0f;
#pragma unroll
        for (int e = 0; e < HDIM / 4; e++) {
            const float4 w = wk4[e], qv = q4[e];
            t += w.x*qv.x + w.y*qv.y + w.z*qv.z + w.w*qv.w;
        }
        s->qt[tid] = t;
        if (tid < NHEAD) {
            float sb = 0.0f;
            for (int e = 0; e < HDIM; e++) sb += s->qv[tid * HDIM + e] * bk[tid * HDIM + e];
            s->qb[tid] = sb;
        }
    }
    __syncthreads();
    if (tid < NHEAD) {   // pq[h] = pb3[h-slice] . qt[h-slice]
        float t = 0.0f;
        for (int d = 0; d < HDIM; d++) t += pb3[tid * HDIM + d] * s->qt[tid * HDIM + d];
        s->pq[tid] = t;
    }

    // ---- object MLP on warp MMA; warp tile 32x64; 2 CTAs/SM ----
    const int mbase = (wid >> 2) * 32;
    const int nbase = (wid & 3) * 64;
    FragC c[2][4];

    // L1: one 32-K chunk (weights in buf0)
#pragma unroll
    for (int mi = 0; mi < 2; mi++)
#pragma unroll
        for (int ni = 0; ni < 4; ni++) wmma::fill_fragment(c[mi][ni], 0.0f);
    CP_WAIT1();                 // L1 done (L2c0 may still be in flight)
    __syncthreads();
    mma_chunk(c, act, &s->bufs[0], 0, mbase, nbase);
    __syncthreads();
    cp_chunk(&s->bufs[0], g_B2 + CHELE, tid); CP_COMMIT();   // L2 chunk1 -> buf0
    epi_act(c, s->w.stg[wid], pb1, act, mbase, nbase, lane);
    __syncthreads();

    // L2: 8 chunks, chunk ch in bufs[(ch+1)&1]
#pragma unroll
    for (int mi = 0; mi < 2; mi++)
#pragma unroll
        for (int ni = 0; ni < 4; ni++) wmma::fill_fragment(c[mi][ni], 0.0f);
    layer_pipe<1>(c, act, s->bufs, g_B2, mbase, nbase, tid);
    cp_chunk(&s->bufs[0], g_B3, tid); CP_COMMIT();           // L3 c0
    cp_chunk(&s->bufs[1], g_B3 + CHELE, tid); CP_COMMIT();   // L3 c1
    epi_act(c, s->w.stg[wid], pb2, act, mbase, nbase, lane);
    __syncthreads();

    // L3: 8 chunks, chunk ch in bufs[ch&1] -> rawP (pb3 folded into attention)
#pragma unroll
    for (int mi = 0; mi < 2; mi++)
#pragma unroll
        for (int ni = 0; ni < 4; ni++) wmma::fill_fragment(c[mi][ni], 0.0f);
    layer_pipe<0>(c, act, s->bufs, g_B3, mbase, nbase, tid);
#pragma unroll
    for (int mi = 0; mi < 2; mi++)
#pragma unroll
        for (int ni = 0; ni < 4; ni++)
            wmma::store_matrix_sync(&s->u.rawP[(size_t)(mbase + mi * 16) * RP + nbase + ni * 16],
                                    c[mi][ni], RP, wmma::mem_row_major);
    __syncthreads();

    // ---- attention (q-len 1; K/V folded; pb3 folded via pq/Wsum) ----
    {
        const int h = tid >> 6, n = tid & 63;
        const float* rp = s->u.rawP + (size_t)n * RP + h * HDIM;
        const float* qt = s->qt + h * HDIM;
        float dot = 0.0f;
#pragma unroll
        for (int d = 0; d < HDIM; d += 4) {
            const float4 a4 = *reinterpret_cast<const float4*>(&rp[d]);
            const float4 b4 = *reinterpret_cast<const float4*>(&qt[d]);
            dot += a4.x*b4.x + a4.y*b4.y + a4.z*b4.z + a4.w*b4.w;
        }
        const float m = s->maskv[n];
        float lg = (m * (dot + s->pq[h]) + s->qb[h]) * 0.0625f;
        if (m == 0.0f) lg = -1000000000.0f;
        s->w.at.logit[h * NOBJ + n] = lg;
    }
    __syncthreads();
    if (wid < NHEAD) {   // softmax: warp = head
        const int hh = wid;
        const float x0 = s->w.at.logit[hh * NOBJ + lane];
        const float x1 = s->w.at.logit[hh * NOBJ + 32 + lane];
        float mx = fmaxf(x0, x1);
#pragma unroll
        for (int o = 16; o > 0; o >>= 1) mx = fmaxf(mx, __shfl_xor_sync(0xffffffffu, mx, o));
        const float e0 = expf(x0 - mx), e1 = expf(x1 - mx);
        float sum = e0 + e1;
#pragma unroll
        for (int o = 16; o > 0; o >>= 1) sum += __shfl_xor_sync(0xffffffffu, sum, o);
        const float inv = 1.0f / sum;
        const float a0 = e0 * inv, a1 = e1 * inv;
        const float m0 = s->maskv[lane], m1 = s->maskv[32 + lane];
        const float w0 = a0 * m0 * m0, w1 = a1 * m1 * m1;
        s->w.at.wgt[hh * NOBJ + lane]      = w0;
        s->w.at.wgt[hh * NOBJ + 32 + lane] = w1;
        float tt = a0 * m0 + a1 * m1;
        float ws = w0 + w1;
#pragma unroll
        for (int o = 16; o > 0; o >>= 1) {
            tt += __shfl_xor_sync(0xffffffffu, tt, o);
            ws += __shfl_xor_sync(0xffffffffu, ws, o);
        }
        if (lane == 0) { s->w.at.Th[hh] = tt; s->w.at.Wsum[hh] = ws; }
    }
    __syncthreads();
    {   // Svec = sum_n wgt*rawP + Wsum*pb3
        const int h = tid >> 6, d = tid & 63;
        const float* wp = s->w.at.wgt + h * NOBJ;
        float acc = 0.0f;
#pragma unroll 4
        for (int nn = 0; nn < NOBJ; nn++)
            acc = fmaf(wp[nn], s->u.rawP[(size_t)nn * RP + h * HDIM + d], acc);
        s->w.at.Svec[tid] = acc + s->w.at.Wsum[h] * pb3[h * HDIM + d];
    }
    __syncthreads();
    {   // out_emb = Svec @ Wv + Th*bv
        const int h = tid >> 6, e = tid & 63;
        float o = s->w.at.Th[h] * bv[h * HDIM + e];
        const float* sv = s->w.at.Svec + h * HDIM;
        const float* wv = Wv + h * (HDIM * HDIM) + e;
#pragma unroll 4
        for (int d = 0; d < HDIM; d++)
            o = fmaf(sv[d], wv[d * HDIM], o);
        out[(size_t)blockIdx.x * 512 + 256 + h * HDIM + e] = o;
    }
}

extern "C" void kernel_launch(void* const* d_in, const int* in_sizes, int n_in,
                              void* d_out, int out_size)
{
    const float* obs = (const float*)d_in[0];
    const float* oW1 = (const float*)d_in[1];
    const float* ob1 = (const float*)d_in[2];
    const float* oW2 = (const float*)d_in[3];
    const float* ob2 = (const float*)d_in[4];
    const float* pW1 = (const float*)d_in[5];
    const float* pb1 = (const float*)d_in[6];
    const float* pW2 = (const float*)d_in[7];
    const float* pb2 = (const float*)d_in[8];
    const float* pW3 = (const float*)d_in[9];
    const float* pb3 = (const float*)d_in[10];
    const float* Wq  = (const float*)d_in[11];
    const float* bq  = (const float*)d_in[12];
    const float* Wk  = (const float*)d_in[13];
    const float* bk  = (const float*)d_in[14];
    const float* Wv  = (const float*)d_in[15];
    const float* bv  = (const float*)d_in[16];
    float* out = (float*)d_out;

    prep_all<<<256, 256>>>(pW1, pW2, pW3, oW1, oW2, Wq);

    const int smem = (int)sizeof(Smem);
    cudaFuncSetAttribute(pinet_wmma_kernel, cudaFuncAttributeMaxDynamicSharedMemorySize, smem);
    pinet_wmma_kernel<<<GRID_N, NTHR, smem>>>(obs, ob1, ob2, pb1, pb2, pb3,
                                              bq, Wk, bk, Wv, bv, out);
}

// round 15
// speedup vs baseline: 7.1805x; 1.1103x over previous
#include <cuda_runtime.h>
#include <cuda_fp16.h>
#include <math.h>
#include <stdint.h>

typedef unsigned long long ull;

#define NOBJ    64
#define FEAT    31
#define HID     256
#define OBS_W   2304
#define OTH_OFF 2048
#define NHEAD   4
#define HDIM    64
#define MROWS   64           // 1 sample x 64 objects per CTA
#define AP      264          // act pitch (half)
#define BP      264          // B-tile pitch (half)
#define RPF     268          // rawP pitch (floats; mod32=12 -> conflict-free rows)
#define GRID_N  4096
#define NTHR    256
#define CHROWS  32           // K-rows per weight chunk
#define CHELE   (CHROWS * HID)

// ---------------- helpers ----------------
static __device__ __forceinline__ uint32_t smem_u32(const void* p) {
    uint32_t a; asm("{ .reg .u64 t; cvta.to.shared.u64 t, %1; cvt.u32.u64 %0, t; }"
                    : "=r"(a) : "l"(p)); return a;
}
static __device__ __forceinline__ void cp16(uint32_t dst, const void* src) {
    asm volatile("cp.async.ca.shared.global [%0], [%1], 16;" :: "r"(dst), "l"(src));
}
#define CP_COMMIT() asm volatile("cp.async.commit_group;" ::: "memory")
#define CP_WAIT1()  asm volatile("cp.async.wait_group 1;" ::: "memory")
#define CP_WAIT0()  asm volatile("cp.async.wait_group 0;" ::: "memory")

static __device__ __forceinline__ ull pack2(float lo, float hi) {
    ull r; asm("mov.b64 %0,{%1,%2};" : "=l"(r) : "f"(lo), "f"(hi)); return r;
}
static __device__ __forceinline__ float2 unpack2(ull v) {
    float2 f; asm("mov.b64 {%0,%1},%2;" : "=f"(f.x), "=f"(f.y) : "l"(v)); return f;
}
static __device__ __forceinline__ ull ffma2(ull a, ull b, ull c) {
    ull d; asm("fma.rn.f32x2 %0,%1,%2,%3;" : "=l"(d) : "l"(a), "l"(b), "l"(c)); return d;
}
static __device__ __forceinline__ uint32_t packh2(float x0, float x1) {
    const __half h0 = __float2half_rn(x0), h1 = __float2half_rn(x1);
    return (uint32_t)__half_as_ushort(h0) | ((uint32_t)__half_as_ushort(h1) << 16);
}

// ---------------- mma.sync primitives ----------------
static __device__ __forceinline__ void ldmA(uint32_t (&a)[4], uint32_t addr) {
    asm volatile("ldmatrix.sync.aligned.m8n8.x4.shared.b16 {%0,%1,%2,%3}, [%4];"
        : "=r"(a[0]), "=r"(a[1]), "=r"(a[2]), "=r"(a[3]) : "r"(addr));
}
static __device__ __forceinline__ void ldmBT(uint32_t (&b)[4], uint32_t addr) {
    asm volatile("ldmatrix.sync.aligned.m8n8.x4.trans.shared.b16 {%0,%1,%2,%3}, [%4];"
        : "=r"(b[0]), "=r"(b[1]), "=r"(b[2]), "=r"(b[3]) : "r"(addr));
}
static __device__ __forceinline__ void mma16816(float (&d)[4], const uint32_t (&a)[4],
                                                uint32_t b0, uint32_t b1) {
    asm volatile("mma.sync.aligned.m16n8k16.row.col.f32.f16.f16.f32 "
        "{%0,%1,%2,%3}, {%4,%5,%6,%7}, {%8,%9}, {%0,%1,%2,%3};"
        : "+f"(d[0]), "+f"(d[1]), "+f"(d[2]), "+f"(d[3])
        : "r"(a[0]), "r"(a[1]), "r"(a[2]), "r"(a[3]), "r"(b0), "r"(b1));
}

// ---------------- global scratch (fp16 RN weights) ----------------
__device__ __align__(16) __half g_B1[32 * HID];     // L1 (k pad 31->32)
__device__ __align__(16) __half g_B2[HID * HID];    // L2
__device__ __align__(16) __half g_B3[HID * HID];    // L3
__device__ ull g_oW1p[(HID/2)*HID], g_oW2p[(HID/2)*HID], g_Wqp[(HID/2)*HID];

__global__ void prep_all(const float* __restrict__ pW1, const float* __restrict__ pW2,
                         const float* __restrict__ pW3, const float* __restrict__ oW1,
                         const float* __restrict__ oW2, const float* __restrict__ Wq)
{
    const int b = blockIdx.x, t = threadIdx.x;
    g_B2[b * HID + t] = __float2half_rn(pW2[b * HID + t]);
    g_B3[b * HID + t] = __float2half_rn(pW3[b * HID + t]);
    if (b < 32)
        g_B1[b * HID + t] = __float2half_rn((b < FEAT) ? pW1[b * HID + t] : 0.0f);
    if (b < 128) {
        g_oW1p[b * HID + t] = pack2(oW1[(2*b) * HID + t], oW1[(2*b+1) * HID + t]);
        g_oW2p[b * HID + t] = pack2(oW2[(2*b) * HID + t], oW2[(2*b+1) * HID + t]);
        g_Wqp [b * HID + t] = pack2(Wq [(2*b) * HID + t], Wq [(2*b+1) * HID + t]);
    }
}

// ---------------- SMEM (~109 KB -> 2 CTAs/SM) ----------------
struct Buf { __half w[CHROWS * BP]; };

struct Smem {
    union {
        __half act[MROWS * AP];          // fp16 activations
        float rawP[MROWS * RPF];
    } u;
    Buf bufs[2];
    float b1s[HID], b2s[HID];            // SMEM bias copies
    union {                              // phase-disjoint scratch
        struct { float v0[HID]; float v1[HID]; } sa;
        struct { float logit[NHEAD * NOBJ]; float wgt[NHEAD * NOBJ];
                 float Svec[HID]; float Th[NHEAD]; float Wsum[NHEAD]; } at;
    } w;
    float qt[HID];
    float qv[HID];
    float qb[NHEAD], pq[NHEAD];
    float maskv[MROWS];
};

// async-copy one 32x256 fp16 chunk (4 cp.async per thread @256thr)
static __device__ __forceinline__ void cp_chunk(Buf* buf, const __half* src, int tid) {
    const char* sp = reinterpret_cast<const char*>(src);
    const uint32_t dp = smem_u32(buf->w);
#pragma unroll
    for (int i = 0; i < 4; i++) {
        const int idx = tid + i * NTHR;       // 0..1023 (32 rows x 32 int4)
        const int r = idx >> 5, c = idx & 31;
        cp16(dp + (uint32_t)(r * BP * 2 + c * 16), sp + (size_t)idx * 16);
    }
}

// MMA over one 32-K chunk: warp tile 32x64; c[2][8][4] accumulators
static __device__ __forceinline__ void mma_chunk(float (&c)[2][8][4],
    uint32_t actAddr, uint32_t bufAddr, int kbase, int mbase, int nbase, int lane)
{
    const uint32_t aoff = (uint32_t)(((lane & 15) * AP + ((lane >> 4) << 3)) * 2);
    const uint32_t boff = (uint32_t)((((lane & 7) + (((lane >> 3) & 1) << 3)) * BP
                                      + ((lane >> 4) << 3)) * 2);
#pragma unroll
    for (int ks = 0; ks < 2; ks++) {
        uint32_t a0[4], a1[4];
        ldmA(a0, actAddr + aoff + (uint32_t)((mbase * AP + kbase + ks * 16) * 2));
        ldmA(a1, actAddr + aoff + (uint32_t)(((mbase + 16) * AP + kbase + ks * 16) * 2));
#pragma unroll
        for (int nj = 0; nj < 4; nj++) {
            uint32_t b[4];
            ldmBT(b, bufAddr + boff + (uint32_t)((ks * 16 * BP + nbase + nj * 16) * 2));
            mma16816(c[0][nj*2+0], a0, b[0], b[1]);
            mma16816(c[0][nj*2+1], a0, b[2], b[3]);
            mma16816(c[1][nj*2+0], a1, b[0], b[1]);
            mma16816(c[1][nj*2+1], a1, b[2], b[3]);
        }
    }
}

// 8-chunk double-buffered layer; chunks 0,1 already in flight, chunk ch in bufs[(ch+PH)&1]
template<int PH>
static __device__ __forceinline__ void layer_pipe(float (&c)[2][8][4],
    uint32_t actAddr, Buf* bufs, uint32_t buf0Addr, uint32_t buf1Addr,
    const __half* src, int mbase, int nbase, int lane, int tid)
{
    const uint32_t ba[2] = { buf0Addr, buf1Addr };
    for (int ch = 0; ch < 8; ch++) {
        if (ch < 7) CP_WAIT1(); else CP_WAIT0();
        __syncthreads();
        mma_chunk(c, actAddr, ba[(ch + PH) & 1], ch * CHROWS, mbase, nbase, lane);
        __syncthreads();
        if (ch + 2 < 8) {
            cp_chunk(&bufs[(ch + PH) & 1], src + (size_t)(ch + 2) * CHELE, tid);
            CP_COMMIT();
        }
    }
}

// register epilogue: x = relu(C + bias) -> fp16 act, direct packed STS.32
static __device__ __forceinline__ void epi_act_reg(float (&c)[2][8][4],
    const float* __restrict__ bias_s, __half* act, int mbase, int nbase, int lane)
{
    const int g = lane >> 2, tc = (lane & 3) * 2;
#pragma unroll
    for (int mi = 0; mi < 2; mi++) {
        const int r0 = mbase + mi * 16 + g;
#pragma unroll
        for (int nj = 0; nj < 8; nj++) {
            const int j = nbase + nj * 8 + tc;
            const float b0 = bias_s[j], b1 = bias_s[j + 1];
            const float x0 = fmaxf(c[mi][nj][0] + b0, 0.0f);
            const float x1 = fmaxf(c[mi][nj][1] + b1, 0.0f);
            const float x2 = fmaxf(c[mi][nj][2] + b0, 0.0f);
            const float x3 = fmaxf(c[mi][nj][3] + b1, 0.0f);
            *reinterpret_cast<uint32_t*>(&act[(size_t)r0 * AP + j])       = packh2(x0, x1);
            *reinterpret_cast<uint32_t*>(&act[(size_t)(r0 + 8) * AP + j]) = packh2(x2, x3);
        }
    }
}

static __device__ __forceinline__ void zero_c(float (&c)[2][8][4]) {
#pragma unroll
    for (int mi = 0; mi < 2; mi++)
#pragma unroll
        for (int nj = 0; nj < 8; nj++)
#pragma unroll
            for (int e = 0; e < 4; e++) c[mi][nj][e] = 0.0f;
}

// 256->256 GEMV, thread j = output column
static __device__ __forceinline__ void gemv1(const ull* __restrict__ Wp,
                                             const float* __restrict__ bias,
                                             const float* x, float* y, int j, bool relu) {
    ull a = pack2(bias[j], 0.0f);
    const ull* wp = Wp + j;
#pragma unroll 4
    for (int k2 = 0; k2 < HID / 2; k2 += 2) {
        const ulonglong2 u = *reinterpret_cast<const ulonglong2*>(x + 2 * k2);
        a = ffma2(u.x, wp[k2 * HID], a);
        a = ffma2(u.y, wp[(k2 + 1) * HID], a);
    }
    const float2 f = unpack2(a);
    float r = f.x + f.y;
    if (relu) r = fmaxf(r, 0.0f);
    y[j] = r;
}

__global__ void __launch_bounds__(NTHR, 2) pinet_mma_kernel(
    const float* __restrict__ obs,
    const float* __restrict__ ob1, const float* __restrict__ ob2,
    const float* __restrict__ pb1, const float* __restrict__ pb2,
    const float* __restrict__ pb3, const float* __restrict__ bq,
    const float* __restrict__ Wk,  const float* __restrict__ bk,
    const float* __restrict__ Wv,  const float* __restrict__ bv,
    float* __restrict__ out)
{
    extern __shared__ char smraw[];
    Smem* s = reinterpret_cast<Smem*>(smraw);
    const int tid = threadIdx.x, wid = tid >> 5, lane = tid & 31;
    __half* act = s->u.act;
    const uint32_t actAddr  = smem_u32(s->u.act);
    const uint32_t buf0Addr = smem_u32(s->bufs[0].w);
    const uint32_t buf1Addr = smem_u32(s->bufs[1].w);

    // ---- prefetch L1 weights (buf0) and L2 chunk0 (buf1) ----
    cp_chunk(&s->bufs[0], g_B1, tid); CP_COMMIT();
    cp_chunk(&s->bufs[1], g_B2, tid); CP_COMMIT();

    const float* row = obs + (size_t)blockIdx.x * OBS_W;

    // ---- load obs: feats -> act fp16 (cols 0..31), mask, others, biases ----
    {
#pragma unroll
        for (int i2 = 0; i2 < 2; i2++) {
            const int i = tid + i2 * NTHR;           // 0..511 float4s of feats
            const float4 a = reinterpret_cast<const float4*>(row)[i];
            const int m0 = i >> 3, d4 = (i & 7) * 4;
            *reinterpret_cast<uint32_t*>(&act[(size_t)m0 * AP + d4])     = packh2(a.x, a.y);
            *reinterpret_cast<uint32_t*>(&act[(size_t)m0 * AP + d4 + 2]) = packh2(a.z, a.w);
            if ((i & 7) == 7) s->maskv[m0] = a.w;
        }
        s->w.sa.v0[tid] = row[OTH_OFF + tid];
        s->b1s[tid] = pb1[tid];
        s->b2s[tid] = pb2[tid];
    }
    __syncthreads();

    // ---- stage A (overlaps in-flight cp.async) ----
    gemv1(g_oW1p, ob1, s->w.sa.v0, s->w.sa.v1, tid, true);
    __syncthreads();
    {
        float oe;
        {
            ull a = pack2(ob2[tid], 0.0f);
            const ull* wp = g_oW2p + tid;
#pragma unroll 4
            for (int k2 = 0; k2 < HID / 2; k2 += 2) {
                const ulonglong2 u = *reinterpret_cast<const ulonglong2*>(s->w.sa.v1 + 2 * k2);
                a = ffma2(u.x, wp[k2 * HID], a);
                a = ffma2(u.y, wp[(k2 + 1) * HID], a);
            }
            const float2 f = unpack2(a);
            oe = f.x + f.y;
        }
        out[(size_t)blockIdx.x * 512 + tid] = oe;
        __syncthreads();
        s->w.sa.v0[tid] = oe;
    }
    __syncthreads();
    gemv1(g_Wqp, bq, s->w.sa.v0, s->qv, tid, false);    // q
    __syncthreads();
    {   // qt[h*64+d] = Wk[h,d,:].q[h,:] ; qb[h] = q.bk
        const int h = tid >> 6, d = tid & 63;
        const float4* wk4 = reinterpret_cast<const float4*>(Wk + h * (HDIM*HDIM) + d * HDIM);
        const float4* q4  = reinterpret_cast<const float4*>(&s->qv[h * HDIM]);
        float t = 0.0f;
#pragma unroll
        for (int e = 0; e < HDIM / 4; e++) {
            const float4 w = wk4[e], qv = q4[e];
            t += w.x*qv.x + w.y*qv.y + w.z*qv.z + w.w*qv.w;
        }
        s->qt[tid] = t;
        if (tid < NHEAD) {
            float sb = 0.0f;
            for (int e = 0; e < HDIM; e++) sb += s->qv[tid * HDIM + e] * bk[tid * HDIM + e];
            s->qb[tid] = sb;
        }
    }
    __syncthreads();
    if (tid < NHEAD) {   // pq[h] = pb3[h-slice] . qt[h-slice]
        float t = 0.0f;
        for (int d = 0; d < HDIM; d++) t += pb3[tid * HDIM + d] * s->qt[tid * HDIM + d];
        s->pq[tid] = t;
    }

    // ---- object MLP on mma.sync; warp tile 32x64; 2 CTAs/SM ----
    const int mbase = (wid >> 2) * 32;
    const int nbase = (wid & 3) * 64;
    float c[2][8][4];

    // L1: one 32-K chunk (weights in buf0)
    zero_c(c);
    CP_WAIT1();                 // L1 done (L2c0 may still be in flight)
    __syncthreads();
    mma_chunk(c, actAddr, buf0Addr, 0, mbase, nbase, lane);
    __syncthreads();
    cp_chunk(&s->bufs[0], g_B2 + CHELE, tid); CP_COMMIT();   // L2 chunk1 -> buf0
    epi_act_reg(c, s->b1s, act, mbase, nbase, lane);
    __syncthreads();

    // L2: 8 chunks, chunk ch in bufs[(ch+1)&1]
    zero_c(c);
    layer_pipe<1>(c, actAddr, s->bufs, buf0Addr, buf1Addr, g_B2, mbase, nbase, lane, tid);
    cp_chunk(&s->bufs[0], g_B3, tid); CP_COMMIT();           // L3 c0
    cp_chunk(&s->bufs[1], g_B3 + CHELE, tid); CP_COMMIT();   // L3 c1
    epi_act_reg(c, s->b2s, act, mbase, nbase, lane);
    __syncthreads();

    // L3: 8 chunks, chunk ch in bufs[ch&1] -> rawP (pb3 folded into attention)
    zero_c(c);
    layer_pipe<0>(c, actAddr, s->bufs, buf0Addr, buf1Addr, g_B3, mbase, nbase, lane, tid);
    {   // direct register -> rawP (act union now dead)
        const int g = lane >> 2, tc = (lane & 3) * 2;
#pragma unroll
        for (int mi = 0; mi < 2; mi++) {
            const int r0 = mbase + mi * 16 + g;
#pragma unroll
            for (int nj = 0; nj < 8; nj++) {
                const int j = nbase + nj * 8 + tc;
                *reinterpret_cast<float2*>(&s->u.rawP[(size_t)r0 * RPF + j]) =
                    make_float2(c[mi][nj][0], c[mi][nj][1]);
                *reinterpret_cast<float2*>(&s->u.rawP[(size_t)(r0 + 8) * RPF + j]) =
                    make_float2(c[mi][nj][2], c[mi][nj][3]);
            }
        }
    }
    __syncthreads();

    // ---- attention (q-len 1; K/V folded; pb3 folded via pq/Wsum) ----
    {
        const int h = tid >> 6, n = tid & 63;
        const float* rp = s->u.rawP + (size_t)n * RPF + h * HDIM;
        const float* qt = s->qt + h * HDIM;
        float dot = 0.0f;
#pragma unroll
        for (int d = 0; d < HDIM; d += 4) {
            const float4 a4 = *reinterpret_cast<const float4*>(&rp[d]);
            const float4 b4 = *reinterpret_cast<const float4*>(&qt[d]);
            dot += a4.x*b4.x + a4.y*b4.y + a4.z*b4.z + a4.w*b4.w;
        }
        const float m = s->maskv[n];
        float lg = (m * (dot + s->pq[h]) + s->qb[h]) * 0.0625f;
        if (m == 0.0f) lg = -1000000000.0f;
        s->w.at.logit[h * NOBJ + n] = lg;
    }
    __syncthreads();
    if (wid < NHEAD) {   // softmax: warp = head
        const int hh = wid;
        const float x0 = s->w.at.logit[hh * NOBJ + lane];
        const float x1 = s->w.at.logit[hh * NOBJ + 32 + lane];
        float mx = fmaxf(x0, x1);
#pragma unroll
        for (int o = 16; o > 0; o >>= 1) mx = fmaxf(mx, __shfl_xor_sync(0xffffffffu, mx, o));
        const float e0 = expf(x0 - mx), e1 = expf(x1 - mx);
        float sum = e0 + e1;
#pragma unroll
        for (int o = 16; o > 0; o >>= 1) sum += __shfl_xor_sync(0xffffffffu, sum, o);
        const float inv = 1.0f / sum;
        const float a0 = e0 * inv, a1 = e1 * inv;
        const float m0 = s->maskv[lane], m1 = s->maskv[32 + lane];
        const float w0 = a0 * m0 * m0, w1 = a1 * m1 * m1;
        s->w.at.wgt[hh * NOBJ + lane]      = w0;
        s->w.at.wgt[hh * NOBJ + 32 + lane] = w1;
        float tt = a0 * m0 + a1 * m1;
        float ws = w0 + w1;
#pragma unroll
        for (int o = 16; o > 0; o >>= 1) {
            tt += __shfl_xor_sync(0xffffffffu, tt, o);
            ws += __shfl_xor_sync(0xffffffffu, ws, o);
        }
        if (lane == 0) { s->w.at.Th[hh] = tt; s->w.at.Wsum[hh] = ws; }
    }
    __syncthreads();
    {   // Svec = sum_n wgt*rawP + Wsum*pb3
        const int h = tid >> 6, d = tid & 63;
        const float* wp = s->w.at.wgt + h * NOBJ;
        float acc = 0.0f;
#pragma unroll 4
        for (int nn = 0; nn < NOBJ; nn++)
            acc = fmaf(wp[nn], s->u.rawP[(size_t)nn * RPF + h * HDIM + d], acc);
        s->w.at.Svec[tid] = acc + s->w.at.Wsum[h] * pb3[h * HDIM + d];
    }
    __syncthreads();
    {   // out_emb = Svec @ Wv + Th*bv
        const int h = tid >> 6, e = tid & 63;
        float o = s->w.at.Th[h] * bv[h * HDIM + e];
        const float* sv = s->w.at.Svec + h * HDIM;
        const float* wv = Wv + h * (HDIM * HDIM) + e;
#pragma unroll 4
        for (int d = 0; d < HDIM; d++)
            o = fmaf(sv[d], wv[d * HDIM], o);
        out[(size_t)blockIdx.x * 512 + 256 + h * HDIM + e] = o;
    }
}

extern "C" void kernel_launch(void* const* d_in, const int* in_sizes, int n_in,
                              void* d_out, int out_size)
{
    const float* obs = (const float*)d_in[0];
    const float* oW1 = (const float*)d_in[1];
    const float* ob1 = (const float*)d_in[2];
    const float* oW2 = (const float*)d_in[3];
    const float* ob2 = (const float*)d_in[4];
    const float* pW1 = (const float*)d_in[5];
    const float* pb1 = (const float*)d_in[6];
    const float* pW2 = (const float*)d_in[7];
    const float* pb2 = (const float*)d_in[8];
    const float* pW3 = (const float*)d_in[9];
    const float* pb3 = (const float*)d_in[10];
    const float* Wq  = (const float*)d_in[11];
    const float* bq  = (const float*)d_in[12];
    const float* Wk  = (const float*)d_in[13];
    const float* bk  = (const float*)d_in[14];
    const float* Wv  = (const float*)d_in[15];
    const float* bv  = (const float*)d_in[16];
    float* out = (float*)d_out;

    prep_all<<<256, 256>>>(pW1, pW2, pW3, oW1, oW2, Wq);

    const int smem = (int)sizeof(Smem);
    cudaFuncSetAttribute(pinet_mma_kernel, cudaFuncAttributeMaxDynamicSharedMemorySize, smem);
    pinet_mma_kernel<<<GRID_N, NTHR, smem>>>(obs, ob1, ob2, pb1, pb2, pb3,
                                             bq, Wk, bk, Wv, bv, out);
}

// round 16
// speedup vs baseline: 7.2483x; 1.0094x over previous
#include <cuda_runtime.h>
#include <cuda_fp16.h>
#include <math.h>
#include <stdint.h>

typedef unsigned long long ull;

#define NOBJ    64
#define FEAT    31
#define HID     256
#define OBS_W   2304
#define OTH_OFF 2048
#define NHEAD   4
#define HDIM    64
#define MROWS   64           // 1 sample x 64 objects per CTA
#define AP      264          // act pitch (half)
#define BP      264          // B-tile pitch (half)
#define RPF     268          // rawP pitch (floats)
#define GRID_N  4096
#define NTHR    256
#define CHROWS  32           // K-rows per weight chunk
#define CHELE   (CHROWS * HID)

// ---------------- helpers ----------------
static __device__ __forceinline__ uint32_t smem_u32(const void* p) {
    uint32_t a; asm("{ .reg .u64 t; cvta.to.shared.u64 t, %1; cvt.u32.u64 %0, t; }"
                    : "=r"(a) : "l"(p)); return a;
}
// .cg: bypass L1 (L2 -> SMEM direct); saves the L1 fill traffic of .ca
static __device__ __forceinline__ void cp16(uint32_t dst, const void* src) {
    asm volatile("cp.async.cg.shared.global [%0], [%1], 16;" :: "r"(dst), "l"(src));
}
#define CP_COMMIT() asm volatile("cp.async.commit_group;" ::: "memory")
#define CP_WAIT1()  asm volatile("cp.async.wait_group 1;" ::: "memory")
#define CP_WAIT0()  asm volatile("cp.async.wait_group 0;" ::: "memory")

static __device__ __forceinline__ ull pack2(float lo, float hi) {
    ull r; asm("mov.b64 %0,{%1,%2};" : "=l"(r) : "f"(lo), "f"(hi)); return r;
}
static __device__ __forceinline__ float2 unpack2(ull v) {
    float2 f; asm("mov.b64 {%0,%1},%2;" : "=f"(f.x), "=f"(f.y) : "l"(v)); return f;
}
static __device__ __forceinline__ ull ffma2(ull a, ull b, ull c) {
    ull d; asm("fma.rn.f32x2 %0,%1,%2,%3;" : "=l"(d) : "l"(a), "l"(b), "l"(c)); return d;
}
static __device__ __forceinline__ uint32_t packh2(float x0, float x1) {
    const __half h0 = __float2half_rn(x0), h1 = __float2half_rn(x1);
    return (uint32_t)__half_as_ushort(h0) | ((uint32_t)__half_as_ushort(h1) << 16);
}

// ---------------- mma.sync primitives ----------------
static __device__ __forceinline__ void ldmA(uint32_t (&a)[4], uint32_t addr) {
    asm volatile("ldmatrix.sync.aligned.m8n8.x4.shared.b16 {%0,%1,%2,%3}, [%4];"
        : "=r"(a[0]), "=r"(a[1]), "=r"(a[2]), "=r"(a[3]) : "r"(addr));
}
static __device__ __forceinline__ void ldmBT(uint32_t (&b)[4], uint32_t addr) {
    asm volatile("ldmatrix.sync.aligned.m8n8.x4.trans.shared.b16 {%0,%1,%2,%3}, [%4];"
        : "=r"(b[0]), "=r"(b[1]), "=r"(b[2]), "=r"(b[3]) : "r"(addr));
}
static __device__ __forceinline__ void mma16816(float (&d)[4], const uint32_t (&a)[4],
                                                uint32_t b0, uint32_t b1) {
    asm volatile("mma.sync.aligned.m16n8k16.row.col.f32.f16.f16.f32 "
        "{%0,%1,%2,%3}, {%4,%5,%6,%7}, {%8,%9}, {%0,%1,%2,%3};"
        : "+f"(d[0]), "+f"(d[1]), "+f"(d[2]), "+f"(d[3])
        : "r"(a[0]), "r"(a[1]), "r"(a[2]), "r"(a[3]), "r"(b0), "r"(b1));
}

// ---------------- global scratch (fp16 RN weights) ----------------
__device__ __align__(16) __half g_B1[32 * HID];     // L1 (k pad 31->32)
__device__ __align__(16) __half g_B2[HID * HID];    // L2
__device__ __align__(16) __half g_B3[HID * HID];    // L3
__device__ ull g_oW1p[(HID/2)*HID], g_oW2p[(HID/2)*HID], g_Wqp[(HID/2)*HID];

__global__ void prep_all(const float* __restrict__ pW1, const float* __restrict__ pW2,
                         const float* __restrict__ pW3, const float* __restrict__ oW1,
                         const float* __restrict__ oW2, const float* __restrict__ Wq)
{
    const int b = blockIdx.x, t = threadIdx.x;
    g_B2[b * HID + t] = __float2half_rn(pW2[b * HID + t]);
    g_B3[b * HID + t] = __float2half_rn(pW3[b * HID + t]);
    if (b < 32)
        g_B1[b * HID + t] = __float2half_rn((b < FEAT) ? pW1[b * HID + t] : 0.0f);
    if (b < 128) {
        g_oW1p[b * HID + t] = pack2(oW1[(2*b) * HID + t], oW1[(2*b+1) * HID + t]);
        g_oW2p[b * HID + t] = pack2(oW2[(2*b) * HID + t], oW2[(2*b+1) * HID + t]);
        g_Wqp [b * HID + t] = pack2(Wq [(2*b) * HID + t], Wq [(2*b+1) * HID + t]);
    }
}

// ---------------- SMEM (~109 KB -> 2 CTAs/SM) ----------------
struct Buf { __half w[CHROWS * BP]; };

struct Smem {
    union {
        __half act[MROWS * AP];          // fp16 activations
        float rawP[MROWS * RPF];
    } u;
    Buf bufs[2];
    float b1s[HID], b2s[HID];            // SMEM bias copies
    union {                              // phase-disjoint scratch
        struct { float v0[HID]; float v1[HID]; } sa;
        struct { float logit[NHEAD * NOBJ]; float wgt[NHEAD * NOBJ];
                 float Svec[HID]; float Th[NHEAD]; float Wsum[NHEAD]; } at;
    } w;
    float qt[HID];
    float qv[HID];
    float qb[NHEAD], pq[NHEAD];
    float maskv[MROWS];
};

// async-copy one 32x256 fp16 chunk (4 cp.async per thread @256thr)
static __device__ __forceinline__ void cp_chunk(Buf* buf, const __half* src, int tid) {
    const char* sp = reinterpret_cast<const char*>(src);
    const uint32_t dp = smem_u32(buf->w);
#pragma unroll
    for (int i = 0; i < 4; i++) {
        const int idx = tid + i * NTHR;       // 0..1023 (32 rows x 32 int4)
        const int r = idx >> 5, c = idx & 31;
        cp16(dp + (uint32_t)(r * BP * 2 + c * 16), sp + (size_t)idx * 16);
    }
}

// MMA over one 32-K chunk: warp tile 32x64; batched LDSM per ks for MLP
static __device__ __forceinline__ void mma_chunk(float (&c)[2][8][4],
    uint32_t actAddr, uint32_t bufAddr, int kbase, int mbase, int nbase, int lane)
{
    const uint32_t aoff = (uint32_t)(((lane & 15) * AP + ((lane >> 4) << 3)) * 2);
    const uint32_t boff = (uint32_t)((((lane & 7) + (((lane >> 3) & 1) << 3)) * BP
                                      + ((lane >> 4) << 3)) * 2);
#pragma unroll
    for (int ks = 0; ks < 2; ks++) {
        // batch all loads for this k-step (6 independent LDSM in flight)
        uint32_t a0[4], a1[4], b[4][4];
        ldmA(a0, actAddr + aoff + (uint32_t)((mbase * AP + kbase + ks * 16) * 2));
        ldmA(a1, actAddr + aoff + (uint32_t)(((mbase + 16) * AP + kbase + ks * 16) * 2));
#pragma unroll
        for (int nj = 0; nj < 4; nj++)
            ldmBT(b[nj], bufAddr + boff + (uint32_t)((ks * 16 * BP + nbase + nj * 16) * 2));
#pragma unroll
        for (int nj = 0; nj < 4; nj++) {
            mma16816(c[0][nj*2+0], a0, b[nj][0], b[nj][1]);
            mma16816(c[0][nj*2+1], a0, b[nj][2], b[nj][3]);
            mma16816(c[1][nj*2+0], a1, b[nj][0], b[nj][1]);
            mma16816(c[1][nj*2+1], a1, b[nj][2], b[nj][3]);
        }
    }
}

// 8-chunk double-buffered layer; chunks 0,1 already in flight, chunk ch in bufs[(ch+PH)&1]
template<int PH>
static __device__ __forceinline__ void layer_pipe(float (&c)[2][8][4],
    uint32_t actAddr, Buf* bufs, uint32_t buf0Addr, uint32_t buf1Addr,
    const __half* src, int mbase, int nbase, int lane, int tid)
{
    const uint32_t ba[2] = { buf0Addr, buf1Addr };
    for (int ch = 0; ch < 8; ch++) {
        if (ch < 7) CP_WAIT1(); else CP_WAIT0();
        __syncthreads();
        mma_chunk(c, actAddr, ba[(ch + PH) & 1], ch * CHROWS, mbase, nbase, lane);
        __syncthreads();
        if (ch + 2 < 8) {
            cp_chunk(&bufs[(ch + PH) & 1], src + (size_t)(ch + 2) * CHELE, tid);
            CP_COMMIT();
        }
    }
}

// register epilogue: x = relu(C + bias) -> fp16 act, direct packed STS.32
static __device__ __forceinline__ void epi_act_reg(float (&c)[2][8][4],
    const float* __restrict__ bias_s, __half* act, int mbase, int nbase, int lane)
{
    const int g = lane >> 2, tc = (lane & 3) * 2;
#pragma unroll
    for (int mi = 0; mi < 2; mi++) {
        const int r0 = mbase + mi * 16 + g;
#pragma unroll
        for (int nj = 0; nj < 8; nj++) {
            const int j = nbase + nj * 8 + tc;
            const float b0 = bias_s[j], b1 = bias_s[j + 1];
            const float x0 = fmaxf(c[mi][nj][0] + b0, 0.0f);
            const float x1 = fmaxf(c[mi][nj][1] + b1, 0.0f);
            const float x2 = fmaxf(c[mi][nj][2] + b0, 0.0f);
            const float x3 = fmaxf(c[mi][nj][3] + b1, 0.0f);
            *reinterpret_cast<uint32_t*>(&act[(size_t)r0 * AP + j])       = packh2(x0, x1);
            *reinterpret_cast<uint32_t*>(&act[(size_t)(r0 + 8) * AP + j]) = packh2(x2, x3);
        }
    }
}

static __device__ __forceinline__ void zero_c(float (&c)[2][8][4]) {
#pragma unroll
    for (int mi = 0; mi < 2; mi++)
#pragma unroll
        for (int nj = 0; nj < 8; nj++)
#pragma unroll
            for (int e = 0; e < 4; e++) c[mi][nj][e] = 0.0f;
}

// 256->256 GEMV, thread j = output column
static __device__ __forceinline__ void gemv1(const ull* __restrict__ Wp,
                                             const float* __restrict__ bias,
                                             const float* x, float* y, int j, bool relu) {
    ull a = pack2(bias[j], 0.0f);
    const ull* wp = Wp + j;
#pragma unroll 4
    for (int k2 = 0; k2 < HID / 2; k2 += 2) {
        const ulonglong2 u = *reinterpret_cast<const ulonglong2*>(x + 2 * k2);
        a = ffma2(u.x, wp[k2 * HID], a);
        a = ffma2(u.y, wp[(k2 + 1) * HID], a);
    }
    const float2 f = unpack2(a);
    float r = f.x + f.y;
    if (relu) r = fmaxf(r, 0.0f);
    y[j] = r;
}

__global__ void __launch_bounds__(NTHR, 2) pinet_mma_kernel(
    const float* __restrict__ obs,
    const float* __restrict__ ob1, const float* __restrict__ ob2,
    const float* __restrict__ pb1, const float* __restrict__ pb2,
    const float* __restrict__ pb3, const float* __restrict__ bq,
    const float* __restrict__ Wk,  const float* __restrict__ bk,
    const float* __restrict__ Wv,  const float* __restrict__ bv,
    float* __restrict__ out)
{
    extern __shared__ char smraw[];
    Smem* s = reinterpret_cast<Smem*>(smraw);
    const int tid = threadIdx.x, wid = tid >> 5, lane = tid & 31;
    __half* act = s->u.act;
    const uint32_t actAddr  = smem_u32(s->u.act);
    const uint32_t buf0Addr = smem_u32(s->bufs[0].w);
    const uint32_t buf1Addr = smem_u32(s->bufs[1].w);

    // ---- prefetch L1 weights (buf0) and L2 chunk0 (buf1) ----
    cp_chunk(&s->bufs[0], g_B1, tid); CP_COMMIT();
    cp_chunk(&s->bufs[1], g_B2, tid); CP_COMMIT();

    const float* row = obs + (size_t)blockIdx.x * OBS_W;

    // ---- load obs: feats -> act fp16 (cols 0..31), mask, others, biases ----
    {
#pragma unroll
        for (int i2 = 0; i2 < 2; i2++) {
            const int i = tid + i2 * NTHR;           // 0..511 float4s of feats
            const float4 a = reinterpret_cast<const float4*>(row)[i];
            const int m0 = i >> 3, d4 = (i & 7) * 4;
            *reinterpret_cast<uint32_t*>(&act[(size_t)m0 * AP + d4])     = packh2(a.x, a.y);
            *reinterpret_cast<uint32_t*>(&act[(size_t)m0 * AP + d4 + 2]) = packh2(a.z, a.w);
            if ((i & 7) == 7) s->maskv[m0] = a.w;
        }
        s->w.sa.v0[tid] = row[OTH_OFF + tid];
        s->b1s[tid] = pb1[tid];
        s->b2s[tid] = pb2[tid];
    }
    __syncthreads();

    // ---- stage A (overlaps in-flight cp.async) ----
    gemv1(g_oW1p, ob1, s->w.sa.v0, s->w.sa.v1, tid, true);
    __syncthreads();
    {
        float oe;
        {
            ull a = pack2(ob2[tid], 0.0f);
            const ull* wp = g_oW2p + tid;
#pragma unroll 4
            for (int k2 = 0; k2 < HID / 2; k2 += 2) {
                const ulonglong2 u = *reinterpret_cast<const ulonglong2*>(s->w.sa.v1 + 2 * k2);
                a = ffma2(u.x, wp[k2 * HID], a);
                a = ffma2(u.y, wp[(k2 + 1) * HID], a);
            }
            const float2 f = unpack2(a);
            oe = f.x + f.y;
        }
        out[(size_t)blockIdx.x * 512 + tid] = oe;
        __syncthreads();
        s->w.sa.v0[tid] = oe;
    }
    __syncthreads();
    gemv1(g_Wqp, bq, s->w.sa.v0, s->qv, tid, false);    // q
    __syncthreads();
    {   // qt[h*64+d] = Wk[h,d,:].q[h,:] ; qb[h] = q.bk
        const int h = tid >> 6, d = tid & 63;
        const float4* wk4 = reinterpret_cast<const float4*>(Wk + h * (HDIM*HDIM) + d * HDIM);
        const float4* q4  = reinterpret_cast<const float4*>(&s->qv[h * HDIM]);
        float t = 0.0f;
#pragma unroll
        for (int e = 0; e < HDIM / 4; e++) {
            const float4 w = wk4[e], qv = q4[e];
            t += w.x*qv.x + w.y*qv.y + w.z*qv.z + w.w*qv.w;
        }
        s->qt[tid] = t;
        if (tid < NHEAD) {
            float sb = 0.0f;
            for (int e = 0; e < HDIM; e++) sb += s->qv[tid * HDIM + e] * bk[tid * HDIM + e];
            s->qb[tid] = sb;
        }
    }
    __syncthreads();
    if (tid < NHEAD) {   // pq[h] = pb3[h-slice] . qt[h-slice]
        float t = 0.0f;
        for (int d = 0; d < HDIM; d++) t += pb3[tid * HDIM + d] * s->qt[tid * HDIM + d];
        s->pq[tid] = t;
    }

    // ---- object MLP on mma.sync; warp tile 32x64; 2 CTAs/SM ----
    const int mbase = (wid >> 2) * 32;
    const int nbase = (wid & 3) * 64;
    float c[2][8][4];

    // L1: one 32-K chunk (weights in buf0)
    zero_c(c);
    CP_WAIT1();                 // L1 done (L2c0 may still be in flight)
    __syncthreads();
    mma_chunk(c, actAddr, buf0Addr, 0, mbase, nbase, lane);
    __syncthreads();
    cp_chunk(&s->bufs[0], g_B2 + CHELE, tid); CP_COMMIT();   // L2 chunk1 -> buf0
    epi_act_reg(c, s->b1s, act, mbase, nbase, lane);
    __syncthreads();

    // L2: 8 chunks, chunk ch in bufs[(ch+1)&1]
    zero_c(c);
    layer_pipe<1>(c, actAddr, s->bufs, buf0Addr, buf1Addr, g_B2, mbase, nbase, lane, tid);
    cp_chunk(&s->bufs[0], g_B3, tid); CP_COMMIT();           // L3 c0
    cp_chunk(&s->bufs[1], g_B3 + CHELE, tid); CP_COMMIT();   // L3 c1
    epi_act_reg(c, s->b2s, act, mbase, nbase, lane);
    __syncthreads();

    // L3: 8 chunks, chunk ch in bufs[ch&1] -> rawP (pb3 folded into attention)
    zero_c(c);
    layer_pipe<0>(c, actAddr, s->bufs, buf0Addr, buf1Addr, g_B3, mbase, nbase, lane, tid);
    {   // direct register -> rawP (act union now dead)
        const int g = lane >> 2, tc = (lane & 3) * 2;
#pragma unroll
        for (int mi = 0; mi < 2; mi++) {
            const int r0 = mbase + mi * 16 + g;
#pragma unroll
            for (int nj = 0; nj < 8; nj++) {
                const int j = nbase + nj * 8 + tc;
                *reinterpret_cast<float2*>(&s->u.rawP[(size_t)r0 * RPF + j]) =
                    make_float2(c[mi][nj][0], c[mi][nj][1]);
                *reinterpret_cast<float2*>(&s->u.rawP[(size_t)(r0 + 8) * RPF + j]) =
                    make_float2(c[mi][nj][2], c[mi][nj][3]);
            }
        }
    }
    __syncthreads();

    // ---- attention (q-len 1; K/V folded; pb3 folded via pq/Wsum) ----
    {
        const int h = tid >> 6, n = tid & 63;
        const float* rp = s->u.rawP + (size_t)n * RPF + h * HDIM;
        const float* qt = s->qt + h * HDIM;
        float dot = 0.0f;
#pragma unroll
        for (int d = 0; d < HDIM; d += 4) {
            const float4 a4 = *reinterpret_cast<const float4*>(&rp[d]);
            const float4 b4 = *reinterpret_cast<const float4*>(&qt[d]);
            dot += a4.x*b4.x + a4.y*b4.y + a4.z*b4.z + a4.w*b4.w;
        }
        const float m = s->maskv[n];
        float lg = (m * (dot + s->pq[h]) + s->qb[h]) * 0.0625f;
        if (m == 0.0f) lg = -1000000000.0f;
        s->w.at.logit[h * NOBJ + n] = lg;
    }
    __syncthreads();
    if (wid < NHEAD) {   // softmax: warp = head
        const int hh = wid;
        const float x0 = s->w.at.logit[hh * NOBJ + lane];
        const float x1 = s->w.at.logit[hh * NOBJ + 32 + lane];
        float mx = fmaxf(x0, x1);
#pragma unroll
        for (int o = 16; o > 0; o >>= 1) mx = fmaxf(mx, __shfl_xor_sync(0xffffffffu, mx, o));
        const float e0 = expf(x0 - mx), e1 = expf(x1 - mx);
        float sum = e0 + e1;
#pragma unroll
        for (int o = 16; o > 0; o >>= 1) sum += __shfl_xor_sync(0xffffffffu, sum, o);
        const float inv = 1.0f / sum;
        const float a0 = e0 * inv, a1 = e1 * inv;
        const float m0 = s->maskv[lane], m1 = s->maskv[32 + lane];
        const float w0 = a0 * m0 * m0, w1 = a1 * m1 * m1;
        s->w.at.wgt[hh * NOBJ + lane]      = w0;
        s->w.at.wgt[hh * NOBJ + 32 + lane] = w1;
        float tt = a0 * m0 + a1 * m1;
        float ws = w0 + w1;
#pragma unroll
        for (int o = 16; o > 0; o >>= 1) {
            tt += __shfl_xor_sync(0xffffffffu, tt, o);
            ws += __shfl_xor_sync(0xffffffffu, ws, o);
        }
        if (lane == 0) { s->w.at.Th[hh] = tt; s->w.at.Wsum[hh] = ws; }
    }
    __syncthreads();
    {   // Svec = sum_n wgt*rawP + Wsum*pb3
        const int h = tid >> 6, d = tid & 63;
        const float* wp = s->w.at.wgt + h * NOBJ;
        float acc = 0.0f;
#pragma unroll 4
        for (int nn = 0; nn < NOBJ; nn++)
            acc = fmaf(wp[nn], s->u.rawP[(size_t)nn * RPF + h * HDIM + d], acc);
        s->w.at.Svec[tid] = acc + s->w.at.Wsum[h] * pb3[h * HDIM + d];
    }
    __syncthreads();
    {   // out_emb = Svec @ Wv + Th*bv
        const int h = tid >> 6, e = tid & 63;
        float o = s->w.at.Th[h] * bv[h * HDIM + e];
        const float* sv = s->w.at.Svec + h * HDIM;
        const float* wv = Wv + h * (HDIM * HDIM) + e;
#pragma unroll 4
        for (int d = 0; d < HDIM; d++)
            o = fmaf(sv[d], wv[d * HDIM], o);
        out[(size_t)blockIdx.x * 512 + 256 + h * HDIM + e] = o;
    }
}

extern "C" void kernel_launch(void* const* d_in, const int* in_sizes, int n_in,
                              void* d_out, int out_size)
{
    const float* obs = (const float*)d_in[0];
    const float* oW1 = (const float*)d_in[1];
    const float* ob1 = (const float*)d_in[2];
    const float* oW2 = (const float*)d_in[3];
    const float* ob2 = (const float*)d_in[4];
    const float* pW1 = (const float*)d_in[5];
    const float* pb1 = (const float*)d_in[6];
    const float* pW2 = (const float*)d_in[7];
    const float* pb2 = (const float*)d_in[8];
    const float* pW3 = (const float*)d_in[9];
    const float* pb3 = (const float*)d_in[10];
    const float* Wq  = (const float*)d_in[11];
    const float* bq  = (const float*)d_in[12];
    const float* Wk  = (const float*)d_in[13];
    const float* bk  = (const float*)d_in[14];
    const float* Wv  = (const float*)d_in[15];
    const float* bv  = (const float*)d_in[16];
    float* out = (float*)d_out;

    prep_all<<<256, 256>>>(pW1, pW2, pW3, oW1, oW2, Wq);

    const int smem = (int)sizeof(Smem);
    cudaFuncSetAttribute(pinet_mma_kernel, cudaFuncAttributeMaxDynamicSharedMemorySize, smem);
    pinet_mma_kernel<<<GRID_N, NTHR, smem>>>(obs, ob1, ob2, pb1, pb2, pb3,
                                             bq, Wk, bk, Wv, bv, out);
}

// round 17
// speedup vs baseline: 7.3948x; 1.0202x over previous
#include <cuda_runtime.h>
#include <cuda_fp16.h>
#include <math.h>
#include <stdint.h>

typedef unsigned long long ull;

#define NOBJ    64
#define FEAT    31
#define HID     256
#define OBS_W   2304
#define OTH_OFF 2048
#define NHEAD   4
#define HDIM    64
#define MROWS   128          // 2 samples x 64 objects per CTA
#define AP      264          // act pitch (half)
#define BP      264          // B-tile pitch (half)
#define RPF     268          // rawP pitch (floats)
#define GRID_N  2048
#define NTHR    512
#define CHROWS  32           // K-rows per weight chunk
#define CHELE   (CHROWS * HID)

// ---------------- helpers ----------------
static __device__ __forceinline__ uint32_t smem_u32(const void* p) {
    uint32_t a; asm("{ .reg .u64 t; cvta.to.shared.u64 t, %1; cvt.u32.u64 %0, t; }"
                    : "=r"(a) : "l"(p)); return a;
}
static __device__ __forceinline__ void cp16(uint32_t dst, const void* src) {
    asm volatile("cp.async.cg.shared.global [%0], [%1], 16;" :: "r"(dst), "l"(src));
}
#define CP_COMMIT() asm volatile("cp.async.commit_group;" ::: "memory")
#define CP_WAIT1()  asm volatile("cp.async.wait_group 1;" ::: "memory")
#define CP_WAIT0()  asm volatile("cp.async.wait_group 0;" ::: "memory")

static __device__ __forceinline__ ull pack2(float lo, float hi) {
    ull r; asm("mov.b64 %0,{%1,%2};" : "=l"(r) : "f"(lo), "f"(hi)); return r;
}
static __device__ __forceinline__ float2 unpack2(ull v) {
    float2 f; asm("mov.b64 {%0,%1},%2;" : "=f"(f.x), "=f"(f.y) : "l"(v)); return f;
}
static __device__ __forceinline__ ull ffma2(ull a, ull b, ull c) {
    ull d; asm("fma.rn.f32x2 %0,%1,%2,%3;" : "=l"(d) : "l"(a), "l"(b), "l"(c)); return d;
}
static __device__ __forceinline__ uint32_t packh2(float x0, float x1) {
    const __half h0 = __float2half_rn(x0), h1 = __float2half_rn(x1);
    return (uint32_t)__half_as_ushort(h0) | ((uint32_t)__half_as_ushort(h1) << 16);
}

// ---------------- mma.sync primitives ----------------
static __device__ __forceinline__ void ldmA(uint32_t (&a)[4], uint32_t addr) {
    asm volatile("ldmatrix.sync.aligned.m8n8.x4.shared.b16 {%0,%1,%2,%3}, [%4];"
        : "=r"(a[0]), "=r"(a[1]), "=r"(a[2]), "=r"(a[3]) : "r"(addr));
}
static __device__ __forceinline__ void ldmBT(uint32_t (&b)[4], uint32_t addr) {
    asm volatile("ldmatrix.sync.aligned.m8n8.x4.trans.shared.b16 {%0,%1,%2,%3}, [%4];"
        : "=r"(b[0]), "=r"(b[1]), "=r"(b[2]), "=r"(b[3]) : "r"(addr));
}
static __device__ __forceinline__ void mma16816(float (&d)[4], const uint32_t (&a)[4],
                                                uint32_t b0, uint32_t b1) {
    asm volatile("mma.sync.aligned.m16n8k16.row.col.f32.f16.f16.f32 "
        "{%0,%1,%2,%3}, {%4,%5,%6,%7}, {%8,%9}, {%0,%1,%2,%3};"
        : "+f"(d[0]), "+f"(d[1]), "+f"(d[2]), "+f"(d[3])
        : "r"(a[0]), "r"(a[1]), "r"(a[2]), "r"(a[3]), "r"(b0), "r"(b1));
}

// ---------------- global scratch (fp16 RN weights) ----------------
__device__ __align__(16) __half g_B1[32 * HID];     // L1 (k pad 31->32)
__device__ __align__(16) __half g_B2[HID * HID];    // L2
__device__ __align__(16) __half g_B3[HID * HID];    // L3
__device__ ull g_oW1p[(HID/2)*HID], g_oW2p[(HID/2)*HID], g_Wqp[(HID/2)*HID];

__global__ void prep_all(const float* __restrict__ pW1, const float* __restrict__ pW2,
                         const float* __restrict__ pW3, const float* __restrict__ oW1,
                         const float* __restrict__ oW2, const float* __restrict__ Wq)
{
    const int b = blockIdx.x, t = threadIdx.x;
    g_B2[b * HID + t] = __float2half_rn(pW2[b * HID + t]);
    g_B3[b * HID + t] = __float2half_rn(pW3[b * HID + t]);
    if (b < 32)
        g_B1[b * HID + t] = __float2half_rn((b < FEAT) ? pW1[b * HID + t] : 0.0f);
    if (b < 128) {
        g_oW1p[b * HID + t] = pack2(oW1[(2*b) * HID + t], oW1[(2*b+1) * HID + t]);
        g_oW2p[b * HID + t] = pack2(oW2[(2*b) * HID + t], oW2[(2*b+1) * HID + t]);
        g_Wqp [b * HID + t] = pack2(Wq [(2*b) * HID + t], Wq [(2*b+1) * HID + t]);
    }
}

// ---------------- SMEM (~184 KB, 1 CTA/SM @512 thr) ----------------
struct Buf { __half w[CHROWS * BP]; };

struct Smem {
    union {
        __half act[MROWS * AP];          // fp16 activations (2 samples)
        float rawP[MROWS * RPF];
    } u;
    Buf bufs[2];
    float b1s[HID], b2s[HID];
    union {                              // phase-disjoint scratch
        struct { float v0[2][HID]; float v1[2][HID]; } sa;
        struct { float logit[2][NHEAD * NOBJ]; float wgt[2][NHEAD * NOBJ];
                 float Svec[2][HID]; float Th[2][NHEAD]; float Wsum[2][NHEAD]; } at;
    } w;
    float qt[2][HID];
    float qv[2][HID];
    float qb[2][NHEAD], pq[2][NHEAD];
    float maskv[MROWS];
};

// async-copy one 32x256 fp16 chunk (2 cp.async per thread @512thr)
static __device__ __forceinline__ void cp_chunk(Buf* buf, const __half* src, int tid) {
    const char* sp = reinterpret_cast<const char*>(src);
    const uint32_t dp = smem_u32(buf->w);
#pragma unroll
    for (int i = 0; i < 2; i++) {
        const int idx = tid + i * NTHR;       // 0..1023 (32 rows x 32 int4)
        const int r = idx >> 5, c = idx & 31;
        cp16(dp + (uint32_t)(r * BP * 2 + c * 16), sp + (size_t)idx * 16);
    }
}

// MMA over one 32-K chunk: warp tile 32x64; batched LDSM per k-step
static __device__ __forceinline__ void mma_chunk(float (&c)[2][8][4],
    uint32_t actAddr, uint32_t bufAddr, int kbase, int mbase, int nbase, int lane)
{
    const uint32_t aoff = (uint32_t)(((lane & 15) * AP + ((lane >> 4) << 3)) * 2);
    const uint32_t boff = (uint32_t)((((lane & 7) + (((lane >> 3) & 1) << 3)) * BP
                                      + ((lane >> 4) << 3)) * 2);
#pragma unroll
    for (int ks = 0; ks < 2; ks++) {
        uint32_t a0[4], a1[4], b[4][4];
        ldmA(a0, actAddr + aoff + (uint32_t)((mbase * AP + kbase + ks * 16) * 2));
        ldmA(a1, actAddr + aoff + (uint32_t)(((mbase + 16) * AP + kbase + ks * 16) * 2));
#pragma unroll
        for (int nj = 0; nj < 4; nj++)
            ldmBT(b[nj], bufAddr + boff + (uint32_t)((ks * 16 * BP + nbase + nj * 16) * 2));
#pragma unroll
        for (int nj = 0; nj < 4; nj++) {
            mma16816(c[0][nj*2+0], a0, b[nj][0], b[nj][1]);
            mma16816(c[0][nj*2+1], a0, b[nj][2], b[nj][3]);
            mma16816(c[1][nj*2+0], a1, b[nj][0], b[nj][1]);
            mma16816(c[1][nj*2+1], a1, b[nj][2], b[nj][3]);
        }
    }
}

// 8-chunk double-buffered layer; chunks 0,1 already in flight, chunk ch in bufs[(ch+PH)&1]
template<int PH>
static __device__ __forceinline__ void layer_pipe(float (&c)[2][8][4],
    uint32_t actAddr, Buf* bufs, uint32_t buf0Addr, uint32_t buf1Addr,
    const __half* src, int mbase, int nbase, int lane, int tid)
{
    const uint32_t ba[2] = { buf0Addr, buf1Addr };
    for (int ch = 0; ch < 8; ch++) {
        if (ch < 7) CP_WAIT1(); else CP_WAIT0();
        __syncthreads();
        mma_chunk(c, actAddr, ba[(ch + PH) & 1], ch * CHROWS, mbase, nbase, lane);
        __syncthreads();
        if (ch + 2 < 8) {
            cp_chunk(&bufs[(ch + PH) & 1], src + (size_t)(ch + 2) * CHELE, tid);
            CP_COMMIT();
        }
    }
}

// register epilogue: x = relu(C + bias) -> fp16 act, direct packed STS.32
static __device__ __forceinline__ void epi_act_reg(float (&c)[2][8][4],
    const float* __restrict__ bias_s, __half* act, int mbase, int nbase, int lane)
{
    const int g = lane >> 2, tc = (lane & 3) * 2;
#pragma unroll
    for (int mi = 0; mi < 2; mi++) {
        const int r0 = mbase + mi * 16 + g;
#pragma unroll
        for (int nj = 0; nj < 8; nj++) {
            const int j = nbase + nj * 8 + tc;
            const float b0 = bias_s[j], b1 = bias_s[j + 1];
            const float x0 = fmaxf(c[mi][nj][0] + b0, 0.0f);
            const float x1 = fmaxf(c[mi][nj][1] + b1, 0.0f);
            const float x2 = fmaxf(c[mi][nj][2] + b0, 0.0f);
            const float x3 = fmaxf(c[mi][nj][3] + b1, 0.0f);
            *reinterpret_cast<uint32_t*>(&act[(size_t)r0 * AP + j])       = packh2(x0, x1);
            *reinterpret_cast<uint32_t*>(&act[(size_t)(r0 + 8) * AP + j]) = packh2(x2, x3);
        }
    }
}

static __device__ __forceinline__ void zero_c(float (&c)[2][8][4]) {
#pragma unroll
    for (int mi = 0; mi < 2; mi++)
#pragma unroll
        for (int nj = 0; nj < 8; nj++)
#pragma unroll
            for (int e = 0; e < 4; e++) c[mi][nj][e] = 0.0f;
}

// 256->256 GEMV over BOTH samples sharing weight loads (threads 0..255)
static __device__ __forceinline__ void gemv2(const ull* __restrict__ Wp,
                                             const float* __restrict__ bias,
                                             const float* x0, const float* x1,
                                             float* y0, float* y1, int j, bool relu) {
    ull a0 = pack2(bias[j], 0.0f), a1 = a0;
    const ull* wp = Wp + j;
#pragma unroll 4
    for (int k2 = 0; k2 < HID / 2; k2 += 2) {
        const ull wA = wp[k2 * HID], wB = wp[(k2 + 1) * HID];
        const ulonglong2 u0 = *reinterpret_cast<const ulonglong2*>(x0 + 2 * k2);
        const ulonglong2 u1 = *reinterpret_cast<const ulonglong2*>(x1 + 2 * k2);
        a0 = ffma2(u0.x, wA, a0); a0 = ffma2(u0.y, wB, a0);
        a1 = ffma2(u1.x, wA, a1); a1 = ffma2(u1.y, wB, a1);
    }
    const float2 f0 = unpack2(a0), f1 = unpack2(a1);
    float r0 = f0.x + f0.y, r1 = f1.x + f1.y;
    if (relu) { r0 = fmaxf(r0, 0.0f); r1 = fmaxf(r1, 0.0f); }
    y0[j] = r0; y1[j] = r1;
}

__global__ void __launch_bounds__(NTHR, 1) pinet_mma_kernel(
    const float* __restrict__ obs,
    const float* __restrict__ ob1, const float* __restrict__ ob2,
    const float* __restrict__ pb1, const float* __restrict__ pb2,
    const float* __restrict__ pb3, const float* __restrict__ bq,
    const float* __restrict__ Wk,  const float* __restrict__ bk,
    const float* __restrict__ Wv,  const float* __restrict__ bv,
    float* __restrict__ out)
{
    extern __shared__ char smraw[];
    Smem* s = reinterpret_cast<Smem*>(smraw);
    const int tid = threadIdx.x, wid = tid >> 5, lane = tid & 31;
    const int smp = tid >> 8, idx = tid & 255;     // per-sample thread mapping
    __half* act = s->u.act;
    const uint32_t actAddr  = smem_u32(s->u.act);
    const uint32_t buf0Addr = smem_u32(s->bufs[0].w);
    const uint32_t buf1Addr = smem_u32(s->bufs[1].w);

    // ---- prefetch L1 weights (buf0) and L2 chunk0 (buf1) ----
    cp_chunk(&s->bufs[0], g_B1, tid); CP_COMMIT();
    cp_chunk(&s->bufs[1], g_B2, tid); CP_COMMIT();

    const float* r0 = obs + (size_t)(blockIdx.x * 2 + 0) * OBS_W;
    const float* r1 = obs + (size_t)(blockIdx.x * 2 + 1) * OBS_W;

    // ---- load obs: feats (both samples) -> act fp16, mask, others, biases ----
    {
        const int i = tid;                         // 0..511 float4s per sample
        const float4 a = reinterpret_cast<const float4*>(r0)[i];
        const float4 b = reinterpret_cast<const float4*>(r1)[i];
        const int m0 = i >> 3, d4 = (i & 7) * 4;
        *reinterpret_cast<uint32_t*>(&act[(size_t)m0 * AP + d4])            = packh2(a.x, a.y);
        *reinterpret_cast<uint32_t*>(&act[(size_t)m0 * AP + d4 + 2])        = packh2(a.z, a.w);
        *reinterpret_cast<uint32_t*>(&act[(size_t)(64 + m0) * AP + d4])     = packh2(b.x, b.y);
        *reinterpret_cast<uint32_t*>(&act[(size_t)(64 + m0) * AP + d4 + 2]) = packh2(b.z, b.w);
        if ((i & 7) == 7) { s->maskv[m0] = a.w; s->maskv[64 + m0] = b.w; }
        s->w.sa.v0[smp][idx] = (smp == 0) ? r0[OTH_OFF + idx] : r1[OTH_OFF + idx];
        if (tid < HID) { s->b1s[tid] = pb1[tid]; s->b2s[tid] = pb2[tid]; }
    }
    __syncthreads();

    // ---- stage A on threads 0..255, both samples share weight loads ----
    if (tid < HID)
        gemv2(g_oW1p, ob1, s->w.sa.v0[0], s->w.sa.v0[1],
              s->w.sa.v1[0], s->w.sa.v1[1], tid, true);
    __syncthreads();
    if (tid < HID) {
        gemv2(g_oW2p, ob2, s->w.sa.v1[0], s->w.sa.v1[1],
              s->w.sa.v0[0], s->w.sa.v0[1], tid, false);        // others_e
        out[(size_t)(blockIdx.x * 2 + 0) * 512 + tid] = s->w.sa.v0[0][tid];
        out[(size_t)(blockIdx.x * 2 + 1) * 512 + tid] = s->w.sa.v0[1][tid];
    }
    __syncthreads();
    if (tid < HID)
        gemv2(g_Wqp, bq, s->w.sa.v0[0], s->w.sa.v0[1],
              s->qv[0], s->qv[1], tid, false);                  // q
    __syncthreads();
    {   // qt[s][h*64+d] = Wk[h,d,:].q[s,h,:] ; qb[s][h] = q.bk   (512 thr = 2 samples)
        const int h = idx >> 6, d = idx & 63;
        const float4* wk4 = reinterpret_cast<const float4*>(Wk + h * (HDIM*HDIM) + d * HDIM);
        const float4* q4  = reinterpret_cast<const float4*>(&s->qv[smp][h * HDIM]);
        float t = 0.0f;
#pragma unroll
        for (int e = 0; e < HDIM / 4; e++) {
            const float4 w = wk4[e], qv = q4[e];
            t += w.x*qv.x + w.y*qv.y + w.z*qv.z + w.w*qv.w;
        }
        s->qt[smp][idx] = t;
        if (idx < NHEAD) {
            float sb = 0.0f;
            for (int e = 0; e < HDIM; e++) sb += s->qv[smp][idx * HDIM + e] * bk[idx * HDIM + e];
            s->qb[smp][idx] = sb;
        }
    }
    __syncthreads();
    if (tid < 8) {   // pq[s][h] = pb3[h-slice] . qt[s][h-slice]
        const int sm = tid >> 2, hh = tid & 3;
        float t = 0.0f;
        for (int d = 0; d < HDIM; d++) t += pb3[hh * HDIM + d] * s->qt[sm][hh * HDIM + d];
        s->pq[sm][hh] = t;
    }

    // ---- object MLP on mma.sync; 16 warps = 4m x 4n, warp tile 32x64 ----
    const int mbase = (wid >> 2) * 32;
    const int nbase = (wid & 3) * 64;
    float c[2][8][4];

    // L1: one 32-K chunk (weights in buf0)
    zero_c(c);
    CP_WAIT1();                 // L1 done (L2c0 may still be in flight)
    __syncthreads();
    mma_chunk(c, actAddr, buf0Addr, 0, mbase, nbase, lane);
    __syncthreads();
    cp_chunk(&s->bufs[0], g_B2 + CHELE, tid); CP_COMMIT();   // L2 chunk1 -> buf0
    epi_act_reg(c, s->b1s, act, mbase, nbase, lane);
    __syncthreads();

    // L2: 8 chunks, chunk ch in bufs[(ch+1)&1]
    zero_c(c);
    layer_pipe<1>(c, actAddr, s->bufs, buf0Addr, buf1Addr, g_B2, mbase, nbase, lane, tid);
    cp_chunk(&s->bufs[0], g_B3, tid); CP_COMMIT();           // L3 c0
    cp_chunk(&s->bufs[1], g_B3 + CHELE, tid); CP_COMMIT();   // L3 c1
    epi_act_reg(c, s->b2s, act, mbase, nbase, lane);
    __syncthreads();

    // L3: 8 chunks, chunk ch in bufs[ch&1] -> rawP (pb3 folded into attention)
    zero_c(c);
    layer_pipe<0>(c, actAddr, s->bufs, buf0Addr, buf1Addr, g_B3, mbase, nbase, lane, tid);
    {   // direct register -> rawP (act union now dead)
        const int g = lane >> 2, tc = (lane & 3) * 2;
#pragma unroll
        for (int mi = 0; mi < 2; mi++) {
            const int rr = mbase + mi * 16 + g;
#pragma unroll
            for (int nj = 0; nj < 8; nj++) {
                const int j = nbase + nj * 8 + tc;
                *reinterpret_cast<float2*>(&s->u.rawP[(size_t)rr * RPF + j]) =
                    make_float2(c[mi][nj][0], c[mi][nj][1]);
                *reinterpret_cast<float2*>(&s->u.rawP[(size_t)(rr + 8) * RPF + j]) =
                    make_float2(c[mi][nj][2], c[mi][nj][3]);
            }
        }
    }
    __syncthreads();

    // ---- attention (both samples; q-len 1; K/V folded; pb3 via pq/Wsum) ----
    {
        const int h = idx >> 6, n = idx & 63;
        const float* rp = s->u.rawP + (size_t)(smp * 64 + n) * RPF + h * HDIM;
        const float* qt = s->qt[smp] + h * HDIM;
        float dot = 0.0f;
#pragma unroll
        for (int d = 0; d < HDIM; d += 4) {
            const float4 a4 = *reinterpret_cast<const float4*>(&rp[d]);
            const float4 b4 = *reinterpret_cast<const float4*>(&qt[d]);
            dot += a4.x*b4.x + a4.y*b4.y + a4.z*b4.z + a4.w*b4.w;
        }
        const float m = s->maskv[smp * 64 + n];
        float lg = (m * (dot + s->pq[smp][h]) + s->qb[smp][h]) * 0.0625f;
        if (m == 0.0f) lg = -1000000000.0f;
        s->w.at.logit[smp][h * NOBJ + n] = lg;
    }
    __syncthreads();
    if (wid < 8) {   // softmax: 8 warp-tasks = 2 samples x 4 heads
        const int sm = wid >> 2, hh = wid & 3;
        const float x0 = s->w.at.logit[sm][hh * NOBJ + lane];
        const float x1 = s->w.at.logit[sm][hh * NOBJ + 32 + lane];
        float mx = fmaxf(x0, x1);
#pragma unroll
        for (int o = 16; o > 0; o >>= 1) mx = fmaxf(mx, __shfl_xor_sync(0xffffffffu, mx, o));
        const float e0 = expf(x0 - mx), e1 = expf(x1 - mx);
        float sum = e0 + e1;
#pragma unroll
        for (int o = 16; o > 0; o >>= 1) sum += __shfl_xor_sync(0xffffffffu, sum, o);
        const float inv = 1.0f / sum;
        const float a0 = e0 * inv, a1 = e1 * inv;
        const float m0 = s->maskv[sm * 64 + lane], m1 = s->maskv[sm * 64 + 32 + lane];
        const float w0 = a0 * m0 * m0, w1 = a1 * m1 * m1;
        s->w.at.wgt[sm][hh * NOBJ + lane]      = w0;
        s->w.at.wgt[sm][hh * NOBJ + 32 + lane] = w1;
        float tt = a0 * m0 + a1 * m1;
        float ws = w0 + w1;
#pragma unroll
        for (int o = 16; o > 0; o >>= 1) {
            tt += __shfl_xor_sync(0xffffffffu, tt, o);
            ws += __shfl_xor_sync(0xffffffffu, ws, o);
        }
        if (lane == 0) { s->w.at.Th[sm][hh] = tt; s->w.at.Wsum[sm][hh] = ws; }
    }
    __syncthreads();
    {   // Svec = sum_n wgt*rawP + Wsum*pb3
        const int h = idx >> 6, d = idx & 63;
        const float* wp = s->w.at.wgt[smp] + h * NOBJ;
        float acc = 0.0f;
#pragma unroll 4
        for (int nn = 0; nn < NOBJ; nn++)
            acc = fmaf(wp[nn], s->u.rawP[(size_t)(smp * 64 + nn) * RPF + h * HDIM + d], acc);
        s->w.at.Svec[smp][idx] = acc + s->w.at.Wsum[smp][h] * pb3[h * HDIM + d];
    }
    __syncthreads();
    {   // out_emb = Svec @ Wv + Th*bv
        const int h = idx >> 6, e = idx & 63;
        float o = s->w.at.Th[smp][h] * bv[h * HDIM + e];
        const float* sv = s->w.at.Svec[smp] + h * HDIM;
        const float* wv = Wv + h * (HDIM * HDIM) + e;
#pragma unroll 4
        for (int d = 0; d < HDIM; d++)
            o = fmaf(sv[d], wv[d * HDIM], o);
        out[(size_t)(blockIdx.x * 2 + smp) * 512 + 256 + h * HDIM + e] = o;
    }
}

extern "C" void kernel_launch(void* const* d_in, const int* in_sizes, int n_in,
                              void* d_out, int out_size)
{
    const float* obs = (const float*)d_in[0];
    const float* oW1 = (const float*)d_in[1];
    const float* ob1 = (const float*)d_in[2];
    const float* oW2 = (const float*)d_in[3];
    const float* ob2 = (const float*)d_in[4];
    const float* pW1 = (const float*)d_in[5];
    const float* pb1 = (const float*)d_in[6];
    const float* pW2 = (const float*)d_in[7];
    const float* pb2 = (const float*)d_in[8];
    const float* pW3 = (const float*)d_in[9];
    const float* pb3 = (const float*)d_in[10];
    const float* Wq  = (const float*)d_in[11];
    const float* bq  = (const float*)d_in[12];
    const float* Wk  = (const float*)d_in[13];
    const float* bk  = (const float*)d_in[14];
    const float* Wv  = (const float*)d_in[15];
    const float* bv  = (const float*)d_in[16];
    float* out = (float*)d_out;

    prep_all<<<256, 256>>>(pW1, pW2, pW3, oW1, oW2, Wq);

    const int smem = (int)sizeof(Smem);
    cudaFuncSetAttribute(pinet_mma_kernel, cudaFuncAttributeMaxDynamicSharedMemorySize, smem);
    pinet_mma_kernel<<<GRID_N, NTHR, smem>>>(obs, ob1, ob2, pb1, pb2, pb3,
                                             bq, Wk, bk, Wv, bv, out);
}